// round 11
// baseline (speedup 1.0000x reference)
#include <cuda_runtime.h>
#include <cuda_fp16.h>
#include <cstdint>
#include <math_constants.h>

#define B_   4
#define CIN  512
#define CI   64
#define HW_  4096
#define EPSN 1e-5f
#define PITCH 72
#define SHIFT 12.0f
#define TILE_SZ (2*64*PITCH)   // halfs per staged k4 tile (fcH, fdH)

// k1_tc chunk geometry (halfs)
#define CH_XH 0
#define CH_XL 9216
#define CH_W  18432
#define CH_HALFS (18432 + 18432)
#define CH_BYTES (CH_HALFS*2)

// k1b_tc smem (bytes) - 64q version
#define QB_AH 0
#define QB_AL 9216
#define QB_W  18432
#define QB_BIAS (18432 + 55296)     // 73728
#define QB_TOTAL (QB_BIAS + 1024)   // 74752

// k6_tc smem (bytes)
#define K6_AH 0
#define K6_AL 18432
#define K6_WH 36864
#define K6_WL (36864 + 18432)
#define K6_SO 73728
#define K6_BN (73728 + 67584)
#define K6_TOTAL (K6_BN + 4096)     // 145408

// k4 smem (bytes) - 64q version
#define K4_FB 0
#define K4_STG 9216
#define K4_RS (9216 + 3*TILE_SZ*2)  // 64512
#define K4_TOTAL (K4_RS + 512)      // 65024

// ---------------- scratch (device globals; no allocation) ----------------
__device__ float g_fp    [B_*CI*HW_];
__device__ float g_fcb   [B_*CI*HW_];
__device__ float g_featp [B_*CI*HW_];
__device__ float g_gpart [B_*CI*CI*32];
__device__ float g_attnc [B_*CI*CI];
__device__ __align__(16) __half g_xT_h [B_*HW_*CIN];
__device__ __align__(16) __half g_xT_l [B_*HW_*CIN];
__device__ __align__(16) __half g_wh   [2][CI*CIN];
__device__ __align__(16) __half g_wl   [2][CI*CIN];
__device__ __align__(16) __half g_woh  [CIN*CI];
__device__ __align__(16) __half g_wol  [CIN*CI];
__device__ __align__(16) __half g_fpT_h[B_*HW_*CI];
__device__ __align__(16) __half g_fpT_l[B_*HW_*CI];
__device__ __align__(16) __half g_fusT_h[B_*HW_*CI];
__device__ __align__(16) __half g_fusT_l[B_*HW_*CI];
__device__ __align__(16) __half g_fbT_h[B_*HW_*CI];
__device__ __align__(16) __half g_fcT_h[B_*HW_*CI];
__device__ __align__(16) __half g_fd_h [B_*CI*HW_];

// ---------------- helpers ----------------
__device__ __forceinline__ uint32_t smem_u32(const void* p){
    uint32_t a;
    asm("{ .reg .u64 t; cvta.to.shared.u64 t, %1; cvt.u32.u64 %0, t; }" : "=r"(a) : "l"(p));
    return a;
}
#define CP_ASYNC16(dst, src) asm volatile("cp.async.cg.shared.global [%0], [%1], 16;" :: "r"(dst), "l"(src))
#define CP_COMMIT()          asm volatile("cp.async.commit_group;")
#define CP_WAIT(n)           asm volatile("cp.async.wait_group %0;" :: "n"(n))

__device__ __forceinline__ void mma16816(float c[4], const uint32_t a[4],
                                         uint32_t b0, uint32_t b1){
    asm volatile("mma.sync.aligned.m16n8k16.row.col.f32.f16.f16.f32 "
        "{%0,%1,%2,%3}, {%4,%5,%6,%7}, {%8,%9}, {%0,%1,%2,%3};"
        : "+f"(c[0]), "+f"(c[1]), "+f"(c[2]), "+f"(c[3])
        : "r"(a[0]), "r"(a[1]), "r"(a[2]), "r"(a[3]), "r"(b0), "r"(b1));
}
__device__ __forceinline__ uint32_t packh2(float a, float b){
    __half2 v = __floats2half2_rn(a, b);
    return *(uint32_t*)&v;
}
__device__ __forceinline__ void split2(float v0, float v1, uint32_t& h, uint32_t& l){
    __half2 h2 = __floats2half2_rn(v0, v1);
    __half2 l2 = __floats2half2_rn(v0 - __half2float(h2.x), v1 - __half2float(h2.y));
    h = *(uint32_t*)&h2; l = *(uint32_t*)&l2;
}

// ================= K0w =====================================================
__global__ void k0w_planes(const float* __restrict__ wp1,
                           const float* __restrict__ wc1,
                           const float* __restrict__ wo)
{
    const int which = blockIdx.x;
    const float* w = (which==0) ? wp1 : (which==1) ? wc1 : wo;
    __half* dh = (which==0) ? g_wh[0] : (which==1) ? g_wh[1] : g_woh;
    __half* dl = (which==0) ? g_wl[0] : (which==1) ? g_wl[1] : g_wol;
    for (int f = threadIdx.x; f < CI*CIN/4; f += 256){
        float4 v = *(const float4*)&w[f*4];
        uint32_t h0,l0,h1,l1;
        split2(v.x, v.y, h0, l0);
        split2(v.z, v.w, h1, l1);
        *(uint2*)&dh[f*4] = make_uint2(h0, h1);
        *(uint2*)&dl[f*4] = make_uint2(l0, l1);
    }
}

// ================= K0x =====================================================
__global__ __launch_bounds__(256) void k0x_planes(const float* __restrict__ x)
{
    __shared__ float ts[64*68];
    const int hw0 = blockIdx.x*64, c0 = blockIdx.y*64, b = blockIdx.z;
    const int t = threadIdx.x;
    for (int f=t; f<1024; f+=256){
        int cc = f>>4, qv = (f&15)<<2;
        *(float4*)&ts[cc*68+qv] =
            *(const float4*)&x[(size_t)(b*CIN + c0+cc)*HW_ + hw0 + qv];
    }
    __syncthreads();
    for (int f=t; f<512; f+=256){
        int hw = f>>3, j8 = f&7;
        uint32_t uh[4], ul[4];
#pragma unroll
        for (int i=0;i<4;i++)
            split2(ts[(j8*8+2*i)*68 + hw], ts[(j8*8+2*i+1)*68 + hw], uh[i], ul[i]);
        size_t base = ((size_t)b*HW_ + hw0 + hw)*CIN + c0 + j8*8;
        *(uint4*)&g_xT_h[base] = make_uint4(uh[0],uh[1],uh[2],uh[3]);
        *(uint4*)&g_xT_l[base] = make_uint4(ul[0],ul[1],ul[2],ul[3]);
    }
}

// ================= K1_tc ===================================================
__device__ __forceinline__ void k1_stage(char* smbase, int buf, int chunk,
                                         int b, int q0, int t){
    __half* base = (__half*)(smbase + (size_t)buf*CH_BYTES);
#pragma unroll
    for (int i=0;i<8;i++){
        int idx = t + i*256;
        int pl = idx>>10, r = (idx>>3)&127, j = idx&7;
        const __half* src = (pl ? g_xT_l : g_xT_h)
                            + ((size_t)b*HW_ + q0 + r)*CIN + chunk*64 + j*8;
        CP_ASYNC16(smem_u32(base + (pl?CH_XL:CH_XH) + r*PITCH + j*8), src);
    }
#pragma unroll
    for (int i=0;i<8;i++){
        int idx = t + i*256;
        int conv = idx>>10, pl = (idx>>9)&1, oc = (idx>>3)&63, j = idx&7;
        const __half* src = (pl ? g_wl[conv] : g_wh[conv]) + oc*CIN + chunk*64 + j*8;
        CP_ASYNC16(smem_u32(base + CH_W + (conv*2+pl)*4608 + oc*PITCH + j*8), src);
    }
}

__global__ __launch_bounds__(256, 1) void k1_tc(
    const float* __restrict__ gp1, const float* __restrict__ bp1,
    const float* __restrict__ mp1, const float* __restrict__ vp1,
    const float* __restrict__ gc1, const float* __restrict__ bc1,
    const float* __restrict__ mc1, const float* __restrict__ vc1)
{
    extern __shared__ char sm[];
    float* binv = (float*)(sm + 3*CH_BYTES);
    float* bsh  = binv + 128;

    const int b = blockIdx.y, q0 = blockIdx.x*128, t = threadIdx.x;
    const int w = t>>5, lane = t&31;
    const int mh = w&3, nh = w>>2;
    const int m0 = mh*32;
    const int g = lane>>2, j4 = lane&3;

    if (t < 64){
        binv[t] = gp1[t]*rsqrtf(vp1[t]+EPSN);
        bsh [t] = bp1[t] - mp1[t]*binv[t];
    } else if (t < 128){
        int o = t-64;
        binv[64+o] = gc1[o]*rsqrtf(vc1[o]+EPSN);
        bsh [64+o] = bc1[o] - mc1[o]*binv[64+o];
    }

    k1_stage(sm, 0, 0, b, q0, t); CP_COMMIT();
    k1_stage(sm, 1, 1, b, q0, t); CP_COMMIT();

    float acc[2][8][4];
#pragma unroll
    for (int mf=0;mf<2;mf++)
#pragma unroll
        for (int nf=0;nf<8;nf++)
#pragma unroll
            for (int r=0;r<4;r++) acc[mf][nf][r]=0.f;

    for (int c=0; c<8; c++){
        if (c == 7) { CP_WAIT(0); } else { CP_WAIT(1); }
        __syncthreads();
        if (c + 2 < 8){ k1_stage(sm, (c+2)%3, c+2, b, q0, t); CP_COMMIT(); }
        __half* base = (__half*)(sm + (size_t)(c%3)*CH_BYTES);
        const __half* wbH = base + CH_W + (nh*2+0)*4608;
        const __half* wbL = base + CH_W + (nh*2+1)*4608;

#pragma unroll
        for (int ks=0; ks<4; ks++){
            int col = ks*16 + 2*j4;
            uint32_t ah[2][4], al[2][4];
#pragma unroll
            for (int mf=0; mf<2; mf++){
                int r0 = m0 + mf*16 + g;
                ah[mf][0] = *(const uint32_t*)&base[CH_XH + (r0  )*PITCH + col];
                ah[mf][1] = *(const uint32_t*)&base[CH_XH + (r0+8)*PITCH + col];
                ah[mf][2] = *(const uint32_t*)&base[CH_XH + (r0  )*PITCH + col+8];
                ah[mf][3] = *(const uint32_t*)&base[CH_XH + (r0+8)*PITCH + col+8];
                al[mf][0] = *(const uint32_t*)&base[CH_XL + (r0  )*PITCH + col];
                al[mf][1] = *(const uint32_t*)&base[CH_XL + (r0+8)*PITCH + col];
                al[mf][2] = *(const uint32_t*)&base[CH_XL + (r0  )*PITCH + col+8];
                al[mf][3] = *(const uint32_t*)&base[CH_XL + (r0+8)*PITCH + col+8];
            }
#pragma unroll
            for (int nf=0; nf<8; nf++){
                int ocr = nf*8 + g;
                uint32_t wh0 = *(const uint32_t*)&wbH[ocr*PITCH + col];
                uint32_t wh1 = *(const uint32_t*)&wbH[ocr*PITCH + col+8];
                uint32_t wl0 = *(const uint32_t*)&wbL[ocr*PITCH + col];
                uint32_t wl1 = *(const uint32_t*)&wbL[ocr*PITCH + col+8];
#pragma unroll
                for (int mf=0; mf<2; mf++){
                    mma16816(acc[mf][nf], ah[mf], wh0, wh1);
                    mma16816(acc[mf][nf], al[mf], wh0, wh1);
                    mma16816(acc[mf][nf], ah[mf], wl0, wl1);
                }
            }
        }
    }
    __syncthreads();

    float* so = (float*)(sm + (size_t)nh*36864);
#pragma unroll
    for (int mf=0; mf<2; mf++)
#pragma unroll
    for (int nf=0; nf<8; nf++)
#pragma unroll
    for (int r=0; r<4; r++){
        int oc = nf*8 + 2*j4 + (r&1);
        int hw = m0 + mf*16 + g + ((r>>1)*8);
        so[oc*132 + hw] = fmaf(acc[mf][nf][r], binv[nh*64+oc], bsh[nh*64+oc]);
    }
    __syncthreads();
    for (int f=t; f<4096; f+=256){
        int conv = f>>11, oc = (f>>5)&63, hg = (f&31)*4;
        const float* s = (const float*)(sm + (size_t)conv*36864);
        float4 v = make_float4(s[oc*132+hg], s[oc*132+hg+1],
                               s[oc*132+hg+2], s[oc*132+hg+3]);
        float* dst = conv ? g_fcb : g_fp;
        *(float4*)&dst[(size_t)(b*CI+oc)*HW_ + q0 + hg] = v;
    }
    {
        const float* s0 = (const float*)sm;
        for (int f=t; f<1024; f+=256){
            int hw = f&127, c8 = f>>7;
            uint32_t uh[4], ul[4];
#pragma unroll
            for (int i=0;i<4;i++)
                split2(s0[(c8*8+2*i)*132+hw], s0[(c8*8+2*i+1)*132+hw], uh[i], ul[i]);
            size_t base = ((size_t)b*HW_ + q0 + hw)*64 + c8*8;
            *(uint4*)&g_fpT_h[base] = make_uint4(uh[0],uh[1],uh[2],uh[3]);
            *(uint4*)&g_fpT_l[base] = make_uint4(ul[0],ul[1],ul[2],ul[3]);
        }
    }
}

// ================= K1b_tc: QKV via tensor cores (64q, 128thr, 2/SM) =======
__global__ __launch_bounds__(128, 2) void k1b_tc(
    const float* __restrict__ wb,  const float* __restrict__ bbv,
    const float* __restrict__ wc2, const float* __restrict__ bc2,
    const float* __restrict__ wd,  const float* __restrict__ bd)
{
    extern __shared__ char sm[];
    __half* A_h = (__half*)(sm + QB_AH);
    __half* A_l = (__half*)(sm + QB_AL);
    float* bias_s = (float*)(sm + QB_BIAS);

    const int b = blockIdx.y, q0 = blockIdx.x*64, t = threadIdx.x;
    const int w = t>>5, lane = t&31;
    const int mh = w&1, nh = w>>1;       // m0 = mh*32, oc-half = nh*32
    const int m0 = mh*32;
    const int g = lane>>2, j4 = lane&3;

#pragma unroll
    for (int i=0;i<8;i++){
        int idx = t + i*128;
        int pl = idx>>9, r = (idx>>3)&63, j = idx&7;
        const __half* src = (pl ? g_fpT_l : g_fpT_h) + ((size_t)b*HW_+q0+r)*64 + j*8;
        CP_ASYNC16(smem_u32((pl?A_l:A_h) + r*PITCH + j*8), src);
    }
    CP_COMMIT();
    const float* Wsrc[3] = {wb, wc2, wd};
    for (int cv=0; cv<3; cv++){
        __half* WH = (__half*)(sm + QB_W) + (cv*2+0)*4608;
        __half* WL = (__half*)(sm + QB_W) + (cv*2+1)*4608;
        for (int f=t; f<1024; f+=128){
            int oc = f>>4, c4 = (f&15)*4;
            float4 v = *(const float4*)&Wsrc[cv][oc*64 + c4];
            uint32_t h0,l0,h1,l1;
            split2(v.x, v.y, h0, l0);
            split2(v.z, v.w, h1, l1);
            *(uint2*)&WH[oc*PITCH + c4] = make_uint2(h0, h1);
            *(uint2*)&WL[oc*PITCH + c4] = make_uint2(l0, l1);
        }
    }
    if (t < 64){ bias_s[t]=bbv[t]; bias_s[64+t]=bc2[t]; bias_s[128+t]=bd[t]; }
    CP_WAIT(0);
    __syncthreads();

    for (int cv=0; cv<3; cv++){
        const __half* WH = (const __half*)(sm + QB_W) + (cv*2+0)*4608;
        const __half* WL = (const __half*)(sm + QB_W) + (cv*2+1)*4608;
        float acc[2][4][4];
#pragma unroll
        for (int mf=0;mf<2;mf++)
#pragma unroll
            for (int nf=0;nf<4;nf++)
#pragma unroll
                for (int r=0;r<4;r++) acc[mf][nf][r]=0.f;

#pragma unroll
        for (int ks=0; ks<4; ks++){
            int col = ks*16 + 2*j4;
            uint32_t ah[2][4], al[2][4];
#pragma unroll
            for (int mf=0; mf<2; mf++){
                int r0 = m0 + mf*16 + g;
                ah[mf][0] = *(const uint32_t*)&A_h[(r0  )*PITCH + col];
                ah[mf][1] = *(const uint32_t*)&A_h[(r0+8)*PITCH + col];
                ah[mf][2] = *(const uint32_t*)&A_h[(r0  )*PITCH + col+8];
                ah[mf][3] = *(const uint32_t*)&A_h[(r0+8)*PITCH + col+8];
                al[mf][0] = *(const uint32_t*)&A_l[(r0  )*PITCH + col];
                al[mf][1] = *(const uint32_t*)&A_l[(r0+8)*PITCH + col];
                al[mf][2] = *(const uint32_t*)&A_l[(r0  )*PITCH + col+8];
                al[mf][3] = *(const uint32_t*)&A_l[(r0+8)*PITCH + col+8];
            }
#pragma unroll
            for (int nf=0; nf<4; nf++){
                int ocr = nh*32 + nf*8 + g;
                uint32_t wh0 = *(const uint32_t*)&WH[ocr*PITCH + col];
                uint32_t wh1 = *(const uint32_t*)&WH[ocr*PITCH + col+8];
                uint32_t wl0 = *(const uint32_t*)&WL[ocr*PITCH + col];
                uint32_t wl1 = *(const uint32_t*)&WL[ocr*PITCH + col+8];
#pragma unroll
                for (int mf=0; mf<2; mf++){
                    mma16816(acc[mf][nf], ah[mf], wh0, wh1);
                    mma16816(acc[mf][nf], al[mf], wh0, wh1);
                    mma16816(acc[mf][nf], ah[mf], wl0, wl1);
                }
            }
        }

        if (cv < 2){
            __half* dst = (cv==0) ? g_fbT_h : g_fcT_h;
#pragma unroll
            for (int mf=0; mf<2; mf++)
#pragma unroll
            for (int nf=0; nf<4; nf++){
                int oc = nh*32 + nf*8 + 2*j4;
                float b0v = bias_s[cv*64+oc], b1v = bias_s[cv*64+oc+1];
                int r0 = m0 + mf*16 + g;
                *(uint32_t*)&dst[((size_t)b*HW_+q0+r0  )*64 + oc] =
                    packh2(acc[mf][nf][0]+b0v, acc[mf][nf][1]+b1v);
                *(uint32_t*)&dst[((size_t)b*HW_+q0+r0+8)*64 + oc] =
                    packh2(acc[mf][nf][2]+b0v, acc[mf][nf][3]+b1v);
            }
        } else {
            __syncthreads();
            float* so = (float*)sm;    // [64 oc][68], reuses A region
#pragma unroll
            for (int mf=0; mf<2; mf++)
#pragma unroll
            for (int nf=0; nf<4; nf++)
#pragma unroll
            for (int r=0; r<4; r++){
                int oc = nh*32 + nf*8 + 2*j4 + (r&1);
                int hw = m0 + mf*16 + g + ((r>>1)*8);
                so[oc*68 + hw] = acc[mf][nf][r] + bias_s[128+oc];
            }
            __syncthreads();
            for (int f=t; f<1024; f+=128){
                int oc = f>>4, hg = (f&15)*4;
                *(uint2*)&g_fd_h[(size_t)(b*CI+oc)*HW_ + q0 + hg] = make_uint2(
                    packh2(so[oc*68+hg  ], so[oc*68+hg+1]),
                    packh2(so[oc*68+hg+2], so[oc*68+hg+3]));
            }
        }
    }
}

// ================= K2: Gram partials ======================================
__global__ __launch_bounds__(256) void k2_gram()
{
    __shared__ float fas[128*68];
    const int b = blockIdx.y, n0 = blockIdx.x*128, t = threadIdx.x;
    const int td = t & 15, tc = t >> 4;

    for (int f=t; f<2048; f+=256){
        int c = f>>5, nv = (f&31)<<2;
        float4 v = *(const float4*)&g_fcb[(size_t)(b*CI+c)*HW_ + n0 + nv];
        fas[(nv+0)*68+c]=v.x; fas[(nv+1)*68+c]=v.y;
        fas[(nv+2)*68+c]=v.z; fas[(nv+3)*68+c]=v.w;
    }
    __syncthreads();
    float acc[4][4];
#pragma unroll
    for (int i=0;i<4;i++)
#pragma unroll
        for (int j=0;j<4;j++) acc[i][j]=0.f;
#pragma unroll 4
    for (int nn=0;nn<128;nn++){
        float4 a = *(float4*)&fas[nn*68 + tc*4];
        float4 d = *(float4*)&fas[nn*68 + td*4];
        float av[4]={a.x,a.y,a.z,a.w}, dv[4]={d.x,d.y,d.z,d.w};
#pragma unroll
        for (int i=0;i<4;i++)
#pragma unroll
            for (int j=0;j<4;j++) acc[i][j] = fmaf(av[i], dv[j], acc[i][j]);
    }
#pragma unroll
    for (int i=0;i<4;i++)
#pragma unroll
        for (int j=0;j<4;j++)
            g_gpart[((size_t)((b*CI + tc*4+i)*CI) + td*4+j)*32 + blockIdx.x] = acc[i][j];
}

// ================= K3: channel softmax ====================================
__global__ void k3_csoft()
{
    __shared__ float sg[64];
    const int b = blockIdx.y, c = blockIdx.x, d = threadIdx.x;
    size_t base = ((size_t)((b*CI + c)*CI) + d)*32;
    float s = 0.f;
#pragma unroll
    for (int ch=0; ch<32; ch++) s += g_gpart[base+ch];
    sg[d] = s; __syncthreads();
    for (int o=32; o; o>>=1){ if (d<o) sg[d] = fminf(sg[d], sg[d+o]); __syncthreads(); }
    float mn = sg[0]; __syncthreads();
    float e = __expf(mn - s);
    sg[d] = e; __syncthreads();
    for (int o=32; o; o>>=1){ if (d<o) sg[d] += sg[d+o]; __syncthreads(); }
    g_attnc[(b*CI + c)*CI + d] = e * (1.f/sg[0]);
}

// ================= K4: flash attention (64q CTAs, 128thr, 2/SM) ===========
__device__ __forceinline__ void stage_tile(__half* dst, int kt, int b, int t){
    const int k0g = kt*64;
#pragma unroll
    for (int i=0;i<8;i++){
        int idx = t + i*128;
        int tl = idx>>9, r = (idx>>3)&63, j = idx&7;
        const __half* src = (tl==0)
            ? g_fcT_h + ((size_t)b*HW_ + k0g + r)*64 + j*8
            : g_fd_h  + ((size_t)(b*CI) + r)*HW_ + k0g + j*8;
        CP_ASYNC16(smem_u32(dst + tl*64*PITCH + r*PITCH + j*8), src);
    }
}

__global__ __launch_bounds__(128, 2) void k4_mma(const float* __restrict__ alpha)
{
    extern __shared__ char sm[];
    __half* fbH = (__half*)(sm + K4_FB);                 // 64 x 72
    __half* stg = (__half*)(sm + K4_STG);                // 3 x TILE_SZ
    float* rs_sm = (float*)(sm + K4_RS);                 // 2 x 64
    float* Opart = (float*)(sm + K4_STG);                // reuse: [64][65]

    const int b = blockIdx.y, q0 = blockIdx.x*64, t = threadIdx.x;
    const int w = t>>5, lane = t&31;
    const int qg = w>>1, kg = w&1;
    const int g = lane>>2, j4 = lane&3;

#pragma unroll
    for (int i=0;i<4;i++){
        int idx = t + i*128;
        int r = idx>>3, j = idx&7;
        *(uint4*)(fbH + r*PITCH + j*8) =
            *(const uint4*)(g_fbT_h + ((size_t)b*HW_ + q0 + r)*64 + j*8);
    }
    stage_tile(stg,           0, b, t); CP_COMMIT();
    stage_tile(stg + TILE_SZ, 1, b, t); CP_COMMIT();
    __syncthreads();

    uint32_t Ah[2][4][4];
#pragma unroll
    for (int mt=0; mt<2; mt++)
#pragma unroll
    for (int ct=0; ct<4; ct++){
        int q = qg*32 + mt*16;
        int cb = ct*16 + 2*j4;
        Ah[mt][ct][0] = *(const uint32_t*)&fbH[(q+g  )*PITCH + cb];
        Ah[mt][ct][1] = *(const uint32_t*)&fbH[(q+g+8)*PITCH + cb];
        Ah[mt][ct][2] = *(const uint32_t*)&fbH[(q+g  )*PITCH + cb + 8];
        Ah[mt][ct][3] = *(const uint32_t*)&fbH[(q+g+8)*PITCH + cb + 8];
    }

    float O[2][8][4];
#pragma unroll
    for (int mt=0;mt<2;mt++)
#pragma unroll
        for (int dt=0;dt<8;dt++)
#pragma unroll
            for (int r=0;r<4;r++) O[mt][dt][r]=0.f;
    float rsum[2][2] = {{0.f,0.f},{0.f,0.f}};

    for (int kt=0; kt<64; kt++){
        if (kt == 63) { CP_WAIT(0); } else { CP_WAIT(1); }
        __syncthreads();
        if (kt + 2 < 64){
            stage_tile(stg + (size_t)((kt+2)%3)*TILE_SZ, kt+2, b, t);
            CP_COMMIT();
        }
        const __half* buf = stg + (size_t)(kt%3)*TILE_SZ;
        const __half* fcH = buf;
        const __half* fdH = buf + 64*PITCH;

        float S[2][4][4];
#pragma unroll
        for (int mt=0;mt<2;mt++)
#pragma unroll
            for (int nt=0;nt<4;nt++)
#pragma unroll
                for (int r=0;r<4;r++) S[mt][nt][r]=0.f;
#pragma unroll
        for (int ct=0; ct<4; ct++){
            int cb = ct*16 + 2*j4;
#pragma unroll
            for (int nt=0; nt<4; nt++){
                int ka = kg*32 + nt*8 + g;
                uint32_t bh0 = *(const uint32_t*)&fcH[ka*PITCH + cb];
                uint32_t bh1 = *(const uint32_t*)&fcH[ka*PITCH + cb + 8];
#pragma unroll
                for (int mt=0; mt<2; mt++)
                    mma16816(S[mt][nt], Ah[mt][ct], bh0, bh1);
            }
        }

        uint32_t Ph[2][2][4];
#pragma unroll
        for (int mt=0; mt<2; mt++)
#pragma unroll
        for (int nt=0; nt<4; nt++){
            float e0 = __expf(S[mt][nt][0] - SHIFT);
            float e1 = __expf(S[mt][nt][1] - SHIFT);
            float e2 = __expf(S[mt][nt][2] - SHIFT);
            float e3 = __expf(S[mt][nt][3] - SHIFT);
            rsum[mt][0] += e0+e1;
            rsum[mt][1] += e2+e3;
            int k2 = nt>>1, hf = (nt&1)*2;
            Ph[mt][k2][hf+0] = packh2(e0, e1);
            Ph[mt][k2][hf+1] = packh2(e2, e3);
        }

#pragma unroll
        for (int dt=0; dt<8; dt++){
            int d = dt*8 + g;
#pragma unroll
            for (int k2=0; k2<2; k2++){
                int kb = kg*32 + k2*16 + 2*j4;
                uint32_t bh0 = *(const uint32_t*)&fdH[d*PITCH + kb];
                uint32_t bh1 = *(const uint32_t*)&fdH[d*PITCH + kb + 8];
#pragma unroll
                for (int mt=0; mt<2; mt++)
                    mma16816(O[mt][dt], Ph[mt][k2], bh0, bh1);
            }
        }
    }

#pragma unroll
    for (int mt=0; mt<2; mt++)
#pragma unroll
    for (int rr=0; rr<2; rr++){
        float v = rsum[mt][rr];
        v += __shfl_xor_sync(0xffffffffu, v, 1);
        v += __shfl_xor_sync(0xffffffffu, v, 2);
        if (j4 == 0) rs_sm[kg*64 + qg*32 + mt*16 + rr*8 + g] = v;
    }
    __syncthreads();
    if (kg == 1){
#pragma unroll
        for (int mt=0; mt<2; mt++)
#pragma unroll
        for (int dt=0; dt<8; dt++){
            int q = qg*32 + mt*16, d = dt*8 + 2*j4;
            Opart[(q+g  )*65 + d  ] = O[mt][dt][0];
            Opart[(q+g  )*65 + d+1] = O[mt][dt][1];
            Opart[(q+g+8)*65 + d  ] = O[mt][dt][2];
            Opart[(q+g+8)*65 + d+1] = O[mt][dt][3];
        }
    }
    __syncthreads();
    const float a0 = alpha[0];
    if (kg == 0){
#pragma unroll
        for (int mt=0; mt<2; mt++){
            int q = qg*32 + mt*16;
            float i0 = a0 / (rs_sm[q+g  ] + rs_sm[64+q+g  ]);
            float i1 = a0 / (rs_sm[q+g+8] + rs_sm[64+q+g+8]);
#pragma unroll
            for (int dt=0; dt<8; dt++){
                int d = dt*8 + 2*j4;
                Opart[(q+g  )*65+d  ] = (O[mt][dt][0] + Opart[(q+g  )*65+d  ]) * i0;
                Opart[(q+g  )*65+d+1] = (O[mt][dt][1] + Opart[(q+g  )*65+d+1]) * i0;
                Opart[(q+g+8)*65+d  ] = (O[mt][dt][2] + Opart[(q+g+8)*65+d  ]) * i1;
                Opart[(q+g+8)*65+d+1] = (O[mt][dt][3] + Opart[(q+g+8)*65+d+1]) * i1;
            }
        }
    }
    __syncthreads();
#pragma unroll
    for (int i=0; i<8; i++){
        int idx = t + i*128;
        int d = idx>>4, q4 = idx&15;
        size_t base = (size_t)(b*CI+d)*HW_ + q0 + q4*4;
        float4 f = *(const float4*)&g_fp[base];
        *(float4*)&g_featp[base] = make_float4(
            Opart[(q4*4+0)*65+d] + f.x, Opart[(q4*4+1)*65+d] + f.y,
            Opart[(q4*4+2)*65+d] + f.z, Opart[(q4*4+3)*65+d] + f.w);
    }
}

// ================= K5: fusion -> fp16 hi/lo planes ========================
__global__ __launch_bounds__(256) void k5_fuse(const float* __restrict__ beta)
{
    extern __shared__ float sm5[];
    float* at  = sm5;
    float* fat = sm5 + 4096;
    const int b = blockIdx.y, q0 = blockIdx.x*128, t = threadIdx.x;
    const int tq = t & 15, tc = t >> 4;

    for (int f=t; f<1024; f+=256)
        *(float4*)&at[f*4] = *(const float4*)&g_attnc[(size_t)b*CI*CI + f*4];
    for (int f=t; f<2048; f+=256){
        int c = f>>5, qv = (f&31)<<2;
        *(float4*)&fat[c*132+qv] =
            *(const float4*)&g_fcb[(size_t)(b*CI+c)*HW_ + q0 + qv];
    }
    __syncthreads();
    float acc[4][8];
#pragma unroll
    for (int i=0;i<4;i++)
#pragma unroll
        for (int j=0;j<8;j++) acc[i][j]=0.f;
#pragma unroll 4
    for (int d=0; d<CI; d++){
        float4 x0 = *(float4*)&fat[d*132 + tq*8];
        float4 x1 = *(float4*)&fat[d*132 + tq*8 + 4];
        float xv[8] = {x0.x,x0.y,x0.z,x0.w,x1.x,x1.y,x1.z,x1.w};
#pragma unroll
        for (int i=0;i<4;i++){
            float w = at[(tc*4+i)*CI + d];
#pragma unroll
            for (int j=0;j<8;j++) acc[i][j] = fmaf(w, xv[j], acc[i][j]);
        }
    }
    const float b0 = beta[0];
    float r[4][8];
#pragma unroll
    for (int i=0;i<4;i++){
        int c = tc*4+i;
        size_t base = (size_t)(b*CI+c)*HW_ + q0 + tq*8;
        float4 p0 = *(const float4*)&g_featp[base];
        float4 p1 = *(const float4*)&g_featp[base+4];
        float pv[8] = {p0.x,p0.y,p0.z,p0.w,p1.x,p1.y,p1.z,p1.w};
#pragma unroll
        for (int j=0;j<8;j++)
            r[i][j] = pv[j] + fmaf(b0, acc[i][j], fat[c*132+tq*8+j]);
    }
    __syncthreads();
#pragma unroll
    for (int i=0;i<4;i++)
#pragma unroll
        for (int j=0;j<8;j++)
            fat[(tc*4+i)*132 + tq*8+j] = r[i][j];
    __syncthreads();
    for (int f=t; f<1024; f+=256){
        int hw = f&127, c8 = f>>7;
        uint32_t uh[4], ul[4];
#pragma unroll
        for (int i=0;i<4;i++)
            split2(fat[(c8*8+2*i)*132+hw], fat[(c8*8+2*i+1)*132+hw], uh[i], ul[i]);
        size_t base = ((size_t)b*HW_ + q0 + hw)*64 + c8*8;
        *(uint4*)&g_fusT_h[base] = make_uint4(uh[0],uh[1],uh[2],uh[3]);
        *(uint4*)&g_fusT_l[base] = make_uint4(ul[0],ul[1],ul[2],ul[3]);
    }
}

// ================= K6_tc: out conv via tensor cores =======================
__global__ __launch_bounds__(256, 1) void k6_tc(
    const float* __restrict__ go, const float* __restrict__ bo,
    const float* __restrict__ mo, const float* __restrict__ vo,
    float* __restrict__ out)
{
    extern __shared__ char sm[];
    __half* A_h = (__half*)(sm + K6_AH);
    __half* A_l = (__half*)(sm + K6_AL);
    __half* W_h = (__half*)(sm + K6_WH);
    __half* W_l = (__half*)(sm + K6_WL);
    float*  so  = (float*)(sm + K6_SO);
    float* bninv = (float*)(sm + K6_BN);
    float* bnsh  = bninv + 512;

    const int b = blockIdx.y, q0 = blockIdx.x*128, t = threadIdx.x;
    const int w = t>>5, lane = t&31;
    const int mh = w&3, nh = w>>2;
    const int m0 = mh*32;
    const int g = lane>>2, j4 = lane&3;

#pragma unroll
    for (int i=0;i<8;i++){
        int idx = t + i*256;
        int pl = idx>>10, r = (idx>>3)&127, j = idx&7;
        const __half* src = (pl ? g_fusT_l : g_fusT_h) + ((size_t)b*HW_+q0+r)*64 + j*8;
        CP_ASYNC16(smem_u32((pl?A_l:A_h) + r*PITCH + j*8), src);
    }
    CP_COMMIT();
    for (int f=t; f<512; f+=256){
        float inv = go[f]*rsqrtf(vo[f]+EPSN);
        bninv[f] = inv; bnsh[f] = bo[f] - mo[f]*inv;
    }
    CP_WAIT(0);
    __syncthreads();

    for (int co=0; co<4; co++){
#pragma unroll
        for (int i=0;i<8;i++){
            int idx = t + i*256;
            int pl = idx>>10, r = (idx>>3)&127, j = idx&7;
            const __half* src = (pl ? g_wol : g_woh) + (size_t)(co*128+r)*64 + j*8;
            CP_ASYNC16(smem_u32((pl?W_l:W_h) + r*PITCH + j*8), src);
        }
        CP_COMMIT(); CP_WAIT(0);
        __syncthreads();

        float acc[2][8][4];
#pragma unroll
        for (int mf=0;mf<2;mf++)
#pragma unroll
            for (int nf=0;nf<8;nf++)
#pragma unroll
                for (int r=0;r<4;r++) acc[mf][nf][r]=0.f;

#pragma unroll
        for (int ks=0; ks<4; ks++){
            int col = ks*16 + 2*j4;
            uint32_t ah[2][4], al[2][4];
#pragma unroll
            for (int mf=0; mf<2; mf++){
                int r0 = m0 + mf*16 + g;
                ah[mf][0] = *(const uint32_t*)&A_h[(r0  )*PITCH + col];
                ah[mf][1] = *(const uint32_t*)&A_h[(r0+8)*PITCH + col];
                ah[mf][2] = *(const uint32_t*)&A_h[(r0  )*PITCH + col+8];
                ah[mf][3] = *(const uint32_t*)&A_h[(r0+8)*PITCH + col+8];
                al[mf][0] = *(const uint32_t*)&A_l[(r0  )*PITCH + col];
                al[mf][1] = *(const uint32_t*)&A_l[(r0+8)*PITCH + col];
                al[mf][2] = *(const uint32_t*)&A_l[(r0  )*PITCH + col+8];
                al[mf][3] = *(const uint32_t*)&A_l[(r0+8)*PITCH + col+8];
            }
#pragma unroll
            for (int nf=0; nf<8; nf++){
                int ocr = nh*64 + nf*8 + g;
                uint32_t wh0 = *(const uint32_t*)&W_h[ocr*PITCH + col];
                uint32_t wh1 = *(const uint32_t*)&W_h[ocr*PITCH + col+8];
                uint32_t wl0 = *(const uint32_t*)&W_l[ocr*PITCH + col];
                uint32_t wl1 = *(const uint32_t*)&W_l[ocr*PITCH + col+8];
#pragma unroll
                for (int mf=0; mf<2; mf++){
                    mma16816(acc[mf][nf], ah[mf], wh0, wh1);
                    mma16816(acc[mf][nf], al[mf], wh0, wh1);
                    mma16816(acc[mf][nf], ah[mf], wl0, wl1);
                }
            }
        }
#pragma unroll
        for (int mf=0; mf<2; mf++)
#pragma unroll
        for (int nf=0; nf<8; nf++)
#pragma unroll
        for (int r=0; r<4; r++){
            int ocl = nh*64 + nf*8 + 2*j4 + (r&1);
            int hw = m0 + mf*16 + g + ((r>>1)*8);
            so[ocl*132 + hw] = fmaf(acc[mf][nf][r], bninv[co*128+ocl], bnsh[co*128+ocl]);
        }
        __syncthreads();
        for (int f=t; f<4096; f+=256){
            int ocl = f>>5, hg = (f&31)*4;
            *(float4*)&out[(size_t)(b*CIN + co*128 + ocl)*HW_ + q0 + hg] =
                make_float4(so[ocl*132+hg], so[ocl*132+hg+1],
                            so[ocl*132+hg+2], so[ocl*132+hg+3]);
        }
        __syncthreads();
    }
}

// ================= launch ==================================================
extern "C" void kernel_launch(void* const* d_in, const int* in_sizes, int n_in,
                              void* d_out, int out_size)
{
    const float* x   = (const float*)d_in[0];
    const float* wp1 = (const float*)d_in[1];
    const float* gp1 = (const float*)d_in[2];
    const float* bp1 = (const float*)d_in[3];
    const float* mp1 = (const float*)d_in[4];
    const float* vp1 = (const float*)d_in[5];
    const float* wc1 = (const float*)d_in[6];
    const float* gc1 = (const float*)d_in[7];
    const float* bc1 = (const float*)d_in[8];
    const float* mc1 = (const float*)d_in[9];
    const float* vc1 = (const float*)d_in[10];
    const float* wb  = (const float*)d_in[11];
    const float* bb  = (const float*)d_in[12];
    const float* wc2 = (const float*)d_in[13];
    const float* bc2 = (const float*)d_in[14];
    const float* wd  = (const float*)d_in[15];
    const float* bd  = (const float*)d_in[16];
    const float* alpha = (const float*)d_in[17];
    const float* beta  = (const float*)d_in[18];
    const float* wo  = (const float*)d_in[19];
    const float* go  = (const float*)d_in[20];
    const float* bo  = (const float*)d_in[21];
    const float* mo  = (const float*)d_in[22];
    const float* vo  = (const float*)d_in[23];
    float* out = (float*)d_out;

    const int K1_SMEM  = 3*CH_BYTES + 1024;            // 222208
    const int K1B_SMEM = QB_TOTAL;                     // 74752
    const int K4_SMEM  = K4_TOTAL;                     // 65024
    const int K5_SMEM  = (4096 + 64*132)*4;            // 50176
    const int K6_SMEM  = K6_TOTAL;                     // 145408
    cudaFuncSetAttribute(k1_tc,   cudaFuncAttributeMaxDynamicSharedMemorySize, K1_SMEM);
    cudaFuncSetAttribute(k1b_tc,  cudaFuncAttributeMaxDynamicSharedMemorySize, K1B_SMEM);
    cudaFuncSetAttribute(k4_mma,  cudaFuncAttributeMaxDynamicSharedMemorySize, K4_SMEM);
    cudaFuncSetAttribute(k5_fuse, cudaFuncAttributeMaxDynamicSharedMemorySize, K5_SMEM);
    cudaFuncSetAttribute(k6_tc,   cudaFuncAttributeMaxDynamicSharedMemorySize, K6_SMEM);

    k0w_planes<<<3, 256>>>(wp1, wc1, wo);
    k0x_planes<<<dim3(64, 8, B_), 256>>>(x);
    k1_tc     <<<dim3(32, B_), 256, K1_SMEM>>>(gp1,bp1,mp1,vp1, gc1,bc1,mc1,vc1);
    k1b_tc    <<<dim3(64, B_), 128, K1B_SMEM>>>(wb, bb, wc2, bc2, wd, bd);
    k2_gram   <<<dim3(32, B_), 256>>>();
    k3_csoft  <<<dim3(CI, B_), 64>>>();
    k4_mma    <<<dim3(64, B_), 128, K4_SMEM>>>(alpha);
    k5_fuse   <<<dim3(32, B_), 256, K5_SMEM>>>(beta);
    k6_tc     <<<dim3(32, B_), 256, K6_SMEM>>>(go, bo, mo, vo, out);
}

// round 12
// speedup vs baseline: 1.0095x; 1.0095x over previous
#include <cuda_runtime.h>
#include <cuda_fp16.h>
#include <cstdint>
#include <math_constants.h>

#define B_   4
#define CIN  512
#define CI   64
#define HW_  4096
#define EPSN 1e-5f
#define PITCH 72
#define SHIFT 12.0f
#define TILE_SZ (2*64*PITCH)   // halfs per staged k4 tile (fcH, fdH)

// k1_tc chunk geometry (halfs)
#define CH_XH 0
#define CH_XL 9216
#define CH_W  18432
#define CH_HALFS (18432 + 18432)
#define CH_BYTES (CH_HALFS*2)

// k1b_tc smem (bytes) - 64q version
#define QB_AH 0
#define QB_AL 9216
#define QB_W  18432
#define QB_BIAS (18432 + 55296)     // 73728
#define QB_TOTAL (QB_BIAS + 1024)   // 74752

// k6_tc smem (bytes)
#define K6_AH 0
#define K6_AL 18432
#define K6_WH 36864
#define K6_WL (36864 + 18432)
#define K6_SO 73728
#define K6_BN (73728 + 67584)
#define K6_TOTAL (K6_BN + 4096)     // 145408

// k4 smem (bytes) - 64q version
#define K4_FB 0
#define K4_STG 9216
#define K4_RS (9216 + 3*TILE_SZ*2)  // 64512
#define K4_TOTAL (K4_RS + 512)      // 65024

#define GCH 16   // gram k-chunks

// ---------------- scratch (device globals; no allocation) ----------------
__device__ float g_fp    [B_*CI*HW_];
__device__ float g_fcb   [B_*CI*HW_];
__device__ float g_featp [B_*CI*HW_];
__device__ float g_gpart [B_*CI*CI*GCH];
__device__ float g_attnc [B_*CI*CI];
__device__ __align__(16) __half g_xT_h [B_*HW_*CIN];
__device__ __align__(16) __half g_xT_l [B_*HW_*CIN];
__device__ __align__(16) __half g_wh   [2][CI*CIN];
__device__ __align__(16) __half g_wl   [2][CI*CIN];
__device__ __align__(16) __half g_woh  [CIN*CI];
__device__ __align__(16) __half g_wol  [CIN*CI];
__device__ __align__(16) __half g_qwh  [3][CI*CI];   // wb, wc2, wd
__device__ __align__(16) __half g_qwl  [3][CI*CI];
__device__ __align__(16) __half g_fpT_h[B_*HW_*CI];
__device__ __align__(16) __half g_fpT_l[B_*HW_*CI];
__device__ __align__(16) __half g_cb_h [B_*CI*HW_];  // fcb [c][hw] planes
__device__ __align__(16) __half g_cb_l [B_*CI*HW_];
__device__ __align__(16) __half g_fusT_h[B_*HW_*CI];
__device__ __align__(16) __half g_fusT_l[B_*HW_*CI];
__device__ __align__(16) __half g_fbT_h[B_*HW_*CI];
__device__ __align__(16) __half g_fcT_h[B_*HW_*CI];
__device__ __align__(16) __half g_fd_h [B_*CI*HW_];

// ---------------- helpers ----------------
__device__ __forceinline__ uint32_t smem_u32(const void* p){
    uint32_t a;
    asm("{ .reg .u64 t; cvta.to.shared.u64 t, %1; cvt.u32.u64 %0, t; }" : "=r"(a) : "l"(p));
    return a;
}
#define CP_ASYNC16(dst, src) asm volatile("cp.async.cg.shared.global [%0], [%1], 16;" :: "r"(dst), "l"(src))
#define CP_COMMIT()          asm volatile("cp.async.commit_group;")
#define CP_WAIT(n)           asm volatile("cp.async.wait_group %0;" :: "n"(n))

__device__ __forceinline__ void mma16816(float c[4], const uint32_t a[4],
                                         uint32_t b0, uint32_t b1){
    asm volatile("mma.sync.aligned.m16n8k16.row.col.f32.f16.f16.f32 "
        "{%0,%1,%2,%3}, {%4,%5,%6,%7}, {%8,%9}, {%0,%1,%2,%3};"
        : "+f"(c[0]), "+f"(c[1]), "+f"(c[2]), "+f"(c[3])
        : "r"(a[0]), "r"(a[1]), "r"(a[2]), "r"(a[3]), "r"(b0), "r"(b1));
}
__device__ __forceinline__ uint32_t packh2(float a, float b){
    __half2 v = __floats2half2_rn(a, b);
    return *(uint32_t*)&v;
}
__device__ __forceinline__ void split2(float v0, float v1, uint32_t& h, uint32_t& l){
    __half2 h2 = __floats2half2_rn(v0, v1);
    __half2 l2 = __floats2half2_rn(v0 - __half2float(h2.x), v1 - __half2float(h2.y));
    h = *(uint32_t*)&h2; l = *(uint32_t*)&l2;
}

// ================= K0w: big weights ========================================
__global__ void k0w_planes(const float* __restrict__ wp1,
                           const float* __restrict__ wc1,
                           const float* __restrict__ wo)
{
    const int which = blockIdx.x;
    const float* w = (which==0) ? wp1 : (which==1) ? wc1 : wo;
    __half* dh = (which==0) ? g_wh[0] : (which==1) ? g_wh[1] : g_woh;
    __half* dl = (which==0) ? g_wl[0] : (which==1) ? g_wl[1] : g_wol;
    for (int f = threadIdx.x; f < CI*CIN/4; f += 256){
        float4 v = *(const float4*)&w[f*4];
        uint32_t h0,l0,h1,l1;
        split2(v.x, v.y, h0, l0);
        split2(v.z, v.w, h1, l1);
        *(uint2*)&dh[f*4] = make_uint2(h0, h1);
        *(uint2*)&dl[f*4] = make_uint2(l0, l1);
    }
}

// ================= K0q: QKV weights ========================================
__global__ void k0q_planes(const float* __restrict__ wb,
                           const float* __restrict__ wc2,
                           const float* __restrict__ wd)
{
    const int cv = blockIdx.x;
    const float* w = (cv==0) ? wb : (cv==1) ? wc2 : wd;
    for (int f = threadIdx.x; f < CI*CI/4; f += 256){
        float4 v = *(const float4*)&w[f*4];
        uint32_t h0,l0,h1,l1;
        split2(v.x, v.y, h0, l0);
        split2(v.z, v.w, h1, l1);
        *(uint2*)&g_qwh[cv][f*4] = make_uint2(h0, h1);
        *(uint2*)&g_qwl[cv][f*4] = make_uint2(l0, l1);
    }
}

// ================= K0x =====================================================
__global__ __launch_bounds__(256) void k0x_planes(const float* __restrict__ x)
{
    __shared__ float ts[64*68];
    const int hw0 = blockIdx.x*64, c0 = blockIdx.y*64, b = blockIdx.z;
    const int t = threadIdx.x;
    for (int f=t; f<1024; f+=256){
        int cc = f>>4, qv = (f&15)<<2;
        *(float4*)&ts[cc*68+qv] =
            *(const float4*)&x[(size_t)(b*CIN + c0+cc)*HW_ + hw0 + qv];
    }
    __syncthreads();
    for (int f=t; f<512; f+=256){
        int hw = f>>3, j8 = f&7;
        uint32_t uh[4], ul[4];
#pragma unroll
        for (int i=0;i<4;i++)
            split2(ts[(j8*8+2*i)*68 + hw], ts[(j8*8+2*i+1)*68 + hw], uh[i], ul[i]);
        size_t base = ((size_t)b*HW_ + hw0 + hw)*CIN + c0 + j8*8;
        *(uint4*)&g_xT_h[base] = make_uint4(uh[0],uh[1],uh[2],uh[3]);
        *(uint4*)&g_xT_l[base] = make_uint4(ul[0],ul[1],ul[2],ul[3]);
    }
}

// ================= K1_tc ===================================================
__device__ __forceinline__ void k1_stage(char* smbase, int buf, int chunk,
                                         int b, int q0, int t){
    __half* base = (__half*)(smbase + (size_t)buf*CH_BYTES);
#pragma unroll
    for (int i=0;i<8;i++){
        int idx = t + i*256;
        int pl = idx>>10, r = (idx>>3)&127, j = idx&7;
        const __half* src = (pl ? g_xT_l : g_xT_h)
                            + ((size_t)b*HW_ + q0 + r)*CIN + chunk*64 + j*8;
        CP_ASYNC16(smem_u32(base + (pl?CH_XL:CH_XH) + r*PITCH + j*8), src);
    }
#pragma unroll
    for (int i=0;i<8;i++){
        int idx = t + i*256;
        int conv = idx>>10, pl = (idx>>9)&1, oc = (idx>>3)&63, j = idx&7;
        const __half* src = (pl ? g_wl[conv] : g_wh[conv]) + oc*CIN + chunk*64 + j*8;
        CP_ASYNC16(smem_u32(base + CH_W + (conv*2+pl)*4608 + oc*PITCH + j*8), src);
    }
}

__global__ __launch_bounds__(256, 1) void k1_tc(
    const float* __restrict__ gp1, const float* __restrict__ bp1,
    const float* __restrict__ mp1, const float* __restrict__ vp1,
    const float* __restrict__ gc1, const float* __restrict__ bc1,
    const float* __restrict__ mc1, const float* __restrict__ vc1)
{
    extern __shared__ char sm[];
    float* binv = (float*)(sm + 3*CH_BYTES);
    float* bsh  = binv + 128;

    const int b = blockIdx.y, q0 = blockIdx.x*128, t = threadIdx.x;
    const int w = t>>5, lane = t&31;
    const int mh = w&3, nh = w>>2;
    const int m0 = mh*32;
    const int g = lane>>2, j4 = lane&3;

    if (t < 64){
        binv[t] = gp1[t]*rsqrtf(vp1[t]+EPSN);
        bsh [t] = bp1[t] - mp1[t]*binv[t];
    } else if (t < 128){
        int o = t-64;
        binv[64+o] = gc1[o]*rsqrtf(vc1[o]+EPSN);
        bsh [64+o] = bc1[o] - mc1[o]*binv[64+o];
    }

    k1_stage(sm, 0, 0, b, q0, t); CP_COMMIT();
    k1_stage(sm, 1, 1, b, q0, t); CP_COMMIT();

    float acc[2][8][4];
#pragma unroll
    for (int mf=0;mf<2;mf++)
#pragma unroll
        for (int nf=0;nf<8;nf++)
#pragma unroll
            for (int r=0;r<4;r++) acc[mf][nf][r]=0.f;

    for (int c=0; c<8; c++){
        if (c == 7) { CP_WAIT(0); } else { CP_WAIT(1); }
        __syncthreads();
        if (c + 2 < 8){ k1_stage(sm, (c+2)%3, c+2, b, q0, t); CP_COMMIT(); }
        __half* base = (__half*)(sm + (size_t)(c%3)*CH_BYTES);
        const __half* wbH = base + CH_W + (nh*2+0)*4608;
        const __half* wbL = base + CH_W + (nh*2+1)*4608;

#pragma unroll
        for (int ks=0; ks<4; ks++){
            int col = ks*16 + 2*j4;
            uint32_t ah[2][4], al[2][4];
#pragma unroll
            for (int mf=0; mf<2; mf++){
                int r0 = m0 + mf*16 + g;
                ah[mf][0] = *(const uint32_t*)&base[CH_XH + (r0  )*PITCH + col];
                ah[mf][1] = *(const uint32_t*)&base[CH_XH + (r0+8)*PITCH + col];
                ah[mf][2] = *(const uint32_t*)&base[CH_XH + (r0  )*PITCH + col+8];
                ah[mf][3] = *(const uint32_t*)&base[CH_XH + (r0+8)*PITCH + col+8];
                al[mf][0] = *(const uint32_t*)&base[CH_XL + (r0  )*PITCH + col];
                al[mf][1] = *(const uint32_t*)&base[CH_XL + (r0+8)*PITCH + col];
                al[mf][2] = *(const uint32_t*)&base[CH_XL + (r0  )*PITCH + col+8];
                al[mf][3] = *(const uint32_t*)&base[CH_XL + (r0+8)*PITCH + col+8];
            }
#pragma unroll
            for (int nf=0; nf<8; nf++){
                int ocr = nf*8 + g;
                uint32_t wh0 = *(const uint32_t*)&wbH[ocr*PITCH + col];
                uint32_t wh1 = *(const uint32_t*)&wbH[ocr*PITCH + col+8];
                uint32_t wl0 = *(const uint32_t*)&wbL[ocr*PITCH + col];
                uint32_t wl1 = *(const uint32_t*)&wbL[ocr*PITCH + col+8];
#pragma unroll
                for (int mf=0; mf<2; mf++){
                    mma16816(acc[mf][nf], ah[mf], wh0, wh1);
                    mma16816(acc[mf][nf], al[mf], wh0, wh1);
                    mma16816(acc[mf][nf], ah[mf], wl0, wl1);
                }
            }
        }
    }
    __syncthreads();

    float* so = (float*)(sm + (size_t)nh*36864);
#pragma unroll
    for (int mf=0; mf<2; mf++)
#pragma unroll
    for (int nf=0; nf<8; nf++)
#pragma unroll
    for (int r=0; r<4; r++){
        int oc = nf*8 + 2*j4 + (r&1);
        int hw = m0 + mf*16 + g + ((r>>1)*8);
        so[oc*132 + hw] = fmaf(acc[mf][nf][r], binv[nh*64+oc], bsh[nh*64+oc]);
    }
    __syncthreads();
    for (int f=t; f<4096; f+=256){
        int conv = f>>11, oc = (f>>5)&63, hg = (f&31)*4;
        const float* s = (const float*)(sm + (size_t)conv*36864);
        float4 v = make_float4(s[oc*132+hg], s[oc*132+hg+1],
                               s[oc*132+hg+2], s[oc*132+hg+3]);
        float* dst = conv ? g_fcb : g_fp;
        *(float4*)&dst[(size_t)(b*CI+oc)*HW_ + q0 + hg] = v;
    }
    {   // fpT planes (transposed) from conv0
        const float* s0 = (const float*)sm;
        for (int f=t; f<1024; f+=256){
            int hw = f&127, c8 = f>>7;
            uint32_t uh[4], ul[4];
#pragma unroll
            for (int i=0;i<4;i++)
                split2(s0[(c8*8+2*i)*132+hw], s0[(c8*8+2*i+1)*132+hw], uh[i], ul[i]);
            size_t base = ((size_t)b*HW_ + q0 + hw)*64 + c8*8;
            *(uint4*)&g_fpT_h[base] = make_uint4(uh[0],uh[1],uh[2],uh[3]);
            *(uint4*)&g_fpT_l[base] = make_uint4(ul[0],ul[1],ul[2],ul[3]);
        }
    }
    {   // fcb planes (same [c][hw] layout) from conv1, for tensor gram
        const float* s1 = (const float*)(sm + 36864);
        for (int f=t; f<2048; f+=256){
            int oc = f>>5, hg = (f&31)*4;
            uint32_t h0,l0,h1,l1;
            split2(s1[oc*132+hg  ], s1[oc*132+hg+1], h0, l0);
            split2(s1[oc*132+hg+2], s1[oc*132+hg+3], h1, l1);
            size_t off = (size_t)(b*CI+oc)*HW_ + q0 + hg;
            *(uint2*)&g_cb_h[off] = make_uint2(h0, h1);
            *(uint2*)&g_cb_l[off] = make_uint2(l0, l1);
        }
    }
}

// ================= K1b_tc: QKV via tensor cores (64q, 128thr, 2/SM) =======
__global__ __launch_bounds__(128, 2) void k1b_tc(
    const float* __restrict__ bbv, const float* __restrict__ bc2,
    const float* __restrict__ bd)
{
    extern __shared__ char sm[];
    __half* A_h = (__half*)(sm + QB_AH);
    __half* A_l = (__half*)(sm + QB_AL);
    float* bias_s = (float*)(sm + QB_BIAS);

    const int b = blockIdx.y, q0 = blockIdx.x*64, t = threadIdx.x;
    const int w = t>>5, lane = t&31;
    const int mh = w&1, nh = w>>1;
    const int m0 = mh*32;
    const int g = lane>>2, j4 = lane&3;

#pragma unroll
    for (int i=0;i<8;i++){
        int idx = t + i*128;
        int pl = idx>>9, r = (idx>>3)&63, j = idx&7;
        const __half* src = (pl ? g_fpT_l : g_fpT_h) + ((size_t)b*HW_+q0+r)*64 + j*8;
        CP_ASYNC16(smem_u32((pl?A_l:A_h) + r*PITCH + j*8), src);
    }
    // weights: 6 regions (cv*2+pl) x 64 oc x 8 j-groups
#pragma unroll
    for (int i=0;i<24;i++){
        int idx = t + i*128;
        int reg = idx>>9, r = (idx>>3)&63, j = idx&7;
        int cv = reg>>1, pl = reg&1;
        const __half* src = (pl ? g_qwl[cv] : g_qwh[cv]) + r*64 + j*8;
        CP_ASYNC16(smem_u32((__half*)(sm + QB_W) + reg*4608 + r*PITCH + j*8), src);
    }
    CP_COMMIT();
    if (t < 64){ bias_s[t]=bbv[t]; bias_s[64+t]=bc2[t]; bias_s[128+t]=bd[t]; }
    CP_WAIT(0);
    __syncthreads();

    for (int cv=0; cv<3; cv++){
        const __half* WH = (const __half*)(sm + QB_W) + (cv*2+0)*4608;
        const __half* WL = (const __half*)(sm + QB_W) + (cv*2+1)*4608;
        float acc[2][4][4];
#pragma unroll
        for (int mf=0;mf<2;mf++)
#pragma unroll
            for (int nf=0;nf<4;nf++)
#pragma unroll
                for (int r=0;r<4;r++) acc[mf][nf][r]=0.f;

#pragma unroll
        for (int ks=0; ks<4; ks++){
            int col = ks*16 + 2*j4;
            uint32_t ah[2][4], al[2][4];
#pragma unroll
            for (int mf=0; mf<2; mf++){
                int r0 = m0 + mf*16 + g;
                ah[mf][0] = *(const uint32_t*)&A_h[(r0  )*PITCH + col];
                ah[mf][1] = *(const uint32_t*)&A_h[(r0+8)*PITCH + col];
                ah[mf][2] = *(const uint32_t*)&A_h[(r0  )*PITCH + col+8];
                ah[mf][3] = *(const uint32_t*)&A_h[(r0+8)*PITCH + col+8];
                al[mf][0] = *(const uint32_t*)&A_l[(r0  )*PITCH + col];
                al[mf][1] = *(const uint32_t*)&A_l[(r0+8)*PITCH + col];
                al[mf][2] = *(const uint32_t*)&A_l[(r0  )*PITCH + col+8];
                al[mf][3] = *(const uint32_t*)&A_l[(r0+8)*PITCH + col+8];
            }
#pragma unroll
            for (int nf=0; nf<4; nf++){
                int ocr = nh*32 + nf*8 + g;
                uint32_t wh0 = *(const uint32_t*)&WH[ocr*PITCH + col];
                uint32_t wh1 = *(const uint32_t*)&WH[ocr*PITCH + col+8];
                uint32_t wl0 = *(const uint32_t*)&WL[ocr*PITCH + col];
                uint32_t wl1 = *(const uint32_t*)&WL[ocr*PITCH + col+8];
#pragma unroll
                for (int mf=0; mf<2; mf++){
                    mma16816(acc[mf][nf], ah[mf], wh0, wh1);
                    mma16816(acc[mf][nf], al[mf], wh0, wh1);
                    mma16816(acc[mf][nf], ah[mf], wl0, wl1);
                }
            }
        }

        if (cv < 2){
            __half* dst = (cv==0) ? g_fbT_h : g_fcT_h;
#pragma unroll
            for (int mf=0; mf<2; mf++)
#pragma unroll
            for (int nf=0; nf<4; nf++){
                int oc = nh*32 + nf*8 + 2*j4;
                float b0v = bias_s[cv*64+oc], b1v = bias_s[cv*64+oc+1];
                int r0 = m0 + mf*16 + g;
                *(uint32_t*)&dst[((size_t)b*HW_+q0+r0  )*64 + oc] =
                    packh2(acc[mf][nf][0]+b0v, acc[mf][nf][1]+b1v);
                *(uint32_t*)&dst[((size_t)b*HW_+q0+r0+8)*64 + oc] =
                    packh2(acc[mf][nf][2]+b0v, acc[mf][nf][3]+b1v);
            }
        } else {
            __syncthreads();
            float* so = (float*)sm;    // [64 oc][68]
#pragma unroll
            for (int mf=0; mf<2; mf++)
#pragma unroll
            for (int nf=0; nf<4; nf++)
#pragma unroll
            for (int r=0; r<4; r++){
                int oc = nh*32 + nf*8 + 2*j4 + (r&1);
                int hw = m0 + mf*16 + g + ((r>>1)*8);
                so[oc*68 + hw] = acc[mf][nf][r] + bias_s[128+oc];
            }
            __syncthreads();
            for (int f=t; f<1024; f+=128){
                int oc = f>>4, hg = (f&15)*4;
                *(uint2*)&g_fd_h[(size_t)(b*CI+oc)*HW_ + q0 + hg] = make_uint2(
                    packh2(so[oc*68+hg  ], so[oc*68+hg+1]),
                    packh2(so[oc*68+hg+2], so[oc*68+hg+3]));
            }
        }
    }
}

// ================= K2_tc: tensor gram =====================================
// grid (GCH, B_), 256 thr (8 warps = 4 c-groups x 2 d-halves). K=256/CTA.
// Gram[c,d] = sum_n fcb[c,n] fcb[d,n]; 3-product split fp16 (~fp32).
__global__ __launch_bounds__(256, 2) void k2_tc()
{
    extern __shared__ char sm[];
    // 4 subtiles x (A_h 9216 + A_l 9216) halfs*2B = 73728 B
    const int b = blockIdx.y, n0 = blockIdx.x*(HW_/GCH), t = threadIdx.x;
    const int w = t>>5, lane = t&31;
    const int mh = w&3, nh = w>>2;
    const int g = lane>>2, j4 = lane&3;

    // stage all 4 subtiles (each [64c][64n] hi+lo)
#pragma unroll
    for (int i=0;i<16;i++){
        int idx = t + i*256;                     // 4096 ops
        int st = idx>>10, pl = (idx>>9)&1, r = (idx>>3)&63, j = idx&7;
        const __half* src = (pl ? g_cb_l : g_cb_h)
                            + (size_t)(b*CI + r)*HW_ + n0 + st*64 + j*8;
        CP_ASYNC16(smem_u32((__half*)sm + (st*2+pl)*4608 + r*PITCH + j*8), src);
    }
    CP_COMMIT(); CP_WAIT(0);
    __syncthreads();

    float acc[4][4];
#pragma unroll
    for (int i=0;i<4;i++)
#pragma unroll
        for (int j=0;j<4;j++) acc[i][j]=0.f;

#pragma unroll
    for (int st=0; st<4; st++){
        const __half* AH = (const __half*)sm + (st*2+0)*4608;
        const __half* AL = (const __half*)sm + (st*2+1)*4608;
#pragma unroll
        for (int ks=0; ks<4; ks++){
            int col = ks*16 + 2*j4;
            int r0 = mh*16 + g;
            uint32_t ah[4], al[4];
            ah[0] = *(const uint32_t*)&AH[(r0  )*PITCH + col];
            ah[1] = *(const uint32_t*)&AH[(r0+8)*PITCH + col];
            ah[2] = *(const uint32_t*)&AH[(r0  )*PITCH + col+8];
            ah[3] = *(const uint32_t*)&AH[(r0+8)*PITCH + col+8];
            al[0] = *(const uint32_t*)&AL[(r0  )*PITCH + col];
            al[1] = *(const uint32_t*)&AL[(r0+8)*PITCH + col];
            al[2] = *(const uint32_t*)&AL[(r0  )*PITCH + col+8];
            al[3] = *(const uint32_t*)&AL[(r0+8)*PITCH + col+8];
#pragma unroll
            for (int nf=0; nf<4; nf++){
                int dr = nh*32 + nf*8 + g;
                uint32_t bh0 = *(const uint32_t*)&AH[dr*PITCH + col];
                uint32_t bh1 = *(const uint32_t*)&AH[dr*PITCH + col+8];
                uint32_t bl0 = *(const uint32_t*)&AL[dr*PITCH + col];
                uint32_t bl1 = *(const uint32_t*)&AL[dr*PITCH + col+8];
                mma16816(acc[nf], ah, bh0, bh1);
                mma16816(acc[nf], al, bh0, bh1);
                mma16816(acc[nf], ah, bl0, bl1);
            }
        }
    }
#pragma unroll
    for (int nf=0; nf<4; nf++)
#pragma unroll
    for (int r=0; r<4; r++){
        int c = mh*16 + g + ((r>>1)*8);
        int d = nh*32 + nf*8 + 2*j4 + (r&1);
        g_gpart[((size_t)((b*CI + c)*CI) + d)*GCH + blockIdx.x] = acc[nf][r];
    }
}

// ================= K3: channel softmax ====================================
__global__ void k3_csoft()
{
    __shared__ float sg[64];
    const int b = blockIdx.y, c = blockIdx.x, d = threadIdx.x;
    size_t base = ((size_t)((b*CI + c)*CI) + d)*GCH;
    float s = 0.f;
#pragma unroll
    for (int ch=0; ch<GCH; ch++) s += g_gpart[base+ch];
    sg[d] = s; __syncthreads();
    for (int o=32; o; o>>=1){ if (d<o) sg[d] = fminf(sg[d], sg[d+o]); __syncthreads(); }
    float mn = sg[0]; __syncthreads();
    float e = __expf(mn - s);
    sg[d] = e; __syncthreads();
    for (int o=32; o; o>>=1){ if (d<o) sg[d] += sg[d+o]; __syncthreads(); }
    g_attnc[(b*CI + c)*CI + d] = e * (1.f/sg[0]);
}

// ================= K4: flash attention (64q CTAs, 128thr, 2/SM) ===========
__device__ __forceinline__ void stage_tile(__half* dst, int kt, int b, int t){
    const int k0g = kt*64;
#pragma unroll
    for (int i=0;i<8;i++){
        int idx = t + i*128;
        int tl = idx>>9, r = (idx>>3)&63, j = idx&7;
        const __half* src = (tl==0)
            ? g_fcT_h + ((size_t)b*HW_ + k0g + r)*64 + j*8
            : g_fd_h  + ((size_t)(b*CI) + r)*HW_ + k0g + j*8;
        CP_ASYNC16(smem_u32(dst + tl*64*PITCH + r*PITCH + j*8), src);
    }
}

__global__ __launch_bounds__(128, 2) void k4_mma(const float* __restrict__ alpha)
{
    extern __shared__ char sm[];
    __half* fbH = (__half*)(sm + K4_FB);
    __half* stg = (__half*)(sm + K4_STG);
    float* rs_sm = (float*)(sm + K4_RS);
    float* Opart = (float*)(sm + K4_STG);

    const int b = blockIdx.y, q0 = blockIdx.x*64, t = threadIdx.x;
    const int w = t>>5, lane = t&31;
    const int qg = w>>1, kg = w&1;
    const int g = lane>>2, j4 = lane&3;

#pragma unroll
    for (int i=0;i<4;i++){
        int idx = t + i*128;
        int r = idx>>3, j = idx&7;
        *(uint4*)(fbH + r*PITCH + j*8) =
            *(const uint4*)(g_fbT_h + ((size_t)b*HW_ + q0 + r)*64 + j*8);
    }
    stage_tile(stg,           0, b, t); CP_COMMIT();
    stage_tile(stg + TILE_SZ, 1, b, t); CP_COMMIT();
    __syncthreads();

    uint32_t Ah[2][4][4];
#pragma unroll
    for (int mt=0; mt<2; mt++)
#pragma unroll
    for (int ct=0; ct<4; ct++){
        int q = qg*32 + mt*16;
        int cb = ct*16 + 2*j4;
        Ah[mt][ct][0] = *(const uint32_t*)&fbH[(q+g  )*PITCH + cb];
        Ah[mt][ct][1] = *(const uint32_t*)&fbH[(q+g+8)*PITCH + cb];
        Ah[mt][ct][2] = *(const uint32_t*)&fbH[(q+g  )*PITCH + cb + 8];
        Ah[mt][ct][3] = *(const uint32_t*)&fbH[(q+g+8)*PITCH + cb + 8];
    }

    float O[2][8][4];
#pragma unroll
    for (int mt=0;mt<2;mt++)
#pragma unroll
        for (int dt=0;dt<8;dt++)
#pragma unroll
            for (int r=0;r<4;r++) O[mt][dt][r]=0.f;
    float rsum[2][2] = {{0.f,0.f},{0.f,0.f}};

    for (int kt=0; kt<64; kt++){
        if (kt == 63) { CP_WAIT(0); } else { CP_WAIT(1); }
        __syncthreads();
        if (kt + 2 < 64){
            stage_tile(stg + (size_t)((kt+2)%3)*TILE_SZ, kt+2, b, t);
            CP_COMMIT();
        }
        const __half* buf = stg + (size_t)(kt%3)*TILE_SZ;
        const __half* fcH = buf;
        const __half* fdH = buf + 64*PITCH;

        float S[2][4][4];
#pragma unroll
        for (int mt=0;mt<2;mt++)
#pragma unroll
            for (int nt=0;nt<4;nt++)
#pragma unroll
                for (int r=0;r<4;r++) S[mt][nt][r]=0.f;
#pragma unroll
        for (int ct=0; ct<4; ct++){
            int cb = ct*16 + 2*j4;
#pragma unroll
            for (int nt=0; nt<4; nt++){
                int ka = kg*32 + nt*8 + g;
                uint32_t bh0 = *(const uint32_t*)&fcH[ka*PITCH + cb];
                uint32_t bh1 = *(const uint32_t*)&fcH[ka*PITCH + cb + 8];
#pragma unroll
                for (int mt=0; mt<2; mt++)
                    mma16816(S[mt][nt], Ah[mt][ct], bh0, bh1);
            }
        }

        uint32_t Ph[2][2][4];
#pragma unroll
        for (int mt=0; mt<2; mt++)
#pragma unroll
        for (int nt=0; nt<4; nt++){
            float e0 = __expf(S[mt][nt][0] - SHIFT);
            float e1 = __expf(S[mt][nt][1] - SHIFT);
            float e2 = __expf(S[mt][nt][2] - SHIFT);
            float e3 = __expf(S[mt][nt][3] - SHIFT);
            rsum[mt][0] += e0+e1;
            rsum[mt][1] += e2+e3;
            int k2 = nt>>1, hf = (nt&1)*2;
            Ph[mt][k2][hf+0] = packh2(e0, e1);
            Ph[mt][k2][hf+1] = packh2(e2, e3);
        }

#pragma unroll
        for (int dt=0; dt<8; dt++){
            int d = dt*8 + g;
#pragma unroll
            for (int k2=0; k2<2; k2++){
                int kb = kg*32 + k2*16 + 2*j4;
                uint32_t bh0 = *(const uint32_t*)&fdH[d*PITCH + kb];
                uint32_t bh1 = *(const uint32_t*)&fdH[d*PITCH + kb + 8];
#pragma unroll
                for (int mt=0; mt<2; mt++)
                    mma16816(O[mt][dt], Ph[mt][k2], bh0, bh1);
            }
        }
    }

#pragma unroll
    for (int mt=0; mt<2; mt++)
#pragma unroll
    for (int rr=0; rr<2; rr++){
        float v = rsum[mt][rr];
        v += __shfl_xor_sync(0xffffffffu, v, 1);
        v += __shfl_xor_sync(0xffffffffu, v, 2);
        if (j4 == 0) rs_sm[kg*64 + qg*32 + mt*16 + rr*8 + g] = v;
    }
    __syncthreads();
    if (kg == 1){
#pragma unroll
        for (int mt=0; mt<2; mt++)
#pragma unroll
        for (int dt=0; dt<8; dt++){
            int q = qg*32 + mt*16, d = dt*8 + 2*j4;
            Opart[(q+g  )*65 + d  ] = O[mt][dt][0];
            Opart[(q+g  )*65 + d+1] = O[mt][dt][1];
            Opart[(q+g+8)*65 + d  ] = O[mt][dt][2];
            Opart[(q+g+8)*65 + d+1] = O[mt][dt][3];
        }
    }
    __syncthreads();
    const float a0 = alpha[0];
    if (kg == 0){
#pragma unroll
        for (int mt=0; mt<2; mt++){
            int q = qg*32 + mt*16;
            float i0 = a0 / (rs_sm[q+g  ] + rs_sm[64+q+g  ]);
            float i1 = a0 / (rs_sm[q+g+8] + rs_sm[64+q+g+8]);
#pragma unroll
            for (int dt=0; dt<8; dt++){
                int d = dt*8 + 2*j4;
                Opart[(q+g  )*65+d  ] = (O[mt][dt][0] + Opart[(q+g  )*65+d  ]) * i0;
                Opart[(q+g  )*65+d+1] = (O[mt][dt][1] + Opart[(q+g  )*65+d+1]) * i0;
                Opart[(q+g+8)*65+d  ] = (O[mt][dt][2] + Opart[(q+g+8)*65+d  ]) * i1;
                Opart[(q+g+8)*65+d+1] = (O[mt][dt][3] + Opart[(q+g+8)*65+d+1]) * i1;
            }
        }
    }
    __syncthreads();
#pragma unroll
    for (int i=0; i<8; i++){
        int idx = t + i*128;
        int d = idx>>4, q4 = idx&15;
        size_t base = (size_t)(b*CI+d)*HW_ + q0 + q4*4;
        float4 f = *(const float4*)&g_fp[base];
        *(float4*)&g_featp[base] = make_float4(
            Opart[(q4*4+0)*65+d] + f.x, Opart[(q4*4+1)*65+d] + f.y,
            Opart[(q4*4+2)*65+d] + f.z, Opart[(q4*4+3)*65+d] + f.w);
    }
}

// ================= K5: fusion -> fp16 hi/lo planes ========================
__global__ __launch_bounds__(256) void k5_fuse(const float* __restrict__ beta)
{
    extern __shared__ float sm5[];
    float* at  = sm5;
    float* fat = sm5 + 4096;
    const int b = blockIdx.y, q0 = blockIdx.x*128, t = threadIdx.x;
    const int tq = t & 15, tc = t >> 4;

    for (int f=t; f<1024; f+=256)
        *(float4*)&at[f*4] = *(const float4*)&g_attnc[(size_t)b*CI*CI + f*4];
    for (int f=t; f<2048; f+=256){
        int c = f>>5, qv = (f&31)<<2;
        *(float4*)&fat[c*132+qv] =
            *(const float4*)&g_fcb[(size_t)(b*CI+c)*HW_ + q0 + qv];
    }
    __syncthreads();
    float acc[4][8];
#pragma unroll
    for (int i=0;i<4;i++)
#pragma unroll
        for (int j=0;j<8;j++) acc[i][j]=0.f;
#pragma unroll 4
    for (int d=0; d<CI; d++){
        float4 x0 = *(float4*)&fat[d*132 + tq*8];
        float4 x1 = *(float4*)&fat[d*132 + tq*8 + 4];
        float xv[8] = {x0.x,x0.y,x0.z,x0.w,x1.x,x1.y,x1.z,x1.w};
#pragma unroll
        for (int i=0;i<4;i++){
            float w = at[(tc*4+i)*CI + d];
#pragma unroll
            for (int j=0;j<8;j++) acc[i][j] = fmaf(w, xv[j], acc[i][j]);
        }
    }
    const float b0 = beta[0];
    float r[4][8];
#pragma unroll
    for (int i=0;i<4;i++){
        int c = tc*4+i;
        size_t base = (size_t)(b*CI+c)*HW_ + q0 + tq*8;
        float4 p0 = *(const float4*)&g_featp[base];
        float4 p1 = *(const float4*)&g_featp[base+4];
        float pv[8] = {p0.x,p0.y,p0.z,p0.w,p1.x,p1.y,p1.z,p1.w};
#pragma unroll
        for (int j=0;j<8;j++)
            r[i][j] = pv[j] + fmaf(b0, acc[i][j], fat[c*132+tq*8+j]);
    }
    __syncthreads();
#pragma unroll
    for (int i=0;i<4;i++)
#pragma unroll
        for (int j=0;j<8;j++)
            fat[(tc*4+i)*132 + tq*8+j] = r[i][j];
    __syncthreads();
    for (int f=t; f<1024; f+=256){
        int hw = f&127, c8 = f>>7;
        uint32_t uh[4], ul[4];
#pragma unroll
        for (int i=0;i<4;i++)
            split2(fat[(c8*8+2*i)*132+hw], fat[(c8*8+2*i+1)*132+hw], uh[i], ul[i]);
        size_t base = ((size_t)b*HW_ + q0 + hw)*64 + c8*8;
        *(uint4*)&g_fusT_h[base] = make_uint4(uh[0],uh[1],uh[2],uh[3]);
        *(uint4*)&g_fusT_l[base] = make_uint4(ul[0],ul[1],ul[2],ul[3]);
    }
}

// ================= K6_tc: out conv via tensor cores =======================
__global__ __launch_bounds__(256, 1) void k6_tc(
    const float* __restrict__ go, const float* __restrict__ bo,
    const float* __restrict__ mo, const float* __restrict__ vo,
    float* __restrict__ out)
{
    extern __shared__ char sm[];
    __half* A_h = (__half*)(sm + K6_AH);
    __half* A_l = (__half*)(sm + K6_AL);
    __half* W_h = (__half*)(sm + K6_WH);
    __half* W_l = (__half*)(sm + K6_WL);
    float*  so  = (float*)(sm + K6_SO);
    float* bninv = (float*)(sm + K6_BN);
    float* bnsh  = bninv + 512;

    const int b = blockIdx.y, q0 = blockIdx.x*128, t = threadIdx.x;
    const int w = t>>5, lane = t&31;
    const int mh = w&3, nh = w>>2;
    const int m0 = mh*32;
    const int g = lane>>2, j4 = lane&3;

#pragma unroll
    for (int i=0;i<8;i++){
        int idx = t + i*256;
        int pl = idx>>10, r = (idx>>3)&127, j = idx&7;
        const __half* src = (pl ? g_fusT_l : g_fusT_h) + ((size_t)b*HW_+q0+r)*64 + j*8;
        CP_ASYNC16(smem_u32((pl?A_l:A_h) + r*PITCH + j*8), src);
    }
    CP_COMMIT();
    for (int f=t; f<512; f+=256){
        float inv = go[f]*rsqrtf(vo[f]+EPSN);
        bninv[f] = inv; bnsh[f] = bo[f] - mo[f]*inv;
    }
    CP_WAIT(0);
    __syncthreads();

    for (int co=0; co<4; co++){
#pragma unroll
        for (int i=0;i<8;i++){
            int idx = t + i*256;
            int pl = idx>>10, r = (idx>>3)&127, j = idx&7;
            const __half* src = (pl ? g_wol : g_woh) + (size_t)(co*128+r)*64 + j*8;
            CP_ASYNC16(smem_u32((pl?W_l:W_h) + r*PITCH + j*8), src);
        }
        CP_COMMIT(); CP_WAIT(0);
        __syncthreads();

        float acc[2][8][4];
#pragma unroll
        for (int mf=0;mf<2;mf++)
#pragma unroll
            for (int nf=0;nf<8;nf++)
#pragma unroll
                for (int r=0;r<4;r++) acc[mf][nf][r]=0.f;

#pragma unroll
        for (int ks=0; ks<4; ks++){
            int col = ks*16 + 2*j4;
            uint32_t ah[2][4], al[2][4];
#pragma unroll
            for (int mf=0; mf<2; mf++){
                int r0 = m0 + mf*16 + g;
                ah[mf][0] = *(const uint32_t*)&A_h[(r0  )*PITCH + col];
                ah[mf][1] = *(const uint32_t*)&A_h[(r0+8)*PITCH + col];
                ah[mf][2] = *(const uint32_t*)&A_h[(r0  )*PITCH + col+8];
                ah[mf][3] = *(const uint32_t*)&A_h[(r0+8)*PITCH + col+8];
                al[mf][0] = *(const uint32_t*)&A_l[(r0  )*PITCH + col];
                al[mf][1] = *(const uint32_t*)&A_l[(r0+8)*PITCH + col];
                al[mf][2] = *(const uint32_t*)&A_l[(r0  )*PITCH + col+8];
                al[mf][3] = *(const uint32_t*)&A_l[(r0+8)*PITCH + col+8];
            }
#pragma unroll
            for (int nf=0; nf<8; nf++){
                int ocr = nh*64 + nf*8 + g;
                uint32_t wh0 = *(const uint32_t*)&W_h[ocr*PITCH + col];
                uint32_t wh1 = *(const uint32_t*)&W_h[ocr*PITCH + col+8];
                uint32_t wl0 = *(const uint32_t*)&W_l[ocr*PITCH + col];
                uint32_t wl1 = *(const uint32_t*)&W_l[ocr*PITCH + col+8];
#pragma unroll
                for (int mf=0; mf<2; mf++){
                    mma16816(acc[mf][nf], ah[mf], wh0, wh1);
                    mma16816(acc[mf][nf], al[mf], wh0, wh1);
                    mma16816(acc[mf][nf], ah[mf], wl0, wl1);
                }
            }
        }
#pragma unroll
        for (int mf=0; mf<2; mf++)
#pragma unroll
        for (int nf=0; nf<8; nf++)
#pragma unroll
        for (int r=0; r<4; r++){
            int ocl = nh*64 + nf*8 + 2*j4 + (r&1);
            int hw = m0 + mf*16 + g + ((r>>1)*8);
            so[ocl*132 + hw] = fmaf(acc[mf][nf][r], bninv[co*128+ocl], bnsh[co*128+ocl]);
        }
        __syncthreads();
        for (int f=t; f<4096; f+=256){
            int ocl = f>>5, hg = (f&31)*4;
            *(float4*)&out[(size_t)(b*CIN + co*128 + ocl)*HW_ + q0 + hg] =
                make_float4(so[ocl*132+hg], so[ocl*132+hg+1],
                            so[ocl*132+hg+2], so[ocl*132+hg+3]);
        }
        __syncthreads();
    }
}

// ================= launch ==================================================
extern "C" void kernel_launch(void* const* d_in, const int* in_sizes, int n_in,
                              void* d_out, int out_size)
{
    const float* x   = (const float*)d_in[0];
    const float* wp1 = (const float*)d_in[1];
    const float* gp1 = (const float*)d_in[2];
    const float* bp1 = (const float*)d_in[3];
    const float* mp1 = (const float*)d_in[4];
    const float* vp1 = (const float*)d_in[5];
    const float* wc1 = (const float*)d_in[6];
    const float* gc1 = (const float*)d_in[7];
    const float* bc1 = (const float*)d_in[8];
    const float* mc1 = (const float*)d_in[9];
    const float* vc1 = (const float*)d_in[10];
    const float* wb  = (const float*)d_in[11];
    const float* bb  = (const float*)d_in[12];
    const float* wc2 = (const float*)d_in[13];
    const float* bc2 = (const float*)d_in[14];
    const float* wd  = (const float*)d_in[15];
    const float* bd  = (const float*)d_in[16];
    const float* alpha = (const float*)d_in[17];
    const float* beta  = (const float*)d_in[18];
    const float* wo  = (const float*)d_in[19];
    const float* go  = (const float*)d_in[20];
    const float* bo  = (const float*)d_in[21];
    const float* mo  = (const float*)d_in[22];
    const float* vo  = (const float*)d_in[23];
    float* out = (float*)d_out;

    const int K1_SMEM  = 3*CH_BYTES + 1024;            // 222208
    const int K1B_SMEM = QB_TOTAL;                     // 74752
    const int K2_SMEM  = 73728 + 512;
    const int K4_SMEM  = K4_TOTAL;                     // 65024
    const int K5_SMEM  = (4096 + 64*132)*4;            // 50176
    const int K6_SMEM  = K6_TOTAL;                     // 145408
    cudaFuncSetAttribute(k1_tc,   cudaFuncAttributeMaxDynamicSharedMemorySize, K1_SMEM);
    cudaFuncSetAttribute(k1b_tc,  cudaFuncAttributeMaxDynamicSharedMemorySize, K1B_SMEM);
    cudaFuncSetAttribute(k2_tc,   cudaFuncAttributeMaxDynamicSharedMemorySize, K2_SMEM);
    cudaFuncSetAttribute(k4_mma,  cudaFuncAttributeMaxDynamicSharedMemorySize, K4_SMEM);
    cudaFuncSetAttribute(k5_fuse, cudaFuncAttributeMaxDynamicSharedMemorySize, K5_SMEM);
    cudaFuncSetAttribute(k6_tc,   cudaFuncAttributeMaxDynamicSharedMemorySize, K6_SMEM);

    k0w_planes<<<3, 256>>>(wp1, wc1, wo);
    k0q_planes<<<3, 256>>>(wb, wc2, wd);
    k0x_planes<<<dim3(64, 8, B_), 256>>>(x);
    k1_tc     <<<dim3(32, B_), 256, K1_SMEM>>>(gp1,bp1,mp1,vp1, gc1,bc1,mc1,vc1);
    k1b_tc    <<<dim3(64, B_), 128, K1B_SMEM>>>(bb, bc2, bd);
    k2_tc     <<<dim3(GCH, B_), 256, K2_SMEM>>>();
    k3_csoft  <<<dim3(CI, B_), 64>>>();
    k4_mma    <<<dim3(64, B_), 128, K4_SMEM>>>(alpha);
    k5_fuse   <<<dim3(32, B_), 256, K5_SMEM>>>(beta);
    k6_tc     <<<dim3(32, B_), 256, K6_SMEM>>>(go, bo, mo, vo, out);
}

// round 13
// speedup vs baseline: 1.0132x; 1.0037x over previous
#include <cuda_runtime.h>
#include <cuda_fp16.h>
#include <cstdint>
#include <math_constants.h>

#define B_   4
#define CIN  512
#define CI   64
#define HW_  4096
#define EPSN 1e-5f
#define PITCH 72
#define SHIFT 12.0f
#define TILE_SZ (2*64*PITCH)   // halfs per staged k4 tile (fcH, fdH)

// k1_tc chunk geometry (halfs)
#define CH_XH 0
#define CH_XL 9216
#define CH_W  18432
#define CH_HALFS (18432 + 18432)
#define CH_BYTES (CH_HALFS*2)

// k1b_tc smem (bytes) - 64q version
#define QB_AH 0
#define QB_AL 9216
#define QB_W  18432
#define QB_BIAS (18432 + 55296)     // 73728
#define QB_TOTAL (QB_BIAS + 1024)   // 74752

// k6_tc smem (bytes)
#define K6_AH 0
#define K6_AL 18432
#define K6_WH 36864
#define K6_WL (36864 + 18432)
#define K6_SO 73728
#define K6_BN (73728 + 67584)
#define K6_TOTAL (K6_BN + 4096)     // 145408

// k4 smem (bytes) - 64q version
#define K4_FB 0
#define K4_STG 9216
#define K4_RS (9216 + 3*TILE_SZ*2)  // 64512
#define K4_TOTAL (K4_RS + 512)      // 65024

#define GCH 16   // gram k-chunks

// ---------------- scratch (device globals; no allocation) ----------------
__device__ float g_fp    [B_*CI*HW_];
__device__ float g_fcb   [B_*CI*HW_];
__device__ float g_featp [B_*CI*HW_];
__device__ float g_gpart [B_*CI*CI*GCH];
__device__ float g_attnc [B_*CI*CI];
__device__ __align__(16) __half g_xT_h [B_*HW_*CIN];
__device__ __align__(16) __half g_xT_l [B_*HW_*CIN];
__device__ __align__(16) __half g_wh   [2][CI*CIN];
__device__ __align__(16) __half g_wl   [2][CI*CIN];
__device__ __align__(16) __half g_woh  [CIN*CI];
__device__ __align__(16) __half g_wol  [CIN*CI];
__device__ __align__(16) __half g_qwh  [3][CI*CI];   // wb, wc2, wd
__device__ __align__(16) __half g_qwl  [3][CI*CI];
__device__ __align__(16) __half g_fpT_h[B_*HW_*CI];
__device__ __align__(16) __half g_fpT_l[B_*HW_*CI];
__device__ __align__(16) __half g_cb_h [B_*CI*HW_];  // fcb [c][hw] planes
__device__ __align__(16) __half g_cb_l [B_*CI*HW_];
__device__ __align__(16) __half g_fusT_h[B_*HW_*CI];
__device__ __align__(16) __half g_fusT_l[B_*HW_*CI];
__device__ __align__(16) __half g_fbT_h[B_*HW_*CI];
__device__ __align__(16) __half g_fcT_h[B_*HW_*CI];
__device__ __align__(16) __half g_fd_h [B_*CI*HW_];

// ---------------- helpers ----------------
__device__ __forceinline__ uint32_t smem_u32(const void* p){
    uint32_t a;
    asm("{ .reg .u64 t; cvta.to.shared.u64 t, %1; cvt.u32.u64 %0, t; }" : "=r"(a) : "l"(p));
    return a;
}
#define CP_ASYNC16(dst, src) asm volatile("cp.async.cg.shared.global [%0], [%1], 16;" :: "r"(dst), "l"(src))
#define CP_COMMIT()          asm volatile("cp.async.commit_group;")
#define CP_WAIT(n)           asm volatile("cp.async.wait_group %0;" :: "n"(n))

__device__ __forceinline__ void mma16816(float c[4], const uint32_t a[4],
                                         uint32_t b0, uint32_t b1){
    asm volatile("mma.sync.aligned.m16n8k16.row.col.f32.f16.f16.f32 "
        "{%0,%1,%2,%3}, {%4,%5,%6,%7}, {%8,%9}, {%0,%1,%2,%3};"
        : "+f"(c[0]), "+f"(c[1]), "+f"(c[2]), "+f"(c[3])
        : "r"(a[0]), "r"(a[1]), "r"(a[2]), "r"(a[3]), "r"(b0), "r"(b1));
}
__device__ __forceinline__ uint32_t packh2(float a, float b){
    __half2 v = __floats2half2_rn(a, b);
    return *(uint32_t*)&v;
}
__device__ __forceinline__ void split2(float v0, float v1, uint32_t& h, uint32_t& l){
    __half2 h2 = __floats2half2_rn(v0, v1);
    __half2 l2 = __floats2half2_rn(v0 - __half2float(h2.x), v1 - __half2float(h2.y));
    h = *(uint32_t*)&h2; l = *(uint32_t*)&l2;
}

// ================= K0w: big weights ========================================
__global__ void k0w_planes(const float* __restrict__ wp1,
                           const float* __restrict__ wc1,
                           const float* __restrict__ wo)
{
    const int which = blockIdx.x;
    const float* w = (which==0) ? wp1 : (which==1) ? wc1 : wo;
    __half* dh = (which==0) ? g_wh[0] : (which==1) ? g_wh[1] : g_woh;
    __half* dl = (which==0) ? g_wl[0] : (which==1) ? g_wl[1] : g_wol;
    for (int f = threadIdx.x; f < CI*CIN/4; f += 256){
        float4 v = *(const float4*)&w[f*4];
        uint32_t h0,l0,h1,l1;
        split2(v.x, v.y, h0, l0);
        split2(v.z, v.w, h1, l1);
        *(uint2*)&dh[f*4] = make_uint2(h0, h1);
        *(uint2*)&dl[f*4] = make_uint2(l0, l1);
    }
}

// ================= K0q: QKV weights ========================================
__global__ void k0q_planes(const float* __restrict__ wb,
                           const float* __restrict__ wc2,
                           const float* __restrict__ wd)
{
    const int cv = blockIdx.x;
    const float* w = (cv==0) ? wb : (cv==1) ? wc2 : wd;
    for (int f = threadIdx.x; f < CI*CI/4; f += 256){
        float4 v = *(const float4*)&w[f*4];
        uint32_t h0,l0,h1,l1;
        split2(v.x, v.y, h0, l0);
        split2(v.z, v.w, h1, l1);
        *(uint2*)&g_qwh[cv][f*4] = make_uint2(h0, h1);
        *(uint2*)&g_qwl[cv][f*4] = make_uint2(l0, l1);
    }
}

// ================= K0x =====================================================
__global__ __launch_bounds__(256) void k0x_planes(const float* __restrict__ x)
{
    __shared__ float ts[64*68];
    const int hw0 = blockIdx.x*64, c0 = blockIdx.y*64, b = blockIdx.z;
    const int t = threadIdx.x;
    for (int f=t; f<1024; f+=256){
        int cc = f>>4, qv = (f&15)<<2;
        *(float4*)&ts[cc*68+qv] =
            *(const float4*)&x[(size_t)(b*CIN + c0+cc)*HW_ + hw0 + qv];
    }
    __syncthreads();
    for (int f=t; f<512; f+=256){
        int hw = f>>3, j8 = f&7;
        uint32_t uh[4], ul[4];
#pragma unroll
        for (int i=0;i<4;i++)
            split2(ts[(j8*8+2*i)*68 + hw], ts[(j8*8+2*i+1)*68 + hw], uh[i], ul[i]);
        size_t base = ((size_t)b*HW_ + hw0 + hw)*CIN + c0 + j8*8;
        *(uint4*)&g_xT_h[base] = make_uint4(uh[0],uh[1],uh[2],uh[3]);
        *(uint4*)&g_xT_l[base] = make_uint4(ul[0],ul[1],ul[2],ul[3]);
    }
}

// ================= K1_tc ===================================================
__device__ __forceinline__ void k1_stage(char* smbase, int buf, int chunk,
                                         int b, int q0, int t){
    __half* base = (__half*)(smbase + (size_t)buf*CH_BYTES);
#pragma unroll
    for (int i=0;i<8;i++){
        int idx = t + i*256;
        int pl = idx>>10, r = (idx>>3)&127, j = idx&7;
        const __half* src = (pl ? g_xT_l : g_xT_h)
                            + ((size_t)b*HW_ + q0 + r)*CIN + chunk*64 + j*8;
        CP_ASYNC16(smem_u32(base + (pl?CH_XL:CH_XH) + r*PITCH + j*8), src);
    }
#pragma unroll
    for (int i=0;i<8;i++){
        int idx = t + i*256;
        int conv = idx>>10, pl = (idx>>9)&1, oc = (idx>>3)&63, j = idx&7;
        const __half* src = (pl ? g_wl[conv] : g_wh[conv]) + oc*CIN + chunk*64 + j*8;
        CP_ASYNC16(smem_u32(base + CH_W + (conv*2+pl)*4608 + oc*PITCH + j*8), src);
    }
}

__global__ __launch_bounds__(256, 1) void k1_tc(
    const float* __restrict__ gp1, const float* __restrict__ bp1,
    const float* __restrict__ mp1, const float* __restrict__ vp1,
    const float* __restrict__ gc1, const float* __restrict__ bc1,
    const float* __restrict__ mc1, const float* __restrict__ vc1)
{
    extern __shared__ char sm[];
    float* binv = (float*)(sm + 3*CH_BYTES);
    float* bsh  = binv + 128;

    const int b = blockIdx.y, q0 = blockIdx.x*128, t = threadIdx.x;
    const int w = t>>5, lane = t&31;
    const int mh = w&3, nh = w>>2;
    const int m0 = mh*32;
    const int g = lane>>2, j4 = lane&3;

    if (t < 64){
        binv[t] = gp1[t]*rsqrtf(vp1[t]+EPSN);
        bsh [t] = bp1[t] - mp1[t]*binv[t];
    } else if (t < 128){
        int o = t-64;
        binv[64+o] = gc1[o]*rsqrtf(vc1[o]+EPSN);
        bsh [64+o] = bc1[o] - mc1[o]*binv[64+o];
    }

    k1_stage(sm, 0, 0, b, q0, t); CP_COMMIT();
    k1_stage(sm, 1, 1, b, q0, t); CP_COMMIT();

    float acc[2][8][4];
#pragma unroll
    for (int mf=0;mf<2;mf++)
#pragma unroll
        for (int nf=0;nf<8;nf++)
#pragma unroll
            for (int r=0;r<4;r++) acc[mf][nf][r]=0.f;

    for (int c=0; c<8; c++){
        if (c == 7) { CP_WAIT(0); } else { CP_WAIT(1); }
        __syncthreads();
        if (c + 2 < 8){ k1_stage(sm, (c+2)%3, c+2, b, q0, t); CP_COMMIT(); }
        __half* base = (__half*)(sm + (size_t)(c%3)*CH_BYTES);
        const __half* wbH = base + CH_W + (nh*2+0)*4608;
        const __half* wbL = base + CH_W + (nh*2+1)*4608;

#pragma unroll
        for (int ks=0; ks<4; ks++){
            int col = ks*16 + 2*j4;
            uint32_t ah[2][4], al[2][4];
#pragma unroll
            for (int mf=0; mf<2; mf++){
                int r0 = m0 + mf*16 + g;
                ah[mf][0] = *(const uint32_t*)&base[CH_XH + (r0  )*PITCH + col];
                ah[mf][1] = *(const uint32_t*)&base[CH_XH + (r0+8)*PITCH + col];
                ah[mf][2] = *(const uint32_t*)&base[CH_XH + (r0  )*PITCH + col+8];
                ah[mf][3] = *(const uint32_t*)&base[CH_XH + (r0+8)*PITCH + col+8];
                al[mf][0] = *(const uint32_t*)&base[CH_XL + (r0  )*PITCH + col];
                al[mf][1] = *(const uint32_t*)&base[CH_XL + (r0+8)*PITCH + col];
                al[mf][2] = *(const uint32_t*)&base[CH_XL + (r0  )*PITCH + col+8];
                al[mf][3] = *(const uint32_t*)&base[CH_XL + (r0+8)*PITCH + col+8];
            }
#pragma unroll
            for (int nf=0; nf<8; nf++){
                int ocr = nf*8 + g;
                uint32_t wh0 = *(const uint32_t*)&wbH[ocr*PITCH + col];
                uint32_t wh1 = *(const uint32_t*)&wbH[ocr*PITCH + col+8];
                uint32_t wl0 = *(const uint32_t*)&wbL[ocr*PITCH + col];
                uint32_t wl1 = *(const uint32_t*)&wbL[ocr*PITCH + col+8];
#pragma unroll
                for (int mf=0; mf<2; mf++){
                    mma16816(acc[mf][nf], ah[mf], wh0, wh1);
                    mma16816(acc[mf][nf], al[mf], wh0, wh1);
                    mma16816(acc[mf][nf], ah[mf], wl0, wl1);
                }
            }
        }
    }
    __syncthreads();

    float* so = (float*)(sm + (size_t)nh*36864);
#pragma unroll
    for (int mf=0; mf<2; mf++)
#pragma unroll
    for (int nf=0; nf<8; nf++)
#pragma unroll
    for (int r=0; r<4; r++){
        int oc = nf*8 + 2*j4 + (r&1);
        int hw = m0 + mf*16 + g + ((r>>1)*8);
        so[oc*132 + hw] = fmaf(acc[mf][nf][r], binv[nh*64+oc], bsh[nh*64+oc]);
    }
    __syncthreads();
    for (int f=t; f<4096; f+=256){
        int conv = f>>11, oc = (f>>5)&63, hg = (f&31)*4;
        const float* s = (const float*)(sm + (size_t)conv*36864);
        float4 v = make_float4(s[oc*132+hg], s[oc*132+hg+1],
                               s[oc*132+hg+2], s[oc*132+hg+3]);
        float* dst = conv ? g_fcb : g_fp;
        *(float4*)&dst[(size_t)(b*CI+oc)*HW_ + q0 + hg] = v;
    }
    {   // fpT planes (transposed) from conv0
        const float* s0 = (const float*)sm;
        for (int f=t; f<1024; f+=256){
            int hw = f&127, c8 = f>>7;
            uint32_t uh[4], ul[4];
#pragma unroll
            for (int i=0;i<4;i++)
                split2(s0[(c8*8+2*i)*132+hw], s0[(c8*8+2*i+1)*132+hw], uh[i], ul[i]);
            size_t base = ((size_t)b*HW_ + q0 + hw)*64 + c8*8;
            *(uint4*)&g_fpT_h[base] = make_uint4(uh[0],uh[1],uh[2],uh[3]);
            *(uint4*)&g_fpT_l[base] = make_uint4(ul[0],ul[1],ul[2],ul[3]);
        }
    }
    {   // fcb planes ([c][hw]) from conv1, for tensor gram
        const float* s1 = (const float*)(sm + 36864);
        for (int f=t; f<2048; f+=256){
            int oc = f>>5, hg = (f&31)*4;
            uint32_t h0,l0,h1,l1;
            split2(s1[oc*132+hg  ], s1[oc*132+hg+1], h0, l0);
            split2(s1[oc*132+hg+2], s1[oc*132+hg+3], h1, l1);
            size_t off = (size_t)(b*CI+oc)*HW_ + q0 + hg;
            *(uint2*)&g_cb_h[off] = make_uint2(h0, h1);
            *(uint2*)&g_cb_l[off] = make_uint2(l0, l1);
        }
    }
}

// ================= K1b_tc: QKV via tensor cores (64q, 128thr, 2/SM) =======
__global__ __launch_bounds__(128, 2) void k1b_tc(
    const float* __restrict__ bbv, const float* __restrict__ bc2,
    const float* __restrict__ bd)
{
    extern __shared__ char sm[];
    __half* A_h = (__half*)(sm + QB_AH);
    __half* A_l = (__half*)(sm + QB_AL);
    float* bias_s = (float*)(sm + QB_BIAS);

    const int b = blockIdx.y, q0 = blockIdx.x*64, t = threadIdx.x;
    const int w = t>>5, lane = t&31;
    const int mh = w&1, nh = w>>1;
    const int m0 = mh*32;
    const int g = lane>>2, j4 = lane&3;

#pragma unroll
    for (int i=0;i<8;i++){
        int idx = t + i*128;
        int pl = idx>>9, r = (idx>>3)&63, j = idx&7;
        const __half* src = (pl ? g_fpT_l : g_fpT_h) + ((size_t)b*HW_+q0+r)*64 + j*8;
        CP_ASYNC16(smem_u32((pl?A_l:A_h) + r*PITCH + j*8), src);
    }
#pragma unroll
    for (int i=0;i<24;i++){
        int idx = t + i*128;
        int reg = idx>>9, r = (idx>>3)&63, j = idx&7;
        int cv = reg>>1, pl = reg&1;
        const __half* src = (pl ? g_qwl[cv] : g_qwh[cv]) + r*64 + j*8;
        CP_ASYNC16(smem_u32((__half*)(sm + QB_W) + reg*4608 + r*PITCH + j*8), src);
    }
    CP_COMMIT();
    if (t < 64){ bias_s[t]=bbv[t]; bias_s[64+t]=bc2[t]; bias_s[128+t]=bd[t]; }
    CP_WAIT(0);
    __syncthreads();

    for (int cv=0; cv<3; cv++){
        const __half* WH = (const __half*)(sm + QB_W) + (cv*2+0)*4608;
        const __half* WL = (const __half*)(sm + QB_W) + (cv*2+1)*4608;
        float acc[2][4][4];
#pragma unroll
        for (int mf=0;mf<2;mf++)
#pragma unroll
            for (int nf=0;nf<4;nf++)
#pragma unroll
                for (int r=0;r<4;r++) acc[mf][nf][r]=0.f;

#pragma unroll
        for (int ks=0; ks<4; ks++){
            int col = ks*16 + 2*j4;
            uint32_t ah[2][4], al[2][4];
#pragma unroll
            for (int mf=0; mf<2; mf++){
                int r0 = m0 + mf*16 + g;
                ah[mf][0] = *(const uint32_t*)&A_h[(r0  )*PITCH + col];
                ah[mf][1] = *(const uint32_t*)&A_h[(r0+8)*PITCH + col];
                ah[mf][2] = *(const uint32_t*)&A_h[(r0  )*PITCH + col+8];
                ah[mf][3] = *(const uint32_t*)&A_h[(r0+8)*PITCH + col+8];
                al[mf][0] = *(const uint32_t*)&A_l[(r0  )*PITCH + col];
                al[mf][1] = *(const uint32_t*)&A_l[(r0+8)*PITCH + col];
                al[mf][2] = *(const uint32_t*)&A_l[(r0  )*PITCH + col+8];
                al[mf][3] = *(const uint32_t*)&A_l[(r0+8)*PITCH + col+8];
            }
#pragma unroll
            for (int nf=0; nf<4; nf++){
                int ocr = nh*32 + nf*8 + g;
                uint32_t wh0 = *(const uint32_t*)&WH[ocr*PITCH + col];
                uint32_t wh1 = *(const uint32_t*)&WH[ocr*PITCH + col+8];
                uint32_t wl0 = *(const uint32_t*)&WL[ocr*PITCH + col];
                uint32_t wl1 = *(const uint32_t*)&WL[ocr*PITCH + col+8];
#pragma unroll
                for (int mf=0; mf<2; mf++){
                    mma16816(acc[mf][nf], ah[mf], wh0, wh1);
                    mma16816(acc[mf][nf], al[mf], wh0, wh1);
                    mma16816(acc[mf][nf], ah[mf], wl0, wl1);
                }
            }
        }

        if (cv < 2){
            __half* dst = (cv==0) ? g_fbT_h : g_fcT_h;
#pragma unroll
            for (int mf=0; mf<2; mf++)
#pragma unroll
            for (int nf=0; nf<4; nf++){
                int oc = nh*32 + nf*8 + 2*j4;
                float b0v = bias_s[cv*64+oc], b1v = bias_s[cv*64+oc+1];
                int r0 = m0 + mf*16 + g;
                *(uint32_t*)&dst[((size_t)b*HW_+q0+r0  )*64 + oc] =
                    packh2(acc[mf][nf][0]+b0v, acc[mf][nf][1]+b1v);
                *(uint32_t*)&dst[((size_t)b*HW_+q0+r0+8)*64 + oc] =
                    packh2(acc[mf][nf][2]+b0v, acc[mf][nf][3]+b1v);
            }
        } else {
            __syncthreads();
            float* so = (float*)sm;    // [64 oc][68]
#pragma unroll
            for (int mf=0; mf<2; mf++)
#pragma unroll
            for (int nf=0; nf<4; nf++)
#pragma unroll
            for (int r=0; r<4; r++){
                int oc = nh*32 + nf*8 + 2*j4 + (r&1);
                int hw = m0 + mf*16 + g + ((r>>1)*8);
                so[oc*68 + hw] = acc[mf][nf][r] + bias_s[128+oc];
            }
            __syncthreads();
            for (int f=t; f<1024; f+=128){
                int oc = f>>4, hg = (f&15)*4;
                *(uint2*)&g_fd_h[(size_t)(b*CI+oc)*HW_ + q0 + hg] = make_uint2(
                    packh2(so[oc*68+hg  ], so[oc*68+hg+1]),
                    packh2(so[oc*68+hg+2], so[oc*68+hg+3]));
            }
        }
    }
}

// ================= K2_tc: tensor gram =====================================
__global__ __launch_bounds__(256, 2) void k2_tc()
{
    extern __shared__ char sm[];
    const int b = blockIdx.y, n0 = blockIdx.x*(HW_/GCH), t = threadIdx.x;
    const int w = t>>5, lane = t&31;
    const int mh = w&3, nh = w>>2;
    const int g = lane>>2, j4 = lane&3;

#pragma unroll
    for (int i=0;i<16;i++){
        int idx = t + i*256;
        int st = idx>>10, pl = (idx>>9)&1, r = (idx>>3)&63, j = idx&7;
        const __half* src = (pl ? g_cb_l : g_cb_h)
                            + (size_t)(b*CI + r)*HW_ + n0 + st*64 + j*8;
        CP_ASYNC16(smem_u32((__half*)sm + (st*2+pl)*4608 + r*PITCH + j*8), src);
    }
    CP_COMMIT(); CP_WAIT(0);
    __syncthreads();

    float acc[4][4];
#pragma unroll
    for (int i=0;i<4;i++)
#pragma unroll
        for (int j=0;j<4;j++) acc[i][j]=0.f;

#pragma unroll
    for (int st=0; st<4; st++){
        const __half* AH = (const __half*)sm + (st*2+0)*4608;
        const __half* AL = (const __half*)sm + (st*2+1)*4608;
#pragma unroll
        for (int ks=0; ks<4; ks++){
            int col = ks*16 + 2*j4;
            int r0 = mh*16 + g;
            uint32_t ah[4], al[4];
            ah[0] = *(const uint32_t*)&AH[(r0  )*PITCH + col];
            ah[1] = *(const uint32_t*)&AH[(r0+8)*PITCH + col];
            ah[2] = *(const uint32_t*)&AH[(r0  )*PITCH + col+8];
            ah[3] = *(const uint32_t*)&AH[(r0+8)*PITCH + col+8];
            al[0] = *(const uint32_t*)&AL[(r0  )*PITCH + col];
            al[1] = *(const uint32_t*)&AL[(r0+8)*PITCH + col];
            al[2] = *(const uint32_t*)&AL[(r0  )*PITCH + col+8];
            al[3] = *(const uint32_t*)&AL[(r0+8)*PITCH + col+8];
#pragma unroll
            for (int nf=0; nf<4; nf++){
                int dr = nh*32 + nf*8 + g;
                uint32_t bh0 = *(const uint32_t*)&AH[dr*PITCH + col];
                uint32_t bh1 = *(const uint32_t*)&AH[dr*PITCH + col+8];
                uint32_t bl0 = *(const uint32_t*)&AL[dr*PITCH + col];
                uint32_t bl1 = *(const uint32_t*)&AL[dr*PITCH + col+8];
                mma16816(acc[nf], ah, bh0, bh1);
                mma16816(acc[nf], al, bh0, bh1);
                mma16816(acc[nf], ah, bl0, bl1);
            }
        }
    }
#pragma unroll
    for (int nf=0; nf<4; nf++)
#pragma unroll
    for (int r=0; r<4; r++){
        int c = mh*16 + g + ((r>>1)*8);
        int d = nh*32 + nf*8 + 2*j4 + (r&1);
        g_gpart[((size_t)((b*CI + c)*CI) + d)*GCH + blockIdx.x] = acc[nf][r];
    }
}

// ================= K3: channel softmax ====================================
__global__ void k3_csoft()
{
    __shared__ float sg[64];
    const int b = blockIdx.y, c = blockIdx.x, d = threadIdx.x;
    size_t base = ((size_t)((b*CI + c)*CI) + d)*GCH;
    float s = 0.f;
#pragma unroll
    for (int ch=0; ch<GCH; ch++) s += g_gpart[base+ch];
    sg[d] = s; __syncthreads();
    for (int o=32; o; o>>=1){ if (d<o) sg[d] = fminf(sg[d], sg[d+o]); __syncthreads(); }
    float mn = sg[0]; __syncthreads();
    float e = __expf(mn - s);
    sg[d] = e; __syncthreads();
    for (int o=32; o; o>>=1){ if (d<o) sg[d] += sg[d+o]; __syncthreads(); }
    g_attnc[(b*CI + c)*CI + d] = e * (1.f/sg[0]);
}

// ================= K4: flash attention, S-pipelined across k-tiles ========
__device__ __forceinline__ void stage_tile(__half* dst, int kt, int b, int t){
    const int k0g = kt*64;
#pragma unroll
    for (int i=0;i<8;i++){
        int idx = t + i*128;
        int tl = idx>>9, r = (idx>>3)&63, j = idx&7;
        const __half* src = (tl==0)
            ? g_fcT_h + ((size_t)b*HW_ + k0g + r)*64 + j*8
            : g_fd_h  + ((size_t)(b*CI) + r)*HW_ + k0g + j*8;
        CP_ASYNC16(smem_u32(dst + tl*64*PITCH + r*PITCH + j*8), src);
    }
}

__global__ __launch_bounds__(128, 2) void k4_mma(const float* __restrict__ alpha)
{
    extern __shared__ char sm[];
    __half* fbH = (__half*)(sm + K4_FB);
    __half* stg = (__half*)(sm + K4_STG);
    float* rs_sm = (float*)(sm + K4_RS);
    float* Opart = (float*)(sm + K4_STG);

    const int b = blockIdx.y, q0 = blockIdx.x*64, t = threadIdx.x;
    const int w = t>>5, lane = t&31;
    const int qg = w>>1, kg = w&1;
    const int g = lane>>2, j4 = lane&3;

#pragma unroll
    for (int i=0;i<4;i++){
        int idx = t + i*128;
        int r = idx>>3, j = idx&7;
        *(uint4*)(fbH + r*PITCH + j*8) =
            *(const uint4*)(g_fbT_h + ((size_t)b*HW_ + q0 + r)*64 + j*8);
    }
    stage_tile(stg,           0, b, t); CP_COMMIT();
    stage_tile(stg + TILE_SZ, 1, b, t); CP_COMMIT();
    CP_WAIT(1);
    __syncthreads();   // tile 0 staged; fbH visible

    uint32_t Ah[2][4][4];
#pragma unroll
    for (int mt=0; mt<2; mt++)
#pragma unroll
    for (int ct=0; ct<4; ct++){
        int q = qg*32 + mt*16;
        int cb = ct*16 + 2*j4;
        Ah[mt][ct][0] = *(const uint32_t*)&fbH[(q+g  )*PITCH + cb];
        Ah[mt][ct][1] = *(const uint32_t*)&fbH[(q+g+8)*PITCH + cb];
        Ah[mt][ct][2] = *(const uint32_t*)&fbH[(q+g  )*PITCH + cb + 8];
        Ah[mt][ct][3] = *(const uint32_t*)&fbH[(q+g+8)*PITCH + cb + 8];
    }

    float O[2][8][4];
#pragma unroll
    for (int mt=0;mt<2;mt++)
#pragma unroll
        for (int dt=0;dt<8;dt++)
#pragma unroll
            for (int r=0;r<4;r++) O[mt][dt][r]=0.f;
    float rsum[2][2] = {{0.f,0.f},{0.f,0.f}};

    // ---- prologue: S(0) ----
    float Scur[2][4][4], Snext[2][4][4];
#pragma unroll
    for (int mt=0;mt<2;mt++)
#pragma unroll
        for (int nt=0;nt<4;nt++)
#pragma unroll
            for (int r=0;r<4;r++) Scur[mt][nt][r]=0.f;
    {
        const __half* fcH = stg;   // buf 0
#pragma unroll
        for (int ct=0; ct<4; ct++){
            int cb = ct*16 + 2*j4;
#pragma unroll
            for (int nt=0; nt<4; nt++){
                int ka = kg*32 + nt*8 + g;
                uint32_t bh0 = *(const uint32_t*)&fcH[ka*PITCH + cb];
                uint32_t bh1 = *(const uint32_t*)&fcH[ka*PITCH + cb + 8];
#pragma unroll
                for (int mt=0; mt<2; mt++)
                    mma16816(Scur[mt][nt], Ah[mt][ct], bh0, bh1);
            }
        }
    }

    for (int kt=0; kt<64; kt++){
        CP_WAIT(0);        // tiles up to kt+1 fully staged
        __syncthreads();   // all warps past PV(kt-1) -> buf[(kt+2)%3] free
        if (kt + 2 < 64){
            stage_tile(stg + (size_t)((kt+2)%3)*TILE_SZ, kt+2, b, t);
            CP_COMMIT();
        }
        // ---- issue MMA1 for S(kt+1) first: keeps the tensor pipe fed ----
        if (kt < 63){
            const __half* fcN = stg + (size_t)((kt+1)%3)*TILE_SZ;
#pragma unroll
            for (int mt=0;mt<2;mt++)
#pragma unroll
                for (int nt=0;nt<4;nt++)
#pragma unroll
                    for (int r=0;r<4;r++) Snext[mt][nt][r]=0.f;
#pragma unroll
            for (int ct=0; ct<4; ct++){
                int cb = ct*16 + 2*j4;
#pragma unroll
                for (int nt=0; nt<4; nt++){
                    int ka = kg*32 + nt*8 + g;
                    uint32_t bh0 = *(const uint32_t*)&fcN[ka*PITCH + cb];
                    uint32_t bh1 = *(const uint32_t*)&fcN[ka*PITCH + cb + 8];
#pragma unroll
                    for (int mt=0; mt<2; mt++)
                        mma16816(Snext[mt][nt], Ah[mt][ct], bh0, bh1);
                }
            }
        }
        // ---- epilogue on S(kt): drained long ago; MUFU overlaps MMAs ----
        uint32_t Ph[2][2][4];
#pragma unroll
        for (int mt=0; mt<2; mt++)
#pragma unroll
        for (int nt=0; nt<4; nt++){
            float e0 = __expf(Scur[mt][nt][0] - SHIFT);
            float e1 = __expf(Scur[mt][nt][1] - SHIFT);
            float e2 = __expf(Scur[mt][nt][2] - SHIFT);
            float e3 = __expf(Scur[mt][nt][3] - SHIFT);
            rsum[mt][0] += e0+e1;
            rsum[mt][1] += e2+e3;
            int k2 = nt>>1, hf = (nt&1)*2;
            Ph[mt][k2][hf+0] = packh2(e0, e1);
            Ph[mt][k2][hf+1] = packh2(e2, e3);
        }
        // ---- PV(kt) ----
        {
            const __half* fdH = stg + (size_t)(kt%3)*TILE_SZ + 64*PITCH;
#pragma unroll
            for (int dt=0; dt<8; dt++){
                int d = dt*8 + g;
#pragma unroll
                for (int k2=0; k2<2; k2++){
                    int kb = kg*32 + k2*16 + 2*j4;
                    uint32_t bh0 = *(const uint32_t*)&fdH[d*PITCH + kb];
                    uint32_t bh1 = *(const uint32_t*)&fdH[d*PITCH + kb + 8];
#pragma unroll
                    for (int mt=0; mt<2; mt++)
                        mma16816(O[mt][dt], Ph[mt][k2], bh0, bh1);
                }
            }
        }
        // ---- rotate S banks ----
#pragma unroll
        for (int mt=0;mt<2;mt++)
#pragma unroll
            for (int nt=0;nt<4;nt++)
#pragma unroll
                for (int r=0;r<4;r++) Scur[mt][nt][r] = Snext[mt][nt][r];
    }

#pragma unroll
    for (int mt=0; mt<2; mt++)
#pragma unroll
    for (int rr=0; rr<2; rr++){
        float v = rsum[mt][rr];
        v += __shfl_xor_sync(0xffffffffu, v, 1);
        v += __shfl_xor_sync(0xffffffffu, v, 2);
        if (j4 == 0) rs_sm[kg*64 + qg*32 + mt*16 + rr*8 + g] = v;
    }
    __syncthreads();
    if (kg == 1){
#pragma unroll
        for (int mt=0; mt<2; mt++)
#pragma unroll
        for (int dt=0; dt<8; dt++){
            int q = qg*32 + mt*16, d = dt*8 + 2*j4;
            Opart[(q+g  )*65 + d  ] = O[mt][dt][0];
            Opart[(q+g  )*65 + d+1] = O[mt][dt][1];
            Opart[(q+g+8)*65 + d  ] = O[mt][dt][2];
            Opart[(q+g+8)*65 + d+1] = O[mt][dt][3];
        }
    }
    __syncthreads();
    const float a0 = alpha[0];
    if (kg == 0){
#pragma unroll
        for (int mt=0; mt<2; mt++){
            int q = qg*32 + mt*16;
            float i0 = a0 / (rs_sm[q+g  ] + rs_sm[64+q+g  ]);
            float i1 = a0 / (rs_sm[q+g+8] + rs_sm[64+q+g+8]);
#pragma unroll
            for (int dt=0; dt<8; dt++){
                int d = dt*8 + 2*j4;
                Opart[(q+g  )*65+d  ] = (O[mt][dt][0] + Opart[(q+g  )*65+d  ]) * i0;
                Opart[(q+g  )*65+d+1] = (O[mt][dt][1] + Opart[(q+g  )*65+d+1]) * i0;
                Opart[(q+g+8)*65+d  ] = (O[mt][dt][2] + Opart[(q+g+8)*65+d  ]) * i1;
                Opart[(q+g+8)*65+d+1] = (O[mt][dt][3] + Opart[(q+g+8)*65+d+1]) * i1;
            }
        }
    }
    __syncthreads();
#pragma unroll
    for (int i=0; i<8; i++){
        int idx = t + i*128;
        int d = idx>>4, q4 = idx&15;
        size_t base = (size_t)(b*CI+d)*HW_ + q0 + q4*4;
        float4 f = *(const float4*)&g_fp[base];
        *(float4*)&g_featp[base] = make_float4(
            Opart[(q4*4+0)*65+d] + f.x, Opart[(q4*4+1)*65+d] + f.y,
            Opart[(q4*4+2)*65+d] + f.z, Opart[(q4*4+3)*65+d] + f.w);
    }
}

// ================= K5: fusion -> fp16 hi/lo planes ========================
__global__ __launch_bounds__(256) void k5_fuse(const float* __restrict__ beta)
{
    extern __shared__ float sm5[];
    float* at  = sm5;
    float* fat = sm5 + 4096;
    const int b = blockIdx.y, q0 = blockIdx.x*128, t = threadIdx.x;
    const int tq = t & 15, tc = t >> 4;

    for (int f=t; f<1024; f+=256)
        *(float4*)&at[f*4] = *(const float4*)&g_attnc[(size_t)b*CI*CI + f*4];
    for (int f=t; f<2048; f+=256){
        int c = f>>5, qv = (f&31)<<2;
        *(float4*)&fat[c*132+qv] =
            *(const float4*)&g_fcb[(size_t)(b*CI+c)*HW_ + q0 + qv];
    }
    __syncthreads();
    float acc[4][8];
#pragma unroll
    for (int i=0;i<4;i++)
#pragma unroll
        for (int j=0;j<8;j++) acc[i][j]=0.f;
#pragma unroll 4
    for (int d=0; d<CI; d++){
        float4 x0 = *(float4*)&fat[d*132 + tq*8];
        float4 x1 = *(float4*)&fat[d*132 + tq*8 + 4];
        float xv[8] = {x0.x,x0.y,x0.z,x0.w,x1.x,x1.y,x1.z,x1.w};
#pragma unroll
        for (int i=0;i<4;i++){
            float w = at[(tc*4+i)*CI + d];
#pragma unroll
            for (int j=0;j<8;j++) acc[i][j] = fmaf(w, xv[j], acc[i][j]);
        }
    }
    const float b0 = beta[0];
    float r[4][8];
#pragma unroll
    for (int i=0;i<4;i++){
        int c = tc*4+i;
        size_t base = (size_t)(b*CI+c)*HW_ + q0 + tq*8;
        float4 p0 = *(const float4*)&g_featp[base];
        float4 p1 = *(const float4*)&g_featp[base+4];
        float pv[8] = {p0.x,p0.y,p0.z,p0.w,p1.x,p1.y,p1.z,p1.w};
#pragma unroll
        for (int j=0;j<8;j++)
            r[i][j] = pv[j] + fmaf(b0, acc[i][j], fat[c*132+tq*8+j]);
    }
    __syncthreads();
#pragma unroll
    for (int i=0;i<4;i++)
#pragma unroll
        for (int j=0;j<8;j++)
            fat[(tc*4+i)*132 + tq*8+j] = r[i][j];
    __syncthreads();
    for (int f=t; f<1024; f+=256){
        int hw = f&127, c8 = f>>7;
        uint32_t uh[4], ul[4];
#pragma unroll
        for (int i=0;i<4;i++)
            split2(fat[(c8*8+2*i)*132+hw], fat[(c8*8+2*i+1)*132+hw], uh[i], ul[i]);
        size_t base = ((size_t)b*HW_ + q0 + hw)*64 + c8*8;
        *(uint4*)&g_fusT_h[base] = make_uint4(uh[0],uh[1],uh[2],uh[3]);
        *(uint4*)&g_fusT_l[base] = make_uint4(ul[0],ul[1],ul[2],ul[3]);
    }
}

// ================= K6_tc: out conv via tensor cores =======================
__global__ __launch_bounds__(256, 1) void k6_tc(
    const float* __restrict__ go, const float* __restrict__ bo,
    const float* __restrict__ mo, const float* __restrict__ vo,
    float* __restrict__ out)
{
    extern __shared__ char sm[];
    __half* A_h = (__half*)(sm + K6_AH);
    __half* A_l = (__half*)(sm + K6_AL);
    __half* W_h = (__half*)(sm + K6_WH);
    __half* W_l = (__half*)(sm + K6_WL);
    float*  so  = (float*)(sm + K6_SO);
    float* bninv = (float*)(sm + K6_BN);
    float* bnsh  = bninv + 512;

    const int b = blockIdx.y, q0 = blockIdx.x*128, t = threadIdx.x;
    const int w = t>>5, lane = t&31;
    const int mh = w&3, nh = w>>2;
    const int m0 = mh*32;
    const int g = lane>>2, j4 = lane&3;

#pragma unroll
    for (int i=0;i<8;i++){
        int idx = t + i*256;
        int pl = idx>>10, r = (idx>>3)&127, j = idx&7;
        const __half* src = (pl ? g_fusT_l : g_fusT_h) + ((size_t)b*HW_+q0+r)*64 + j*8;
        CP_ASYNC16(smem_u32((pl?A_l:A_h) + r*PITCH + j*8), src);
    }
    CP_COMMIT();
    for (int f=t; f<512; f+=256){
        float inv = go[f]*rsqrtf(vo[f]+EPSN);
        bninv[f] = inv; bnsh[f] = bo[f] - mo[f]*inv;
    }
    CP_WAIT(0);
    __syncthreads();

    for (int co=0; co<4; co++){
#pragma unroll
        for (int i=0;i<8;i++){
            int idx = t + i*256;
            int pl = idx>>10, r = (idx>>3)&127, j = idx&7;
            const __half* src = (pl ? g_wol : g_woh) + (size_t)(co*128+r)*64 + j*8;
            CP_ASYNC16(smem_u32((pl?W_l:W_h) + r*PITCH + j*8), src);
        }
        CP_COMMIT(); CP_WAIT(0);
        __syncthreads();

        float acc[2][8][4];
#pragma unroll
        for (int mf=0;mf<2;mf++)
#pragma unroll
            for (int nf=0;nf<8;nf++)
#pragma unroll
                for (int r=0;r<4;r++) acc[mf][nf][r]=0.f;

#pragma unroll
        for (int ks=0; ks<4; ks++){
            int col = ks*16 + 2*j4;
            uint32_t ah[2][4], al[2][4];
#pragma unroll
            for (int mf=0; mf<2; mf++){
                int r0 = m0 + mf*16 + g;
                ah[mf][0] = *(const uint32_t*)&A_h[(r0  )*PITCH + col];
                ah[mf][1] = *(const uint32_t*)&A_h[(r0+8)*PITCH + col];
                ah[mf][2] = *(const uint32_t*)&A_h[(r0  )*PITCH + col+8];
                ah[mf][3] = *(const uint32_t*)&A_h[(r0+8)*PITCH + col+8];
                al[mf][0] = *(const uint32_t*)&A_l[(r0  )*PITCH + col];
                al[mf][1] = *(const uint32_t*)&A_l[(r0+8)*PITCH + col];
                al[mf][2] = *(const uint32_t*)&A_l[(r0  )*PITCH + col+8];
                al[mf][3] = *(const uint32_t*)&A_l[(r0+8)*PITCH + col+8];
            }
#pragma unroll
            for (int nf=0; nf<8; nf++){
                int ocr = nh*64 + nf*8 + g;
                uint32_t wh0 = *(const uint32_t*)&W_h[ocr*PITCH + col];
                uint32_t wh1 = *(const uint32_t*)&W_h[ocr*PITCH + col+8];
                uint32_t wl0 = *(const uint32_t*)&W_l[ocr*PITCH + col];
                uint32_t wl1 = *(const uint32_t*)&W_l[ocr*PITCH + col+8];
#pragma unroll
                for (int mf=0; mf<2; mf++){
                    mma16816(acc[mf][nf], ah[mf], wh0, wh1);
                    mma16816(acc[mf][nf], al[mf], wh0, wh1);
                    mma16816(acc[mf][nf], ah[mf], wl0, wl1);
                }
            }
        }
#pragma unroll
        for (int mf=0; mf<2; mf++)
#pragma unroll
        for (int nf=0; nf<8; nf++)
#pragma unroll
        for (int r=0; r<4; r++){
            int ocl = nh*64 + nf*8 + 2*j4 + (r&1);
            int hw = m0 + mf*16 + g + ((r>>1)*8);
            so[ocl*132 + hw] = fmaf(acc[mf][nf][r], bninv[co*128+ocl], bnsh[co*128+ocl]);
        }
        __syncthreads();
        for (int f=t; f<4096; f+=256){
            int ocl = f>>5, hg = (f&31)*4;
            *(float4*)&out[(size_t)(b*CIN + co*128 + ocl)*HW_ + q0 + hg] =
                make_float4(so[ocl*132+hg], so[ocl*132+hg+1],
                            so[ocl*132+hg+2], so[ocl*132+hg+3]);
        }
        __syncthreads();
    }
}

// ================= launch ==================================================
extern "C" void kernel_launch(void* const* d_in, const int* in_sizes, int n_in,
                              void* d_out, int out_size)
{
    const float* x   = (const float*)d_in[0];
    const float* wp1 = (const float*)d_in[1];
    const float* gp1 = (const float*)d_in[2];
    const float* bp1 = (const float*)d_in[3];
    const float* mp1 = (const float*)d_in[4];
    const float* vp1 = (const float*)d_in[5];
    const float* wc1 = (const float*)d_in[6];
    const float* gc1 = (const float*)d_in[7];
    const float* bc1 = (const float*)d_in[8];
    const float* mc1 = (const float*)d_in[9];
    const float* vc1 = (const float*)d_in[10];
    const float* wb  = (const float*)d_in[11];
    const float* bb  = (const float*)d_in[12];
    const float* wc2 = (const float*)d_in[13];
    const float* bc2 = (const float*)d_in[14];
    const float* wd  = (const float*)d_in[15];
    const float* bd  = (const float*)d_in[16];
    const float* alpha = (const float*)d_in[17];
    const float* beta  = (const float*)d_in[18];
    const float* wo  = (const float*)d_in[19];
    const float* go  = (const float*)d_in[20];
    const float* bo  = (const float*)d_in[21];
    const float* mo  = (const float*)d_in[22];
    const float* vo  = (const float*)d_in[23];
    float* out = (float*)d_out;

    const int K1_SMEM  = 3*CH_BYTES + 1024;            // 222208
    const int K1B_SMEM = QB_TOTAL;                     // 74752
    const int K2_SMEM  = 73728 + 512;
    const int K4_SMEM  = K4_TOTAL;                     // 65024
    const int K5_SMEM  = (4096 + 64*132)*4;            // 50176
    const int K6_SMEM  = K6_TOTAL;                     // 145408
    cudaFuncSetAttribute(k1_tc,   cudaFuncAttributeMaxDynamicSharedMemorySize, K1_SMEM);
    cudaFuncSetAttribute(k1b_tc,  cudaFuncAttributeMaxDynamicSharedMemorySize, K1B_SMEM);
    cudaFuncSetAttribute(k2_tc,   cudaFuncAttributeMaxDynamicSharedMemorySize, K2_SMEM);
    cudaFuncSetAttribute(k4_mma,  cudaFuncAttributeMaxDynamicSharedMemorySize, K4_SMEM);
    cudaFuncSetAttribute(k5_fuse, cudaFuncAttributeMaxDynamicSharedMemorySize, K5_SMEM);
    cudaFuncSetAttribute(k6_tc,   cudaFuncAttributeMaxDynamicSharedMemorySize, K6_SMEM);

    k0w_planes<<<3, 256>>>(wp1, wc1, wo);
    k0q_planes<<<3, 256>>>(wb, wc2, wd);
    k0x_planes<<<dim3(64, 8, B_), 256>>>(x);
    k1_tc     <<<dim3(32, B_), 256, K1_SMEM>>>(gp1,bp1,mp1,vp1, gc1,bc1,mc1,vc1);
    k1b_tc    <<<dim3(64, B_), 128, K1B_SMEM>>>(bb, bc2, bd);
    k2_tc     <<<dim3(GCH, B_), 256, K2_SMEM>>>();
    k3_csoft  <<<dim3(CI, B_), 64>>>();
    k4_mma    <<<dim3(64, B_), 128, K4_SMEM>>>(alpha);
    k5_fuse   <<<dim3(32, B_), 256, K5_SMEM>>>(beta);
    k6_tc     <<<dim3(32, B_), 256, K6_SMEM>>>(go, bo, mo, vo, out);
}

// round 14
// speedup vs baseline: 1.0420x; 1.0284x over previous
#include <cuda_runtime.h>
#include <cuda_fp16.h>
#include <cstdint>
#include <math_constants.h>

#define B_   4
#define CIN  512
#define CI   64
#define HW_  4096
#define EPSN 1e-5f
#define PITCH 72
#define SHIFT 12.0f
#define TILE_SZ (2*64*PITCH)   // halfs per staged k4 tile (fcH, fdH)

// k1_tc chunk geometry (halfs)
#define CH_XH 0
#define CH_XL 9216
#define CH_W  18432
#define CH_HALFS (18432 + 18432)
#define CH_BYTES (CH_HALFS*2)

// k1b_tc smem (bytes) - 64q version
#define QB_AH 0
#define QB_AL 9216
#define QB_W  18432
#define QB_BIAS (18432 + 55296)     // 73728
#define QB_TOTAL (QB_BIAS + 1024)   // 74752

// k6_tc smem (bytes)
#define K6_AH 0
#define K6_AL 18432
#define K6_WH 36864
#define K6_WL (36864 + 18432)
#define K6_SO 73728
#define K6_BN (73728 + 67584)
#define K6_TOTAL (K6_BN + 4096)     // 145408

// k4 smem (bytes) - 64q version
#define K4_FB 0
#define K4_STG 9216
#define K4_OP  K4_STG                  // Opart [64][65] f32 (reuses stg)
#define K4_ATT (K4_STG + 16640)        // attn_c [64][64] f32
#define K4_FCB (K4_STG + 33024)        // fcb [64][68] f32
#define K4_RS (9216 + 3*TILE_SZ*2)     // 64512
#define K4_TOTAL (K4_RS + 512)         // 65024

#define GCH 16   // gram k-chunks

// ---------------- scratch (device globals; no allocation) ----------------
__device__ float g_fp    [B_*CI*HW_];
__device__ float g_fcb   [B_*CI*HW_];
__device__ float g_gpart [B_*CI*CI*GCH];
__device__ float g_attnc [B_*CI*CI];
__device__ __align__(16) __half g_xT_h [B_*HW_*CIN];
__device__ __align__(16) __half g_xT_l [B_*HW_*CIN];
__device__ __align__(16) __half g_wh   [2][CI*CIN];
__device__ __align__(16) __half g_wl   [2][CI*CIN];
__device__ __align__(16) __half g_woh  [CIN*CI];
__device__ __align__(16) __half g_wol  [CIN*CI];
__device__ __align__(16) __half g_qwh  [3][CI*CI];   // wb, wc2, wd
__device__ __align__(16) __half g_qwl  [3][CI*CI];
__device__ __align__(16) __half g_fpT_h[B_*HW_*CI];
__device__ __align__(16) __half g_fpT_l[B_*HW_*CI];
__device__ __align__(16) __half g_cb_h [B_*CI*HW_];  // fcb [c][hw] planes
__device__ __align__(16) __half g_cb_l [B_*CI*HW_];
__device__ __align__(16) __half g_fusT_h[B_*HW_*CI];
__device__ __align__(16) __half g_fusT_l[B_*HW_*CI];
__device__ __align__(16) __half g_fbT_h[B_*HW_*CI];
__device__ __align__(16) __half g_fcT_h[B_*HW_*CI];
__device__ __align__(16) __half g_fd_h [B_*CI*HW_];

// ---------------- helpers ----------------
__device__ __forceinline__ uint32_t smem_u32(const void* p){
    uint32_t a;
    asm("{ .reg .u64 t; cvta.to.shared.u64 t, %1; cvt.u32.u64 %0, t; }" : "=r"(a) : "l"(p));
    return a;
}
#define CP_ASYNC16(dst, src) asm volatile("cp.async.cg.shared.global [%0], [%1], 16;" :: "r"(dst), "l"(src))
#define CP_COMMIT()          asm volatile("cp.async.commit_group;")
#define CP_WAIT(n)           asm volatile("cp.async.wait_group %0;" :: "n"(n))

__device__ __forceinline__ void mma16816(float c[4], const uint32_t a[4],
                                         uint32_t b0, uint32_t b1){
    asm volatile("mma.sync.aligned.m16n8k16.row.col.f32.f16.f16.f32 "
        "{%0,%1,%2,%3}, {%4,%5,%6,%7}, {%8,%9}, {%0,%1,%2,%3};"
        : "+f"(c[0]), "+f"(c[1]), "+f"(c[2]), "+f"(c[3])
        : "r"(a[0]), "r"(a[1]), "r"(a[2]), "r"(a[3]), "r"(b0), "r"(b1));
}
__device__ __forceinline__ uint32_t packh2(float a, float b){
    __half2 v = __floats2half2_rn(a, b);
    return *(uint32_t*)&v;
}
__device__ __forceinline__ void split2(float v0, float v1, uint32_t& h, uint32_t& l){
    __half2 h2 = __floats2half2_rn(v0, v1);
    __half2 l2 = __floats2half2_rn(v0 - __half2float(h2.x), v1 - __half2float(h2.y));
    h = *(uint32_t*)&h2; l = *(uint32_t*)&l2;
}

// ================= K0w: big weights ========================================
__global__ void k0w_planes(const float* __restrict__ wp1,
                           const float* __restrict__ wc1,
                           const float* __restrict__ wo)
{
    const int which = blockIdx.x;
    const float* w = (which==0) ? wp1 : (which==1) ? wc1 : wo;
    __half* dh = (which==0) ? g_wh[0] : (which==1) ? g_wh[1] : g_woh;
    __half* dl = (which==0) ? g_wl[0] : (which==1) ? g_wl[1] : g_wol;
    for (int f = threadIdx.x; f < CI*CIN/4; f += 256){
        float4 v = *(const float4*)&w[f*4];
        uint32_t h0,l0,h1,l1;
        split2(v.x, v.y, h0, l0);
        split2(v.z, v.w, h1, l1);
        *(uint2*)&dh[f*4] = make_uint2(h0, h1);
        *(uint2*)&dl[f*4] = make_uint2(l0, l1);
    }
}

// ================= K0q: QKV weights ========================================
__global__ void k0q_planes(const float* __restrict__ wb,
                           const float* __restrict__ wc2,
                           const float* __restrict__ wd)
{
    const int cv = blockIdx.x;
    const float* w = (cv==0) ? wb : (cv==1) ? wc2 : wd;
    for (int f = threadIdx.x; f < CI*CI/4; f += 256){
        float4 v = *(const float4*)&w[f*4];
        uint32_t h0,l0,h1,l1;
        split2(v.x, v.y, h0, l0);
        split2(v.z, v.w, h1, l1);
        *(uint2*)&g_qwh[cv][f*4] = make_uint2(h0, h1);
        *(uint2*)&g_qwl[cv][f*4] = make_uint2(l0, l1);
    }
}

// ================= K0x =====================================================
__global__ __launch_bounds__(256) void k0x_planes(const float* __restrict__ x)
{
    __shared__ float ts[64*68];
    const int hw0 = blockIdx.x*64, c0 = blockIdx.y*64, b = blockIdx.z;
    const int t = threadIdx.x;
    for (int f=t; f<1024; f+=256){
        int cc = f>>4, qv = (f&15)<<2;
        *(float4*)&ts[cc*68+qv] =
            *(const float4*)&x[(size_t)(b*CIN + c0+cc)*HW_ + hw0 + qv];
    }
    __syncthreads();
    for (int f=t; f<512; f+=256){
        int hw = f>>3, j8 = f&7;
        uint32_t uh[4], ul[4];
#pragma unroll
        for (int i=0;i<4;i++)
            split2(ts[(j8*8+2*i)*68 + hw], ts[(j8*8+2*i+1)*68 + hw], uh[i], ul[i]);
        size_t base = ((size_t)b*HW_ + hw0 + hw)*CIN + c0 + j8*8;
        *(uint4*)&g_xT_h[base] = make_uint4(uh[0],uh[1],uh[2],uh[3]);
        *(uint4*)&g_xT_l[base] = make_uint4(ul[0],ul[1],ul[2],ul[3]);
    }
}

// ================= K1_tc ===================================================
__device__ __forceinline__ void k1_stage(char* smbase, int buf, int chunk,
                                         int b, int q0, int t){
    __half* base = (__half*)(smbase + (size_t)buf*CH_BYTES);
#pragma unroll
    for (int i=0;i<8;i++){
        int idx = t + i*256;
        int pl = idx>>10, r = (idx>>3)&127, j = idx&7;
        const __half* src = (pl ? g_xT_l : g_xT_h)
                            + ((size_t)b*HW_ + q0 + r)*CIN + chunk*64 + j*8;
        CP_ASYNC16(smem_u32(base + (pl?CH_XL:CH_XH) + r*PITCH + j*8), src);
    }
#pragma unroll
    for (int i=0;i<8;i++){
        int idx = t + i*256;
        int conv = idx>>10, pl = (idx>>9)&1, oc = (idx>>3)&63, j = idx&7;
        const __half* src = (pl ? g_wl[conv] : g_wh[conv]) + oc*CIN + chunk*64 + j*8;
        CP_ASYNC16(smem_u32(base + CH_W + (conv*2+pl)*4608 + oc*PITCH + j*8), src);
    }
}

__global__ __launch_bounds__(256, 1) void k1_tc(
    const float* __restrict__ gp1, const float* __restrict__ bp1,
    const float* __restrict__ mp1, const float* __restrict__ vp1,
    const float* __restrict__ gc1, const float* __restrict__ bc1,
    const float* __restrict__ mc1, const float* __restrict__ vc1)
{
    extern __shared__ char sm[];
    float* binv = (float*)(sm + 3*CH_BYTES);
    float* bsh  = binv + 128;

    const int b = blockIdx.y, q0 = blockIdx.x*128, t = threadIdx.x;
    const int w = t>>5, lane = t&31;
    const int mh = w&3, nh = w>>2;
    const int m0 = mh*32;
    const int g = lane>>2, j4 = lane&3;

    if (t < 64){
        binv[t] = gp1[t]*rsqrtf(vp1[t]+EPSN);
        bsh [t] = bp1[t] - mp1[t]*binv[t];
    } else if (t < 128){
        int o = t-64;
        binv[64+o] = gc1[o]*rsqrtf(vc1[o]+EPSN);
        bsh [64+o] = bc1[o] - mc1[o]*binv[64+o];
    }

    k1_stage(sm, 0, 0, b, q0, t); CP_COMMIT();
    k1_stage(sm, 1, 1, b, q0, t); CP_COMMIT();

    float acc[2][8][4];
#pragma unroll
    for (int mf=0;mf<2;mf++)
#pragma unroll
        for (int nf=0;nf<8;nf++)
#pragma unroll
            for (int r=0;r<4;r++) acc[mf][nf][r]=0.f;

    for (int c=0; c<8; c++){
        if (c == 7) { CP_WAIT(0); } else { CP_WAIT(1); }
        __syncthreads();
        if (c + 2 < 8){ k1_stage(sm, (c+2)%3, c+2, b, q0, t); CP_COMMIT(); }
        __half* base = (__half*)(sm + (size_t)(c%3)*CH_BYTES);
        const __half* wbH = base + CH_W + (nh*2+0)*4608;
        const __half* wbL = base + CH_W + (nh*2+1)*4608;

#pragma unroll
        for (int ks=0; ks<4; ks++){
            int col = ks*16 + 2*j4;
            uint32_t ah[2][4], al[2][4];
#pragma unroll
            for (int mf=0; mf<2; mf++){
                int r0 = m0 + mf*16 + g;
                ah[mf][0] = *(const uint32_t*)&base[CH_XH + (r0  )*PITCH + col];
                ah[mf][1] = *(const uint32_t*)&base[CH_XH + (r0+8)*PITCH + col];
                ah[mf][2] = *(const uint32_t*)&base[CH_XH + (r0  )*PITCH + col+8];
                ah[mf][3] = *(const uint32_t*)&base[CH_XH + (r0+8)*PITCH + col+8];
                al[mf][0] = *(const uint32_t*)&base[CH_XL + (r0  )*PITCH + col];
                al[mf][1] = *(const uint32_t*)&base[CH_XL + (r0+8)*PITCH + col];
                al[mf][2] = *(const uint32_t*)&base[CH_XL + (r0  )*PITCH + col+8];
                al[mf][3] = *(const uint32_t*)&base[CH_XL + (r0+8)*PITCH + col+8];
            }
#pragma unroll
            for (int nf=0; nf<8; nf++){
                int ocr = nf*8 + g;
                uint32_t wh0 = *(const uint32_t*)&wbH[ocr*PITCH + col];
                uint32_t wh1 = *(const uint32_t*)&wbH[ocr*PITCH + col+8];
                uint32_t wl0 = *(const uint32_t*)&wbL[ocr*PITCH + col];
                uint32_t wl1 = *(const uint32_t*)&wbL[ocr*PITCH + col+8];
#pragma unroll
                for (int mf=0; mf<2; mf++){
                    mma16816(acc[mf][nf], ah[mf], wh0, wh1);
                    mma16816(acc[mf][nf], al[mf], wh0, wh1);
                    mma16816(acc[mf][nf], ah[mf], wl0, wl1);
                }
            }
        }
    }
    __syncthreads();

    float* so = (float*)(sm + (size_t)nh*36864);
#pragma unroll
    for (int mf=0; mf<2; mf++)
#pragma unroll
    for (int nf=0; nf<8; nf++)
#pragma unroll
    for (int r=0; r<4; r++){
        int oc = nf*8 + 2*j4 + (r&1);
        int hw = m0 + mf*16 + g + ((r>>1)*8);
        so[oc*132 + hw] = fmaf(acc[mf][nf][r], binv[nh*64+oc], bsh[nh*64+oc]);
    }
    __syncthreads();
    for (int f=t; f<4096; f+=256){
        int conv = f>>11, oc = (f>>5)&63, hg = (f&31)*4;
        const float* s = (const float*)(sm + (size_t)conv*36864);
        float4 v = make_float4(s[oc*132+hg], s[oc*132+hg+1],
                               s[oc*132+hg+2], s[oc*132+hg+3]);
        float* dst = conv ? g_fcb : g_fp;
        *(float4*)&dst[(size_t)(b*CI+oc)*HW_ + q0 + hg] = v;
    }
    {   // fpT planes (transposed) from conv0
        const float* s0 = (const float*)sm;
        for (int f=t; f<1024; f+=256){
            int hw = f&127, c8 = f>>7;
            uint32_t uh[4], ul[4];
#pragma unroll
            for (int i=0;i<4;i++)
                split2(s0[(c8*8+2*i)*132+hw], s0[(c8*8+2*i+1)*132+hw], uh[i], ul[i]);
            size_t base = ((size_t)b*HW_ + q0 + hw)*64 + c8*8;
            *(uint4*)&g_fpT_h[base] = make_uint4(uh[0],uh[1],uh[2],uh[3]);
            *(uint4*)&g_fpT_l[base] = make_uint4(ul[0],ul[1],ul[2],ul[3]);
        }
    }
    {   // fcb planes ([c][hw]) from conv1, for tensor gram
        const float* s1 = (const float*)(sm + 36864);
        for (int f=t; f<2048; f+=256){
            int oc = f>>5, hg = (f&31)*4;
            uint32_t h0,l0,h1,l1;
            split2(s1[oc*132+hg  ], s1[oc*132+hg+1], h0, l0);
            split2(s1[oc*132+hg+2], s1[oc*132+hg+3], h1, l1);
            size_t off = (size_t)(b*CI+oc)*HW_ + q0 + hg;
            *(uint2*)&g_cb_h[off] = make_uint2(h0, h1);
            *(uint2*)&g_cb_l[off] = make_uint2(l0, l1);
        }
    }
}

// ================= K1b_tc: QKV via tensor cores (64q, 128thr, 2/SM) =======
__global__ __launch_bounds__(128, 2) void k1b_tc(
    const float* __restrict__ bbv, const float* __restrict__ bc2,
    const float* __restrict__ bd)
{
    extern __shared__ char sm[];
    __half* A_h = (__half*)(sm + QB_AH);
    __half* A_l = (__half*)(sm + QB_AL);
    float* bias_s = (float*)(sm + QB_BIAS);

    const int b = blockIdx.y, q0 = blockIdx.x*64, t = threadIdx.x;
    const int w = t>>5, lane = t&31;
    const int mh = w&1, nh = w>>1;
    const int m0 = mh*32;
    const int g = lane>>2, j4 = lane&3;

#pragma unroll
    for (int i=0;i<8;i++){
        int idx = t + i*128;
        int pl = idx>>9, r = (idx>>3)&63, j = idx&7;
        const __half* src = (pl ? g_fpT_l : g_fpT_h) + ((size_t)b*HW_+q0+r)*64 + j*8;
        CP_ASYNC16(smem_u32((pl?A_l:A_h) + r*PITCH + j*8), src);
    }
#pragma unroll
    for (int i=0;i<24;i++){
        int idx = t + i*128;
        int reg = idx>>9, r = (idx>>3)&63, j = idx&7;
        int cv = reg>>1, pl = reg&1;
        const __half* src = (pl ? g_qwl[cv] : g_qwh[cv]) + r*64 + j*8;
        CP_ASYNC16(smem_u32((__half*)(sm + QB_W) + reg*4608 + r*PITCH + j*8), src);
    }
    CP_COMMIT();
    if (t < 64){ bias_s[t]=bbv[t]; bias_s[64+t]=bc2[t]; bias_s[128+t]=bd[t]; }
    CP_WAIT(0);
    __syncthreads();

    for (int cv=0; cv<3; cv++){
        const __half* WH = (const __half*)(sm + QB_W) + (cv*2+0)*4608;
        const __half* WL = (const __half*)(sm + QB_W) + (cv*2+1)*4608;
        float acc[2][4][4];
#pragma unroll
        for (int mf=0;mf<2;mf++)
#pragma unroll
            for (int nf=0;nf<4;nf++)
#pragma unroll
                for (int r=0;r<4;r++) acc[mf][nf][r]=0.f;

#pragma unroll
        for (int ks=0; ks<4; ks++){
            int col = ks*16 + 2*j4;
            uint32_t ah[2][4], al[2][4];
#pragma unroll
            for (int mf=0; mf<2; mf++){
                int r0 = m0 + mf*16 + g;
                ah[mf][0] = *(const uint32_t*)&A_h[(r0  )*PITCH + col];
                ah[mf][1] = *(const uint32_t*)&A_h[(r0+8)*PITCH + col];
                ah[mf][2] = *(const uint32_t*)&A_h[(r0  )*PITCH + col+8];
                ah[mf][3] = *(const uint32_t*)&A_h[(r0+8)*PITCH + col+8];
                al[mf][0] = *(const uint32_t*)&A_l[(r0  )*PITCH + col];
                al[mf][1] = *(const uint32_t*)&A_l[(r0+8)*PITCH + col];
                al[mf][2] = *(const uint32_t*)&A_l[(r0  )*PITCH + col+8];
                al[mf][3] = *(const uint32_t*)&A_l[(r0+8)*PITCH + col+8];
            }
#pragma unroll
            for (int nf=0; nf<4; nf++){
                int ocr = nh*32 + nf*8 + g;
                uint32_t wh0 = *(const uint32_t*)&WH[ocr*PITCH + col];
                uint32_t wh1 = *(const uint32_t*)&WH[ocr*PITCH + col+8];
                uint32_t wl0 = *(const uint32_t*)&WL[ocr*PITCH + col];
                uint32_t wl1 = *(const uint32_t*)&WL[ocr*PITCH + col+8];
#pragma unroll
                for (int mf=0; mf<2; mf++){
                    mma16816(acc[mf][nf], ah[mf], wh0, wh1);
                    mma16816(acc[mf][nf], al[mf], wh0, wh1);
                    mma16816(acc[mf][nf], ah[mf], wl0, wl1);
                }
            }
        }

        if (cv < 2){
            __half* dst = (cv==0) ? g_fbT_h : g_fcT_h;
#pragma unroll
            for (int mf=0; mf<2; mf++)
#pragma unroll
            for (int nf=0; nf<4; nf++){
                int oc = nh*32 + nf*8 + 2*j4;
                float b0v = bias_s[cv*64+oc], b1v = bias_s[cv*64+oc+1];
                int r0 = m0 + mf*16 + g;
                *(uint32_t*)&dst[((size_t)b*HW_+q0+r0  )*64 + oc] =
                    packh2(acc[mf][nf][0]+b0v, acc[mf][nf][1]+b1v);
                *(uint32_t*)&dst[((size_t)b*HW_+q0+r0+8)*64 + oc] =
                    packh2(acc[mf][nf][2]+b0v, acc[mf][nf][3]+b1v);
            }
        } else {
            __syncthreads();
            float* so = (float*)sm;    // [64 oc][68]
#pragma unroll
            for (int mf=0; mf<2; mf++)
#pragma unroll
            for (int nf=0; nf<4; nf++)
#pragma unroll
            for (int r=0; r<4; r++){
                int oc = nh*32 + nf*8 + 2*j4 + (r&1);
                int hw = m0 + mf*16 + g + ((r>>1)*8);
                so[oc*68 + hw] = acc[mf][nf][r] + bias_s[128+oc];
            }
            __syncthreads();
            for (int f=t; f<1024; f+=128){
                int oc = f>>4, hg = (f&15)*4;
                *(uint2*)&g_fd_h[(size_t)(b*CI+oc)*HW_ + q0 + hg] = make_uint2(
                    packh2(so[oc*68+hg  ], so[oc*68+hg+1]),
                    packh2(so[oc*68+hg+2], so[oc*68+hg+3]));
            }
        }
    }
}

// ================= K2_tc: tensor gram =====================================
__global__ __launch_bounds__(256, 2) void k2_tc()
{
    extern __shared__ char sm[];
    const int b = blockIdx.y, n0 = blockIdx.x*(HW_/GCH), t = threadIdx.x;
    const int w = t>>5, lane = t&31;
    const int mh = w&3, nh = w>>2;
    const int g = lane>>2, j4 = lane&3;

#pragma unroll
    for (int i=0;i<16;i++){
        int idx = t + i*256;
        int st = idx>>10, pl = (idx>>9)&1, r = (idx>>3)&63, j = idx&7;
        const __half* src = (pl ? g_cb_l : g_cb_h)
                            + (size_t)(b*CI + r)*HW_ + n0 + st*64 + j*8;
        CP_ASYNC16(smem_u32((__half*)sm + (st*2+pl)*4608 + r*PITCH + j*8), src);
    }
    CP_COMMIT(); CP_WAIT(0);
    __syncthreads();

    float acc[4][4];
#pragma unroll
    for (int i=0;i<4;i++)
#pragma unroll
        for (int j=0;j<4;j++) acc[i][j]=0.f;

#pragma unroll
    for (int st=0; st<4; st++){
        const __half* AH = (const __half*)sm + (st*2+0)*4608;
        const __half* AL = (const __half*)sm + (st*2+1)*4608;
#pragma unroll
        for (int ks=0; ks<4; ks++){
            int col = ks*16 + 2*j4;
            int r0 = mh*16 + g;
            uint32_t ah[4], al[4];
            ah[0] = *(const uint32_t*)&AH[(r0  )*PITCH + col];
            ah[1] = *(const uint32_t*)&AH[(r0+8)*PITCH + col];
            ah[2] = *(const uint32_t*)&AH[(r0  )*PITCH + col+8];
            ah[3] = *(const uint32_t*)&AH[(r0+8)*PITCH + col+8];
            al[0] = *(const uint32_t*)&AL[(r0  )*PITCH + col];
            al[1] = *(const uint32_t*)&AL[(r0+8)*PITCH + col];
            al[2] = *(const uint32_t*)&AL[(r0  )*PITCH + col+8];
            al[3] = *(const uint32_t*)&AL[(r0+8)*PITCH + col+8];
#pragma unroll
            for (int nf=0; nf<4; nf++){
                int dr = nh*32 + nf*8 + g;
                uint32_t bh0 = *(const uint32_t*)&AH[dr*PITCH + col];
                uint32_t bh1 = *(const uint32_t*)&AH[dr*PITCH + col+8];
                uint32_t bl0 = *(const uint32_t*)&AL[dr*PITCH + col];
                uint32_t bl1 = *(const uint32_t*)&AL[dr*PITCH + col+8];
                mma16816(acc[nf], ah, bh0, bh1);
                mma16816(acc[nf], al, bh0, bh1);
                mma16816(acc[nf], ah, bl0, bl1);
            }
        }
    }
#pragma unroll
    for (int nf=0; nf<4; nf++)
#pragma unroll
    for (int r=0; r<4; r++){
        int c = mh*16 + g + ((r>>1)*8);
        int d = nh*32 + nf*8 + 2*j4 + (r&1);
        g_gpart[((size_t)((b*CI + c)*CI) + d)*GCH + blockIdx.x] = acc[nf][r];
    }
}

// ================= K3: channel softmax ====================================
__global__ void k3_csoft()
{
    __shared__ float sg[64];
    const int b = blockIdx.y, c = blockIdx.x, d = threadIdx.x;
    size_t base = ((size_t)((b*CI + c)*CI) + d)*GCH;
    float s = 0.f;
#pragma unroll
    for (int ch=0; ch<GCH; ch++) s += g_gpart[base+ch];
    sg[d] = s; __syncthreads();
    for (int o=32; o; o>>=1){ if (d<o) sg[d] = fminf(sg[d], sg[d+o]); __syncthreads(); }
    float mn = sg[0]; __syncthreads();
    float e = __expf(mn - s);
    sg[d] = e; __syncthreads();
    for (int o=32; o; o>>=1){ if (d<o) sg[d] += sg[d+o]; __syncthreads(); }
    g_attnc[(b*CI + c)*CI + d] = e * (1.f/sg[0]);
}

// ================= K4: flash attention + fused channel/fusion epilogue ====
__device__ __forceinline__ void stage_tile(__half* dst, int kt, int b, int t){
    const int k0g = kt*64;
#pragma unroll
    for (int i=0;i<8;i++){
        int idx = t + i*128;
        int tl = idx>>9, r = (idx>>3)&63, j = idx&7;
        const __half* src = (tl==0)
            ? g_fcT_h + ((size_t)b*HW_ + k0g + r)*64 + j*8
            : g_fd_h  + ((size_t)(b*CI) + r)*HW_ + k0g + j*8;
        CP_ASYNC16(smem_u32(dst + tl*64*PITCH + r*PITCH + j*8), src);
    }
}

__global__ __launch_bounds__(128, 2) void k4_mma(const float* __restrict__ alpha,
                                                 const float* __restrict__ beta)
{
    extern __shared__ char sm[];
    __half* fbH = (__half*)(sm + K4_FB);
    __half* stg = (__half*)(sm + K4_STG);
    float* rs_sm = (float*)(sm + K4_RS);

    const int b = blockIdx.y, q0 = blockIdx.x*64, t = threadIdx.x;
    const int w = t>>5, lane = t&31;
    const int qg = w>>1, kg = w&1;
    const int g = lane>>2, j4 = lane&3;

#pragma unroll
    for (int i=0;i<4;i++){
        int idx = t + i*128;
        int r = idx>>3, j = idx&7;
        *(uint4*)(fbH + r*PITCH + j*8) =
            *(const uint4*)(g_fbT_h + ((size_t)b*HW_ + q0 + r)*64 + j*8);
    }
    stage_tile(stg,           0, b, t); CP_COMMIT();
    stage_tile(stg + TILE_SZ, 1, b, t); CP_COMMIT();
    __syncthreads();

    uint32_t Ah[2][4][4];
#pragma unroll
    for (int mt=0; mt<2; mt++)
#pragma unroll
    for (int ct=0; ct<4; ct++){
        int q = qg*32 + mt*16;
        int cb = ct*16 + 2*j4;
        Ah[mt][ct][0] = *(const uint32_t*)&fbH[(q+g  )*PITCH + cb];
        Ah[mt][ct][1] = *(const uint32_t*)&fbH[(q+g+8)*PITCH + cb];
        Ah[mt][ct][2] = *(const uint32_t*)&fbH[(q+g  )*PITCH + cb + 8];
        Ah[mt][ct][3] = *(const uint32_t*)&fbH[(q+g+8)*PITCH + cb + 8];
    }

    float O[2][8][4];
#pragma unroll
    for (int mt=0;mt<2;mt++)
#pragma unroll
        for (int dt=0;dt<8;dt++)
#pragma unroll
            for (int r=0;r<4;r++) O[mt][dt][r]=0.f;
    float rsum[2][2] = {{0.f,0.f},{0.f,0.f}};

    for (int kt=0; kt<64; kt++){
        if (kt == 63) { CP_WAIT(0); } else { CP_WAIT(1); }
        __syncthreads();
        if (kt + 2 < 64){
            stage_tile(stg + (size_t)((kt+2)%3)*TILE_SZ, kt+2, b, t);
            CP_COMMIT();
        }
        const __half* buf = stg + (size_t)(kt%3)*TILE_SZ;
        const __half* fcH = buf;
        const __half* fdH = buf + 64*PITCH;

        float S[2][4][4];
#pragma unroll
        for (int mt=0;mt<2;mt++)
#pragma unroll
            for (int nt=0;nt<4;nt++)
#pragma unroll
                for (int r=0;r<4;r++) S[mt][nt][r]=0.f;
#pragma unroll
        for (int ct=0; ct<4; ct++){
            int cb = ct*16 + 2*j4;
#pragma unroll
            for (int nt=0; nt<4; nt++){
                int ka = kg*32 + nt*8 + g;
                uint32_t bh0 = *(const uint32_t*)&fcH[ka*PITCH + cb];
                uint32_t bh1 = *(const uint32_t*)&fcH[ka*PITCH + cb + 8];
#pragma unroll
                for (int mt=0; mt<2; mt++)
                    mma16816(S[mt][nt], Ah[mt][ct], bh0, bh1);
            }
        }

        uint32_t Ph[2][2][4];
#pragma unroll
        for (int mt=0; mt<2; mt++)
#pragma unroll
        for (int nt=0; nt<4; nt++){
            float e0 = __expf(S[mt][nt][0] - SHIFT);
            float e1 = __expf(S[mt][nt][1] - SHIFT);
            float e2 = __expf(S[mt][nt][2] - SHIFT);
            float e3 = __expf(S[mt][nt][3] - SHIFT);
            rsum[mt][0] += e0+e1;
            rsum[mt][1] += e2+e3;
            int k2 = nt>>1, hf = (nt&1)*2;
            Ph[mt][k2][hf+0] = packh2(e0, e1);
            Ph[mt][k2][hf+1] = packh2(e2, e3);
        }

#pragma unroll
        for (int dt=0; dt<8; dt++){
            int d = dt*8 + g;
#pragma unroll
            for (int k2=0; k2<2; k2++){
                int kb = kg*32 + k2*16 + 2*j4;
                uint32_t bh0 = *(const uint32_t*)&fdH[d*PITCH + kb];
                uint32_t bh1 = *(const uint32_t*)&fdH[d*PITCH + kb + 8];
#pragma unroll
                for (int mt=0; mt<2; mt++)
                    mma16816(O[mt][dt], Ph[mt][k2], bh0, bh1);
            }
        }
    }

    // ---- epilogue: rowsum, O combine, channel GEMM, fusion, fp16 planes ----
#pragma unroll
    for (int mt=0; mt<2; mt++)
#pragma unroll
    for (int rr=0; rr<2; rr++){
        float v = rsum[mt][rr];
        v += __shfl_xor_sync(0xffffffffu, v, 1);
        v += __shfl_xor_sync(0xffffffffu, v, 2);
        if (j4 == 0) rs_sm[kg*64 + qg*32 + mt*16 + rr*8 + g] = v;
    }
    __syncthreads();   // stg region retired by all warps
    float* Opart  = (float*)(sm + K4_OP);    // [64 q][65]
    float* attn_s = (float*)(sm + K4_ATT);   // [64 c][64 d]
    float* fcb_s  = (float*)(sm + K4_FCB);   // [64 c][68]
    if (kg == 1){
#pragma unroll
        for (int mt=0; mt<2; mt++)
#pragma unroll
        for (int dt=0; dt<8; dt++){
            int q = qg*32 + mt*16, d = dt*8 + 2*j4;
            Opart[(q+g  )*65 + d  ] = O[mt][dt][0];
            Opart[(q+g  )*65 + d+1] = O[mt][dt][1];
            Opart[(q+g+8)*65 + d  ] = O[mt][dt][2];
            Opart[(q+g+8)*65 + d+1] = O[mt][dt][3];
        }
    }
    // all threads: load attn_c and the fcb slice
    for (int f=t; f<1024; f+=128){
        int cc = f>>4, dv = (f&15)*4;
        *(float4*)&attn_s[cc*64+dv] =
            *(const float4*)&g_attnc[(size_t)b*CI*CI + cc*64 + dv];
    }
    for (int f=t; f<1024; f+=128){
        int d = f>>4, hv = (f&15)*4;
        *(float4*)&fcb_s[d*68+hv] =
            *(const float4*)&g_fcb[(size_t)(b*CI+d)*HW_ + q0 + hv];
    }
    __syncthreads();
    const float a0 = alpha[0];
    if (kg == 0){
#pragma unroll
        for (int mt=0; mt<2; mt++){
            int q = qg*32 + mt*16;
            float i0 = a0 / (rs_sm[q+g  ] + rs_sm[64+q+g  ]);
            float i1 = a0 / (rs_sm[q+g+8] + rs_sm[64+q+g+8]);
#pragma unroll
            for (int dt=0; dt<8; dt++){
                int d = dt*8 + 2*j4;
                Opart[(q+g  )*65+d  ] = (O[mt][dt][0] + Opart[(q+g  )*65+d  ]) * i0;
                Opart[(q+g  )*65+d+1] = (O[mt][dt][1] + Opart[(q+g  )*65+d+1]) * i0;
                Opart[(q+g+8)*65+d  ] = (O[mt][dt][2] + Opart[(q+g+8)*65+d  ]) * i1;
                Opart[(q+g+8)*65+d+1] = (O[mt][dt][3] + Opart[(q+g+8)*65+d+1]) * i1;
            }
        }
    }
    __syncthreads();
    // channel GEMM + fusion: thread -> c in [tc*8, tc*8+8), hw in [tq*4, tq*4+4)
    {
        const int tq = t & 15, tc = t >> 4;
        const float b0 = beta[0];
        float accf[8][4];
#pragma unroll
        for (int cc=0;cc<8;cc++)
#pragma unroll
            for (int j=0;j<4;j++) accf[cc][j]=0.f;
#pragma unroll 4
        for (int d=0; d<CI; d++){
            float4 fv = *(float4*)&fcb_s[d*68 + tq*4];
#pragma unroll
            for (int cc=0; cc<8; cc++){
                float a = attn_s[(tc*8+cc)*64 + d];
                accf[cc][0] = fmaf(a, fv.x, accf[cc][0]);
                accf[cc][1] = fmaf(a, fv.y, accf[cc][1]);
                accf[cc][2] = fmaf(a, fv.z, accf[cc][2]);
                accf[cc][3] = fmaf(a, fv.w, accf[cc][3]);
            }
        }
        float res[8][4];
#pragma unroll
        for (int cc=0; cc<8; cc++){
            int c = tc*8+cc;
            float4 fpv = *(const float4*)&g_fp[(size_t)(b*CI+c)*HW_ + q0 + tq*4];
            float fpa[4] = {fpv.x, fpv.y, fpv.z, fpv.w};
#pragma unroll
            for (int j=0; j<4; j++){
                int hw = tq*4+j;
                res[cc][j] = Opart[hw*65 + c] + fpa[j]
                           + fmaf(b0, accf[cc][j], fcb_s[c*68+hw]);
            }
        }
        __syncthreads();
        // write fusion back into fcb_s as [c][68]
#pragma unroll
        for (int cc=0; cc<8; cc++)
#pragma unroll
            for (int j=0; j<4; j++)
                fcb_s[(tc*8+cc)*68 + tq*4+j] = res[cc][j];
    }
    __syncthreads();
    // split + transposed store to fusT planes
    for (int f=t; f<512; f+=128){
        int hw = f&63, c8 = f>>6;
        uint32_t uh[4], ul[4];
#pragma unroll
        for (int i=0;i<4;i++)
            split2(fcb_s[(c8*8+2*i)*68+hw], fcb_s[(c8*8+2*i+1)*68+hw], uh[i], ul[i]);
        size_t base = ((size_t)b*HW_ + q0 + hw)*64 + c8*8;
        *(uint4*)&g_fusT_h[base] = make_uint4(uh[0],uh[1],uh[2],uh[3]);
        *(uint4*)&g_fusT_l[base] = make_uint4(ul[0],ul[1],ul[2],ul[3]);
    }
}

// ================= K6_tc: out conv via tensor cores =======================
__global__ __launch_bounds__(256, 1) void k6_tc(
    const float* __restrict__ go, const float* __restrict__ bo,
    const float* __restrict__ mo, const float* __restrict__ vo,
    float* __restrict__ out)
{
    extern __shared__ char sm[];
    __half* A_h = (__half*)(sm + K6_AH);
    __half* A_l = (__half*)(sm + K6_AL);
    __half* W_h = (__half*)(sm + K6_WH);
    __half* W_l = (__half*)(sm + K6_WL);
    float*  so  = (float*)(sm + K6_SO);
    float* bninv = (float*)(sm + K6_BN);
    float* bnsh  = bninv + 512;

    const int b = blockIdx.y, q0 = blockIdx.x*128, t = threadIdx.x;
    const int w = t>>5, lane = t&31;
    const int mh = w&3, nh = w>>2;
    const int m0 = mh*32;
    const int g = lane>>2, j4 = lane&3;

#pragma unroll
    for (int i=0;i<8;i++){
        int idx = t + i*256;
        int pl = idx>>10, r = (idx>>3)&127, j = idx&7;
        const __half* src = (pl ? g_fusT_l : g_fusT_h) + ((size_t)b*HW_+q0+r)*64 + j*8;
        CP_ASYNC16(smem_u32((pl?A_l:A_h) + r*PITCH + j*8), src);
    }
    CP_COMMIT();
    for (int f=t; f<512; f+=256){
        float inv = go[f]*rsqrtf(vo[f]+EPSN);
        bninv[f] = inv; bnsh[f] = bo[f] - mo[f]*inv;
    }
    CP_WAIT(0);
    __syncthreads();

    for (int co=0; co<4; co++){
#pragma unroll
        for (int i=0;i<8;i++){
            int idx = t + i*256;
            int pl = idx>>10, r = (idx>>3)&127, j = idx&7;
            const __half* src = (pl ? g_wol : g_woh) + (size_t)(co*128+r)*64 + j*8;
            CP_ASYNC16(smem_u32((pl?W_l:W_h) + r*PITCH + j*8), src);
        }
        CP_COMMIT(); CP_WAIT(0);
        __syncthreads();

        float acc[2][8][4];
#pragma unroll
        for (int mf=0;mf<2;mf++)
#pragma unroll
            for (int nf=0;nf<8;nf++)
#pragma unroll
                for (int r=0;r<4;r++) acc[mf][nf][r]=0.f;

#pragma unroll
        for (int ks=0; ks<4; ks++){
            int col = ks*16 + 2*j4;
            uint32_t ah[2][4], al[2][4];
#pragma unroll
            for (int mf=0; mf<2; mf++){
                int r0 = m0 + mf*16 + g;
                ah[mf][0] = *(const uint32_t*)&A_h[(r0  )*PITCH + col];
                ah[mf][1] = *(const uint32_t*)&A_h[(r0+8)*PITCH + col];
                ah[mf][2] = *(const uint32_t*)&A_h[(r0  )*PITCH + col+8];
                ah[mf][3] = *(const uint32_t*)&A_h[(r0+8)*PITCH + col+8];
                al[mf][0] = *(const uint32_t*)&A_l[(r0  )*PITCH + col];
                al[mf][1] = *(const uint32_t*)&A_l[(r0+8)*PITCH + col];
                al[mf][2] = *(const uint32_t*)&A_l[(r0  )*PITCH + col+8];
                al[mf][3] = *(const uint32_t*)&A_l[(r0+8)*PITCH + col+8];
            }
#pragma unroll
            for (int nf=0; nf<8; nf++){
                int ocr = nh*64 + nf*8 + g;
                uint32_t wh0 = *(const uint32_t*)&W_h[ocr*PITCH + col];
                uint32_t wh1 = *(const uint32_t*)&W_h[ocr*PITCH + col+8];
                uint32_t wl0 = *(const uint32_t*)&W_l[ocr*PITCH + col];
                uint32_t wl1 = *(const uint32_t*)&W_l[ocr*PITCH + col+8];
#pragma unroll
                for (int mf=0; mf<2; mf++){
                    mma16816(acc[mf][nf], ah[mf], wh0, wh1);
                    mma16816(acc[mf][nf], al[mf], wh0, wh1);
                    mma16816(acc[mf][nf], ah[mf], wl0, wl1);
                }
            }
        }
#pragma unroll
        for (int mf=0; mf<2; mf++)
#pragma unroll
        for (int nf=0; nf<8; nf++)
#pragma unroll
        for (int r=0; r<4; r++){
            int ocl = nh*64 + nf*8 + 2*j4 + (r&1);
            int hw = m0 + mf*16 + g + ((r>>1)*8);
            so[ocl*132 + hw] = fmaf(acc[mf][nf][r], bninv[co*128+ocl], bnsh[co*128+ocl]);
        }
        __syncthreads();
        for (int f=t; f<4096; f+=256){
            int ocl = f>>5, hg = (f&31)*4;
            *(float4*)&out[(size_t)(b*CIN + co*128 + ocl)*HW_ + q0 + hg] =
                make_float4(so[ocl*132+hg], so[ocl*132+hg+1],
                            so[ocl*132+hg+2], so[ocl*132+hg+3]);
        }
        __syncthreads();
    }
}

// ================= launch ==================================================
extern "C" void kernel_launch(void* const* d_in, const int* in_sizes, int n_in,
                              void* d_out, int out_size)
{
    const float* x   = (const float*)d_in[0];
    const float* wp1 = (const float*)d_in[1];
    const float* gp1 = (const float*)d_in[2];
    const float* bp1 = (const float*)d_in[3];
    const float* mp1 = (const float*)d_in[4];
    const float* vp1 = (const float*)d_in[5];
    const float* wc1 = (const float*)d_in[6];
    const float* gc1 = (const float*)d_in[7];
    const float* bc1 = (const float*)d_in[8];
    const float* mc1 = (const float*)d_in[9];
    const float* vc1 = (const float*)d_in[10];
    const float* wb  = (const float*)d_in[11];
    const float* bb  = (const float*)d_in[12];
    const float* wc2 = (const float*)d_in[13];
    const float* bc2 = (const float*)d_in[14];
    const float* wd  = (const float*)d_in[15];
    const float* bd  = (const float*)d_in[16];
    const float* alpha = (const float*)d_in[17];
    const float* beta  = (const float*)d_in[18];
    const float* wo  = (const float*)d_in[19];
    const float* go  = (const float*)d_in[20];
    const float* bo  = (const float*)d_in[21];
    const float* mo  = (const float*)d_in[22];
    const float* vo  = (const float*)d_in[23];
    float* out = (float*)d_out;

    const int K1_SMEM  = 3*CH_BYTES + 1024;            // 222208
    const int K1B_SMEM = QB_TOTAL;                     // 74752
    const int K2_SMEM  = 73728 + 512;
    const int K4_SMEM  = K4_TOTAL;                     // 65024
    const int K6_SMEM  = K6_TOTAL;                     // 145408
    cudaFuncSetAttribute(k1_tc,   cudaFuncAttributeMaxDynamicSharedMemorySize, K1_SMEM);
    cudaFuncSetAttribute(k1b_tc,  cudaFuncAttributeMaxDynamicSharedMemorySize, K1B_SMEM);
    cudaFuncSetAttribute(k2_tc,   cudaFuncAttributeMaxDynamicSharedMemorySize, K2_SMEM);
    cudaFuncSetAttribute(k4_mma,  cudaFuncAttributeMaxDynamicSharedMemorySize, K4_SMEM);
    cudaFuncSetAttribute(k6_tc,   cudaFuncAttributeMaxDynamicSharedMemorySize, K6_SMEM);

    k0w_planes<<<3, 256>>>(wp1, wc1, wo);
    k0q_planes<<<3, 256>>>(wb, wc2, wd);
    k0x_planes<<<dim3(64, 8, B_), 256>>>(x);
    k1_tc     <<<dim3(32, B_), 256, K1_SMEM>>>(gp1,bp1,mp1,vp1, gc1,bc1,mc1,vc1);
    k1b_tc    <<<dim3(64, B_), 128, K1B_SMEM>>>(bb, bc2, bd);
    k2_tc     <<<dim3(GCH, B_), 256, K2_SMEM>>>();
    k3_csoft  <<<dim3(CI, B_), 64>>>();
    k4_mma    <<<dim3(64, B_), 128, K4_SMEM>>>(alpha, beta);
    k6_tc     <<<dim3(32, B_), 256, K6_SMEM>>>(go, bo, mo, vo, out);
}

// round 15
// speedup vs baseline: 1.1945x; 1.1463x over previous
#include <cuda_runtime.h>
#include <cuda_fp16.h>
#include <cstdint>
#include <math_constants.h>

#define B_   4
#define CIN  512
#define CI   64
#define HW_  4096
#define EPSN 1e-5f
#define PITCH 72
#define SHIFT 12.0f
#define TILE_SZ (2*64*PITCH)   // halfs per staged k4 tile (fcH, fdH)

// k1_tc chunk geometry (bytes): raw fp32 x tile + fp16 weights
#define XB_F32 0                 // 64 c x 132 floats = 33792 B
#define XB_W   33792             // 4 regions x 4608 halfs = 36864 B
#define XB_BYTES 70656

// k1b_tc smem (bytes) - 64q version
#define QB_AH 0
#define QB_AL 9216
#define QB_W  18432
#define QB_BIAS (18432 + 55296)     // 73728
#define QB_TOTAL (QB_BIAS + 1024)   // 74752

// k6_tc smem (bytes)
#define K6_AH 0
#define K6_AL 18432
#define K6_WH 36864
#define K6_WL (36864 + 18432)
#define K6_SO 73728
#define K6_BN (73728 + 67584)
#define K6_TOTAL (K6_BN + 4096)     // 145408

// k4 smem (bytes) - 64q version
#define K4_FB 0
#define K4_STG 9216
#define K4_OP  K4_STG                  // Opart [64][65] f32 (reuses stg)
#define K4_ATT (K4_STG + 16640)        // attn_c [64][64] f32
#define K4_FCB (K4_STG + 33024)        // fcb [64][68] f32
#define K4_RS (9216 + 3*TILE_SZ*2)     // 64512
#define K4_TOTAL (K4_RS + 512)         // 65024

#define GCH 16   // gram k-chunks

// ---------------- scratch (device globals; no allocation) ----------------
__device__ float g_fp    [B_*CI*HW_];
__device__ float g_fcb   [B_*CI*HW_];
__device__ float g_gpart [B_*CI*CI*GCH];
__device__ float g_attnc [B_*CI*CI];
__device__ __align__(16) __half g_wh   [2][CI*CIN];
__device__ __align__(16) __half g_wl   [2][CI*CIN];
__device__ __align__(16) __half g_woh  [CIN*CI];
__device__ __align__(16) __half g_wol  [CIN*CI];
__device__ __align__(16) __half g_qwh  [3][CI*CI];   // wb, wc2, wd
__device__ __align__(16) __half g_qwl  [3][CI*CI];
__device__ __align__(16) __half g_fpT_h[B_*HW_*CI];
__device__ __align__(16) __half g_fpT_l[B_*HW_*CI];
__device__ __align__(16) __half g_cb_h [B_*CI*HW_];  // fcb [c][hw] planes
__device__ __align__(16) __half g_cb_l [B_*CI*HW_];
__device__ __align__(16) __half g_fusT_h[B_*HW_*CI];
__device__ __align__(16) __half g_fusT_l[B_*HW_*CI];
__device__ __align__(16) __half g_fbT_h[B_*HW_*CI];
__device__ __align__(16) __half g_fcT_h[B_*HW_*CI];
__device__ __align__(16) __half g_fd_h [B_*CI*HW_];

// ---------------- helpers ----------------
__device__ __forceinline__ uint32_t smem_u32(const void* p){
    uint32_t a;
    asm("{ .reg .u64 t; cvta.to.shared.u64 t, %1; cvt.u32.u64 %0, t; }" : "=r"(a) : "l"(p));
    return a;
}
#define CP_ASYNC16(dst, src) asm volatile("cp.async.cg.shared.global [%0], [%1], 16;" :: "r"(dst), "l"(src))
#define CP_COMMIT()          asm volatile("cp.async.commit_group;")
#define CP_WAIT(n)           asm volatile("cp.async.wait_group %0;" :: "n"(n))

__device__ __forceinline__ void mma16816(float c[4], const uint32_t a[4],
                                         uint32_t b0, uint32_t b1){
    asm volatile("mma.sync.aligned.m16n8k16.row.col.f32.f16.f16.f32 "
        "{%0,%1,%2,%3}, {%4,%5,%6,%7}, {%8,%9}, {%0,%1,%2,%3};"
        : "+f"(c[0]), "+f"(c[1]), "+f"(c[2]), "+f"(c[3])
        : "r"(a[0]), "r"(a[1]), "r"(a[2]), "r"(a[3]), "r"(b0), "r"(b1));
}
__device__ __forceinline__ uint32_t packh2(float a, float b){
    __half2 v = __floats2half2_rn(a, b);
    return *(uint32_t*)&v;
}
__device__ __forceinline__ void split2(float v0, float v1, uint32_t& h, uint32_t& l){
    __half2 h2 = __floats2half2_rn(v0, v1);
    __half2 l2 = __floats2half2_rn(v0 - __half2float(h2.x), v1 - __half2float(h2.y));
    h = *(uint32_t*)&h2; l = *(uint32_t*)&l2;
}

// ================= K0w: all weight planes (6 blocks) ======================
__global__ void k0w_planes(const float* __restrict__ wp1,
                           const float* __restrict__ wc1,
                           const float* __restrict__ wo,
                           const float* __restrict__ wb,
                           const float* __restrict__ wc2,
                           const float* __restrict__ wd)
{
    const int which = blockIdx.x;
    if (which < 3){
        const float* w = (which==0) ? wp1 : (which==1) ? wc1 : wo;
        __half* dh = (which==0) ? g_wh[0] : (which==1) ? g_wh[1] : g_woh;
        __half* dl = (which==0) ? g_wl[0] : (which==1) ? g_wl[1] : g_wol;
        for (int f = threadIdx.x; f < CI*CIN/4; f += 256){
            float4 v = *(const float4*)&w[f*4];
            uint32_t h0,l0,h1,l1;
            split2(v.x, v.y, h0, l0);
            split2(v.z, v.w, h1, l1);
            *(uint2*)&dh[f*4] = make_uint2(h0, h1);
            *(uint2*)&dl[f*4] = make_uint2(l0, l1);
        }
    } else {
        const int cv = which - 3;
        const float* w = (cv==0) ? wb : (cv==1) ? wc2 : wd;
        for (int f = threadIdx.x; f < CI*CI/4; f += 256){
            float4 v = *(const float4*)&w[f*4];
            uint32_t h0,l0,h1,l1;
            split2(v.x, v.y, h0, l0);
            split2(v.z, v.w, h1, l1);
            *(uint2*)&g_qwh[cv][f*4] = make_uint2(h0, h1);
            *(uint2*)&g_qwl[cv][f*4] = make_uint2(l0, l1);
        }
    }
}

// ================= K1_tc: fused split + tensor front conv =================
__device__ __forceinline__ void k1_stage(char* smbase, int buf, int chunk,
                                         const float* __restrict__ x,
                                         int b, int q0, int t){
    char* base = smbase + (size_t)buf*XB_BYTES;
    float* xf = (float*)(base + XB_F32);
#pragma unroll
    for (int i=0;i<8;i++){
        int idx = t + i*256;
        int c = idx>>5, j = idx&31;
        const float* src = x + (size_t)(b*CIN + chunk*64 + c)*HW_ + q0 + j*4;
        CP_ASYNC16(smem_u32(xf + c*132 + j*4), src);
    }
#pragma unroll
    for (int i=0;i<8;i++){
        int idx = t + i*256;
        int conv = idx>>10, pl = (idx>>9)&1, oc = (idx>>3)&63, j = idx&7;
        const __half* src = (pl ? g_wl[conv] : g_wh[conv]) + oc*CIN + chunk*64 + j*8;
        CP_ASYNC16(smem_u32((__half*)(base + XB_W) + (conv*2+pl)*4608 + oc*PITCH + j*8), src);
    }
}

__global__ __launch_bounds__(256, 1) void k1_tc(
    const float* __restrict__ x,
    const float* __restrict__ gp1, const float* __restrict__ bp1,
    const float* __restrict__ mp1, const float* __restrict__ vp1,
    const float* __restrict__ gc1, const float* __restrict__ bc1,
    const float* __restrict__ mc1, const float* __restrict__ vc1)
{
    extern __shared__ char sm[];
    float* binv = (float*)(sm + 3*XB_BYTES);
    float* bsh  = binv + 128;

    const int b = blockIdx.y, q0 = blockIdx.x*128, t = threadIdx.x;
    const int w = t>>5, lane = t&31;
    const int mh = w&3, nh = w>>2;
    const int m0 = mh*32;
    const int g = lane>>2, j4 = lane&3;

    if (t < 64){
        binv[t] = gp1[t]*rsqrtf(vp1[t]+EPSN);
        bsh [t] = bp1[t] - mp1[t]*binv[t];
    } else if (t < 128){
        int o = t-64;
        binv[64+o] = gc1[o]*rsqrtf(vc1[o]+EPSN);
        bsh [64+o] = bc1[o] - mc1[o]*binv[64+o];
    }

    k1_stage(sm, 0, 0, x, b, q0, t); CP_COMMIT();
    k1_stage(sm, 1, 1, x, b, q0, t); CP_COMMIT();

    float acc[2][8][4];
#pragma unroll
    for (int mf=0;mf<2;mf++)
#pragma unroll
        for (int nf=0;nf<8;nf++)
#pragma unroll
            for (int r=0;r<4;r++) acc[mf][nf][r]=0.f;

    for (int c=0; c<8; c++){
        if (c == 7) { CP_WAIT(0); } else { CP_WAIT(1); }
        __syncthreads();
        if (c + 2 < 8){ k1_stage(sm, (c+2)%3, c+2, x, b, q0, t); CP_COMMIT(); }
        char* base = sm + (size_t)(c%3)*XB_BYTES;
        const float* xf = (const float*)(base + XB_F32);
        const __half* wbH = (const __half*)(base + XB_W) + (nh*2+0)*4608;
        const __half* wbL = (const __half*)(base + XB_W) + (nh*2+1)*4608;

#pragma unroll
        for (int ks=0; ks<4; ks++){
            int col = ks*16 + 2*j4;
            uint32_t ah[2][4], al[2][4];
#pragma unroll
            for (int mf=0; mf<2; mf++){
                int r0 = m0 + mf*16 + g;
                split2(xf[(col  )*132 + r0  ], xf[(col+1)*132 + r0  ], ah[mf][0], al[mf][0]);
                split2(xf[(col  )*132 + r0+8], xf[(col+1)*132 + r0+8], ah[mf][1], al[mf][1]);
                split2(xf[(col+8)*132 + r0  ], xf[(col+9)*132 + r0  ], ah[mf][2], al[mf][2]);
                split2(xf[(col+8)*132 + r0+8], xf[(col+9)*132 + r0+8], ah[mf][3], al[mf][3]);
            }
#pragma unroll
            for (int nf=0; nf<8; nf++){
                int ocr = nf*8 + g;
                uint32_t wh0 = *(const uint32_t*)&wbH[ocr*PITCH + col];
                uint32_t wh1 = *(const uint32_t*)&wbH[ocr*PITCH + col+8];
                uint32_t wl0 = *(const uint32_t*)&wbL[ocr*PITCH + col];
                uint32_t wl1 = *(const uint32_t*)&wbL[ocr*PITCH + col+8];
#pragma unroll
                for (int mf=0; mf<2; mf++){
                    mma16816(acc[mf][nf], ah[mf], wh0, wh1);
                    mma16816(acc[mf][nf], al[mf], wh0, wh1);
                    mma16816(acc[mf][nf], ah[mf], wl0, wl1);
                }
            }
        }
    }
    __syncthreads();

    float* so = (float*)(sm + (size_t)nh*36864);   // [64 oc][132] per conv
#pragma unroll
    for (int mf=0; mf<2; mf++)
#pragma unroll
    for (int nf=0; nf<8; nf++)
#pragma unroll
    for (int r=0; r<4; r++){
        int oc = nf*8 + 2*j4 + (r&1);
        int hw = m0 + mf*16 + g + ((r>>1)*8);
        so[oc*132 + hw] = fmaf(acc[mf][nf][r], binv[nh*64+oc], bsh[nh*64+oc]);
    }
    __syncthreads();
    for (int f=t; f<4096; f+=256){
        int conv = f>>11, oc = (f>>5)&63, hg = (f&31)*4;
        const float* s = (const float*)(sm + (size_t)conv*36864);
        float4 v = make_float4(s[oc*132+hg], s[oc*132+hg+1],
                               s[oc*132+hg+2], s[oc*132+hg+3]);
        float* dst = conv ? g_fcb : g_fp;
        *(float4*)&dst[(size_t)(b*CI+oc)*HW_ + q0 + hg] = v;
    }
    {   // fpT planes (transposed) from conv0
        const float* s0 = (const float*)sm;
        for (int f=t; f<1024; f+=256){
            int hw = f&127, c8 = f>>7;
            uint32_t uh[4], ul[4];
#pragma unroll
            for (int i=0;i<4;i++)
                split2(s0[(c8*8+2*i)*132+hw], s0[(c8*8+2*i+1)*132+hw], uh[i], ul[i]);
            size_t base2 = ((size_t)b*HW_ + q0 + hw)*64 + c8*8;
            *(uint4*)&g_fpT_h[base2] = make_uint4(uh[0],uh[1],uh[2],uh[3]);
            *(uint4*)&g_fpT_l[base2] = make_uint4(ul[0],ul[1],ul[2],ul[3]);
        }
    }
    {   // fcb planes ([c][hw]) from conv1, for tensor gram
        const float* s1 = (const float*)(sm + 36864);
        for (int f=t; f<2048; f+=256){
            int oc = f>>5, hg = (f&31)*4;
            uint32_t h0,l0,h1,l1;
            split2(s1[oc*132+hg  ], s1[oc*132+hg+1], h0, l0);
            split2(s1[oc*132+hg+2], s1[oc*132+hg+3], h1, l1);
            size_t off = (size_t)(b*CI+oc)*HW_ + q0 + hg;
            *(uint2*)&g_cb_h[off] = make_uint2(h0, h1);
            *(uint2*)&g_cb_l[off] = make_uint2(l0, l1);
        }
    }
}

// ================= K1b_tc: QKV via tensor cores (64q, 128thr, 2/SM) =======
__global__ __launch_bounds__(128, 2) void k1b_tc(
    const float* __restrict__ bbv, const float* __restrict__ bc2,
    const float* __restrict__ bd)
{
    extern __shared__ char sm[];
    __half* A_h = (__half*)(sm + QB_AH);
    __half* A_l = (__half*)(sm + QB_AL);
    float* bias_s = (float*)(sm + QB_BIAS);

    const int b = blockIdx.y, q0 = blockIdx.x*64, t = threadIdx.x;
    const int w = t>>5, lane = t&31;
    const int mh = w&1, nh = w>>1;
    const int m0 = mh*32;
    const int g = lane>>2, j4 = lane&3;

#pragma unroll
    for (int i=0;i<8;i++){
        int idx = t + i*128;
        int pl = idx>>9, r = (idx>>3)&63, j = idx&7;
        const __half* src = (pl ? g_fpT_l : g_fpT_h) + ((size_t)b*HW_+q0+r)*64 + j*8;
        CP_ASYNC16(smem_u32((pl?A_l:A_h) + r*PITCH + j*8), src);
    }
#pragma unroll
    for (int i=0;i<24;i++){
        int idx = t + i*128;
        int reg = idx>>9, r = (idx>>3)&63, j = idx&7;
        int cv = reg>>1, pl = reg&1;
        const __half* src = (pl ? g_qwl[cv] : g_qwh[cv]) + r*64 + j*8;
        CP_ASYNC16(smem_u32((__half*)(sm + QB_W) + reg*4608 + r*PITCH + j*8), src);
    }
    CP_COMMIT();
    if (t < 64){ bias_s[t]=bbv[t]; bias_s[64+t]=bc2[t]; bias_s[128+t]=bd[t]; }
    CP_WAIT(0);
    __syncthreads();

    for (int cv=0; cv<3; cv++){
        const __half* WH = (const __half*)(sm + QB_W) + (cv*2+0)*4608;
        const __half* WL = (const __half*)(sm + QB_W) + (cv*2+1)*4608;
        float acc[2][4][4];
#pragma unroll
        for (int mf=0;mf<2;mf++)
#pragma unroll
            for (int nf=0;nf<4;nf++)
#pragma unroll
                for (int r=0;r<4;r++) acc[mf][nf][r]=0.f;

#pragma unroll
        for (int ks=0; ks<4; ks++){
            int col = ks*16 + 2*j4;
            uint32_t ah[2][4], al[2][4];
#pragma unroll
            for (int mf=0; mf<2; mf++){
                int r0 = m0 + mf*16 + g;
                ah[mf][0] = *(const uint32_t*)&A_h[(r0  )*PITCH + col];
                ah[mf][1] = *(const uint32_t*)&A_h[(r0+8)*PITCH + col];
                ah[mf][2] = *(const uint32_t*)&A_h[(r0  )*PITCH + col+8];
                ah[mf][3] = *(const uint32_t*)&A_h[(r0+8)*PITCH + col+8];
                al[mf][0] = *(const uint32_t*)&A_l[(r0  )*PITCH + col];
                al[mf][1] = *(const uint32_t*)&A_l[(r0+8)*PITCH + col];
                al[mf][2] = *(const uint32_t*)&A_l[(r0  )*PITCH + col+8];
                al[mf][3] = *(const uint32_t*)&A_l[(r0+8)*PITCH + col+8];
            }
#pragma unroll
            for (int nf=0; nf<4; nf++){
                int ocr = nh*32 + nf*8 + g;
                uint32_t wh0 = *(const uint32_t*)&WH[ocr*PITCH + col];
                uint32_t wh1 = *(const uint32_t*)&WH[ocr*PITCH + col+8];
                uint32_t wl0 = *(const uint32_t*)&WL[ocr*PITCH + col];
                uint32_t wl1 = *(const uint32_t*)&WL[ocr*PITCH + col+8];
#pragma unroll
                for (int mf=0; mf<2; mf++){
                    mma16816(acc[mf][nf], ah[mf], wh0, wh1);
                    mma16816(acc[mf][nf], al[mf], wh0, wh1);
                    mma16816(acc[mf][nf], ah[mf], wl0, wl1);
                }
            }
        }

        if (cv < 2){
            __half* dst = (cv==0) ? g_fbT_h : g_fcT_h;
#pragma unroll
            for (int mf=0; mf<2; mf++)
#pragma unroll
            for (int nf=0; nf<4; nf++){
                int oc = nh*32 + nf*8 + 2*j4;
                float b0v = bias_s[cv*64+oc], b1v = bias_s[cv*64+oc+1];
                int r0 = m0 + mf*16 + g;
                *(uint32_t*)&dst[((size_t)b*HW_+q0+r0  )*64 + oc] =
                    packh2(acc[mf][nf][0]+b0v, acc[mf][nf][1]+b1v);
                *(uint32_t*)&dst[((size_t)b*HW_+q0+r0+8)*64 + oc] =
                    packh2(acc[mf][nf][2]+b0v, acc[mf][nf][3]+b1v);
            }
        } else {
            __syncthreads();
            float* so = (float*)sm;    // [64 oc][68]
#pragma unroll
            for (int mf=0; mf<2; mf++)
#pragma unroll
            for (int nf=0; nf<4; nf++)
#pragma unroll
            for (int r=0; r<4; r++){
                int oc = nh*32 + nf*8 + 2*j4 + (r&1);
                int hw = m0 + mf*16 + g + ((r>>1)*8);
                so[oc*68 + hw] = acc[mf][nf][r] + bias_s[128+oc];
            }
            __syncthreads();
            for (int f=t; f<1024; f+=128){
                int oc = f>>4, hg = (f&15)*4;
                *(uint2*)&g_fd_h[(size_t)(b*CI+oc)*HW_ + q0 + hg] = make_uint2(
                    packh2(so[oc*68+hg  ], so[oc*68+hg+1]),
                    packh2(so[oc*68+hg+2], so[oc*68+hg+3]));
            }
        }
    }
}

// ================= K2_tc: tensor gram =====================================
__global__ __launch_bounds__(256, 2) void k2_tc()
{
    extern __shared__ char sm[];
    const int b = blockIdx.y, n0 = blockIdx.x*(HW_/GCH), t = threadIdx.x;
    const int w = t>>5, lane = t&31;
    const int mh = w&3, nh = w>>2;
    const int g = lane>>2, j4 = lane&3;

#pragma unroll
    for (int i=0;i<16;i++){
        int idx = t + i*256;
        int st = idx>>10, pl = (idx>>9)&1, r = (idx>>3)&63, j = idx&7;
        const __half* src = (pl ? g_cb_l : g_cb_h)
                            + (size_t)(b*CI + r)*HW_ + n0 + st*64 + j*8;
        CP_ASYNC16(smem_u32((__half*)sm + (st*2+pl)*4608 + r*PITCH + j*8), src);
    }
    CP_COMMIT(); CP_WAIT(0);
    __syncthreads();

    float acc[4][4];
#pragma unroll
    for (int i=0;i<4;i++)
#pragma unroll
        for (int j=0;j<4;j++) acc[i][j]=0.f;

#pragma unroll
    for (int st=0; st<4; st++){
        const __half* AH = (const __half*)sm + (st*2+0)*4608;
        const __half* AL = (const __half*)sm + (st*2+1)*4608;
#pragma unroll
        for (int ks=0; ks<4; ks++){
            int col = ks*16 + 2*j4;
            int r0 = mh*16 + g;
            uint32_t ah[4], al[4];
            ah[0] = *(const uint32_t*)&AH[(r0  )*PITCH + col];
            ah[1] = *(const uint32_t*)&AH[(r0+8)*PITCH + col];
            ah[2] = *(const uint32_t*)&AH[(r0  )*PITCH + col+8];
            ah[3] = *(const uint32_t*)&AH[(r0+8)*PITCH + col+8];
            al[0] = *(const uint32_t*)&AL[(r0  )*PITCH + col];
            al[1] = *(const uint32_t*)&AL[(r0+8)*PITCH + col];
            al[2] = *(const uint32_t*)&AL[(r0  )*PITCH + col+8];
            al[3] = *(const uint32_t*)&AL[(r0+8)*PITCH + col+8];
#pragma unroll
            for (int nf=0; nf<4; nf++){
                int dr = nh*32 + nf*8 + g;
                uint32_t bh0 = *(const uint32_t*)&AH[dr*PITCH + col];
                uint32_t bh1 = *(const uint32_t*)&AH[dr*PITCH + col+8];
                uint32_t bl0 = *(const uint32_t*)&AL[dr*PITCH + col];
                uint32_t bl1 = *(const uint32_t*)&AL[dr*PITCH + col+8];
                mma16816(acc[nf], ah, bh0, bh1);
                mma16816(acc[nf], al, bh0, bh1);
                mma16816(acc[nf], ah, bl0, bl1);
            }
        }
    }
#pragma unroll
    for (int nf=0; nf<4; nf++)
#pragma unroll
    for (int r=0; r<4; r++){
        int c = mh*16 + g + ((r>>1)*8);
        int d = nh*32 + nf*8 + 2*j4 + (r&1);
        g_gpart[((size_t)((b*CI + c)*CI) + d)*GCH + blockIdx.x] = acc[nf][r];
    }
}

// ================= K3: channel softmax ====================================
__global__ void k3_csoft()
{
    __shared__ float sg[64];
    const int b = blockIdx.y, c = blockIdx.x, d = threadIdx.x;
    size_t base = ((size_t)((b*CI + c)*CI) + d)*GCH;
    float s = 0.f;
#pragma unroll
    for (int ch=0; ch<GCH; ch++) s += g_gpart[base+ch];
    sg[d] = s; __syncthreads();
    for (int o=32; o; o>>=1){ if (d<o) sg[d] = fminf(sg[d], sg[d+o]); __syncthreads(); }
    float mn = sg[0]; __syncthreads();
    float e = __expf(mn - s);
    sg[d] = e; __syncthreads();
    for (int o=32; o; o>>=1){ if (d<o) sg[d] += sg[d+o]; __syncthreads(); }
    g_attnc[(b*CI + c)*CI + d] = e * (1.f/sg[0]);
}

// ================= K4: flash attention + fused channel/fusion epilogue ====
__device__ __forceinline__ void stage_tile(__half* dst, int kt, int b, int t){
    const int k0g = kt*64;
#pragma unroll
    for (int i=0;i<8;i++){
        int idx = t + i*128;
        int tl = idx>>9, r = (idx>>3)&63, j = idx&7;
        const __half* src = (tl==0)
            ? g_fcT_h + ((size_t)b*HW_ + k0g + r)*64 + j*8
            : g_fd_h  + ((size_t)(b*CI) + r)*HW_ + k0g + j*8;
        CP_ASYNC16(smem_u32(dst + tl*64*PITCH + r*PITCH + j*8), src);
    }
}

__global__ __launch_bounds__(128, 2) void k4_mma(const float* __restrict__ alpha,
                                                 const float* __restrict__ beta)
{
    extern __shared__ char sm[];
    __half* fbH = (__half*)(sm + K4_FB);
    __half* stg = (__half*)(sm + K4_STG);
    float* rs_sm = (float*)(sm + K4_RS);

    const int b = blockIdx.y, q0 = blockIdx.x*64, t = threadIdx.x;
    const int w = t>>5, lane = t&31;
    const int qg = w>>1, kg = w&1;
    const int g = lane>>2, j4 = lane&3;

#pragma unroll
    for (int i=0;i<4;i++){
        int idx = t + i*128;
        int r = idx>>3, j = idx&7;
        *(uint4*)(fbH + r*PITCH + j*8) =
            *(const uint4*)(g_fbT_h + ((size_t)b*HW_ + q0 + r)*64 + j*8);
    }
    stage_tile(stg,           0, b, t); CP_COMMIT();
    stage_tile(stg + TILE_SZ, 1, b, t); CP_COMMIT();
    __syncthreads();

    uint32_t Ah[2][4][4];
#pragma unroll
    for (int mt=0; mt<2; mt++)
#pragma unroll
    for (int ct=0; ct<4; ct++){
        int q = qg*32 + mt*16;
        int cb = ct*16 + 2*j4;
        Ah[mt][ct][0] = *(const uint32_t*)&fbH[(q+g  )*PITCH + cb];
        Ah[mt][ct][1] = *(const uint32_t*)&fbH[(q+g+8)*PITCH + cb];
        Ah[mt][ct][2] = *(const uint32_t*)&fbH[(q+g  )*PITCH + cb + 8];
        Ah[mt][ct][3] = *(const uint32_t*)&fbH[(q+g+8)*PITCH + cb + 8];
    }

    float O[2][8][4];
#pragma unroll
    for (int mt=0;mt<2;mt++)
#pragma unroll
        for (int dt=0;dt<8;dt++)
#pragma unroll
            for (int r=0;r<4;r++) O[mt][dt][r]=0.f;
    float rsum[2][2] = {{0.f,0.f},{0.f,0.f}};

    for (int kt=0; kt<64; kt++){
        if (kt == 63) { CP_WAIT(0); } else { CP_WAIT(1); }
        __syncthreads();
        if (kt + 2 < 64){
            stage_tile(stg + (size_t)((kt+2)%3)*TILE_SZ, kt+2, b, t);
            CP_COMMIT();
        }
        const __half* buf = stg + (size_t)(kt%3)*TILE_SZ;
        const __half* fcH = buf;
        const __half* fdH = buf + 64*PITCH;

        float S[2][4][4];
#pragma unroll
        for (int mt=0;mt<2;mt++)
#pragma unroll
            for (int nt=0;nt<4;nt++)
#pragma unroll
                for (int r=0;r<4;r++) S[mt][nt][r]=0.f;
#pragma unroll
        for (int ct=0; ct<4; ct++){
            int cb = ct*16 + 2*j4;
#pragma unroll
            for (int nt=0; nt<4; nt++){
                int ka = kg*32 + nt*8 + g;
                uint32_t bh0 = *(const uint32_t*)&fcH[ka*PITCH + cb];
                uint32_t bh1 = *(const uint32_t*)&fcH[ka*PITCH + cb + 8];
#pragma unroll
                for (int mt=0; mt<2; mt++)
                    mma16816(S[mt][nt], Ah[mt][ct], bh0, bh1);
            }
        }

        uint32_t Ph[2][2][4];
#pragma unroll
        for (int mt=0; mt<2; mt++)
#pragma unroll
        for (int nt=0; nt<4; nt++){
            float e0 = __expf(S[mt][nt][0] - SHIFT);
            float e1 = __expf(S[mt][nt][1] - SHIFT);
            float e2 = __expf(S[mt][nt][2] - SHIFT);
            float e3 = __expf(S[mt][nt][3] - SHIFT);
            rsum[mt][0] += e0+e1;
            rsum[mt][1] += e2+e3;
            int k2 = nt>>1, hf = (nt&1)*2;
            Ph[mt][k2][hf+0] = packh2(e0, e1);
            Ph[mt][k2][hf+1] = packh2(e2, e3);
        }

#pragma unroll
        for (int dt=0; dt<8; dt++){
            int d = dt*8 + g;
#pragma unroll
            for (int k2=0; k2<2; k2++){
                int kb = kg*32 + k2*16 + 2*j4;
                uint32_t bh0 = *(const uint32_t*)&fdH[d*PITCH + kb];
                uint32_t bh1 = *(const uint32_t*)&fdH[d*PITCH + kb + 8];
#pragma unroll
                for (int mt=0; mt<2; mt++)
                    mma16816(O[mt][dt], Ph[mt][k2], bh0, bh1);
            }
        }
    }

    // ---- epilogue: rowsum, O combine, channel GEMM, fusion, fp16 planes ----
#pragma unroll
    for (int mt=0; mt<2; mt++)
#pragma unroll
    for (int rr=0; rr<2; rr++){
        float v = rsum[mt][rr];
        v += __shfl_xor_sync(0xffffffffu, v, 1);
        v += __shfl_xor_sync(0xffffffffu, v, 2);
        if (j4 == 0) rs_sm[kg*64 + qg*32 + mt*16 + rr*8 + g] = v;
    }
    __syncthreads();   // stg region retired by all warps
    float* Opart  = (float*)(sm + K4_OP);    // [64 q][65]
    float* attn_s = (float*)(sm + K4_ATT);   // [64 c][64 d]
    float* fcb_s  = (float*)(sm + K4_FCB);   // [64 c][68]
    if (kg == 1){
#pragma unroll
        for (int mt=0; mt<2; mt++)
#pragma unroll
        for (int dt=0; dt<8; dt++){
            int q = qg*32 + mt*16, d = dt*8 + 2*j4;
            Opart[(q+g  )*65 + d  ] = O[mt][dt][0];
            Opart[(q+g  )*65 + d+1] = O[mt][dt][1];
            Opart[(q+g+8)*65 + d  ] = O[mt][dt][2];
            Opart[(q+g+8)*65 + d+1] = O[mt][dt][3];
        }
    }
    for (int f=t; f<1024; f+=128){
        int cc = f>>4, dv = (f&15)*4;
        *(float4*)&attn_s[cc*64+dv] =
            *(const float4*)&g_attnc[(size_t)b*CI*CI + cc*64 + dv];
    }
    for (int f=t; f<1024; f+=128){
        int d = f>>4, hv = (f&15)*4;
        *(float4*)&fcb_s[d*68+hv] =
            *(const float4*)&g_fcb[(size_t)(b*CI+d)*HW_ + q0 + hv];
    }
    __syncthreads();
    const float a0 = alpha[0];
    if (kg == 0){
#pragma unroll
        for (int mt=0; mt<2; mt++){
            int q = qg*32 + mt*16;
            float i0 = a0 / (rs_sm[q+g  ] + rs_sm[64+q+g  ]);
            float i1 = a0 / (rs_sm[q+g+8] + rs_sm[64+q+g+8]);
#pragma unroll
            for (int dt=0; dt<8; dt++){
                int d = dt*8 + 2*j4;
                Opart[(q+g  )*65+d  ] = (O[mt][dt][0] + Opart[(q+g  )*65+d  ]) * i0;
                Opart[(q+g  )*65+d+1] = (O[mt][dt][1] + Opart[(q+g  )*65+d+1]) * i0;
                Opart[(q+g+8)*65+d  ] = (O[mt][dt][2] + Opart[(q+g+8)*65+d  ]) * i1;
                Opart[(q+g+8)*65+d+1] = (O[mt][dt][3] + Opart[(q+g+8)*65+d+1]) * i1;
            }
        }
    }
    __syncthreads();
    {
        const int tq = t & 15, tc = t >> 4;
        const float b0 = beta[0];
        float accf[8][4];
#pragma unroll
        for (int cc=0;cc<8;cc++)
#pragma unroll
            for (int j=0;j<4;j++) accf[cc][j]=0.f;
#pragma unroll 4
        for (int d=0; d<CI; d++){
            float4 fv = *(float4*)&fcb_s[d*68 + tq*4];
#pragma unroll
            for (int cc=0; cc<8; cc++){
                float a = attn_s[(tc*8+cc)*64 + d];
                accf[cc][0] = fmaf(a, fv.x, accf[cc][0]);
                accf[cc][1] = fmaf(a, fv.y, accf[cc][1]);
                accf[cc][2] = fmaf(a, fv.z, accf[cc][2]);
                accf[cc][3] = fmaf(a, fv.w, accf[cc][3]);
            }
        }
        float res[8][4];
#pragma unroll
        for (int cc=0; cc<8; cc++){
            int c = tc*8+cc;
            float4 fpv = *(const float4*)&g_fp[(size_t)(b*CI+c)*HW_ + q0 + tq*4];
            float fpa[4] = {fpv.x, fpv.y, fpv.z, fpv.w};
#pragma unroll
            for (int j=0; j<4; j++){
                int hw = tq*4+j;
                res[cc][j] = Opart[hw*65 + c] + fpa[j]
                           + fmaf(b0, accf[cc][j], fcb_s[c*68+hw]);
            }
        }
        __syncthreads();
#pragma unroll
        for (int cc=0; cc<8; cc++)
#pragma unroll
            for (int j=0; j<4; j++)
                fcb_s[(tc*8+cc)*68 + tq*4+j] = res[cc][j];
    }
    __syncthreads();
    for (int f=t; f<512; f+=128){
        int hw = f&63, c8 = f>>6;
        uint32_t uh[4], ul[4];
#pragma unroll
        for (int i=0;i<4;i++)
            split2(fcb_s[(c8*8+2*i)*68+hw], fcb_s[(c8*8+2*i+1)*68+hw], uh[i], ul[i]);
        size_t base = ((size_t)b*HW_ + q0 + hw)*64 + c8*8;
        *(uint4*)&g_fusT_h[base] = make_uint4(uh[0],uh[1],uh[2],uh[3]);
        *(uint4*)&g_fusT_l[base] = make_uint4(ul[0],ul[1],ul[2],ul[3]);
    }
}

// ================= K6_tc: out conv via tensor cores =======================
__global__ __launch_bounds__(256, 1) void k6_tc(
    const float* __restrict__ go, const float* __restrict__ bo,
    const float* __restrict__ mo, const float* __restrict__ vo,
    float* __restrict__ out)
{
    extern __shared__ char sm[];
    __half* A_h = (__half*)(sm + K6_AH);
    __half* A_l = (__half*)(sm + K6_AL);
    __half* W_h = (__half*)(sm + K6_WH);
    __half* W_l = (__half*)(sm + K6_WL);
    float*  so  = (float*)(sm + K6_SO);
    float* bninv = (float*)(sm + K6_BN);
    float* bnsh  = bninv + 512;

    const int b = blockIdx.y, q0 = blockIdx.x*128, t = threadIdx.x;
    const int w = t>>5, lane = t&31;
    const int mh = w&3, nh = w>>2;
    const int m0 = mh*32;
    const int g = lane>>2, j4 = lane&3;

#pragma unroll
    for (int i=0;i<8;i++){
        int idx = t + i*256;
        int pl = idx>>10, r = (idx>>3)&127, j = idx&7;
        const __half* src = (pl ? g_fusT_l : g_fusT_h) + ((size_t)b*HW_+q0+r)*64 + j*8;
        CP_ASYNC16(smem_u32((pl?A_l:A_h) + r*PITCH + j*8), src);
    }
    CP_COMMIT();
    for (int f=t; f<512; f+=256){
        float inv = go[f]*rsqrtf(vo[f]+EPSN);
        bninv[f] = inv; bnsh[f] = bo[f] - mo[f]*inv;
    }
    CP_WAIT(0);
    __syncthreads();

    for (int co=0; co<4; co++){
#pragma unroll
        for (int i=0;i<8;i++){
            int idx = t + i*256;
            int pl = idx>>10, r = (idx>>3)&127, j = idx&7;
            const __half* src = (pl ? g_wol : g_woh) + (size_t)(co*128+r)*64 + j*8;
            CP_ASYNC16(smem_u32((pl?W_l:W_h) + r*PITCH + j*8), src);
        }
        CP_COMMIT(); CP_WAIT(0);
        __syncthreads();

        float acc[2][8][4];
#pragma unroll
        for (int mf=0;mf<2;mf++)
#pragma unroll
            for (int nf=0;nf<8;nf++)
#pragma unroll
                for (int r=0;r<4;r++) acc[mf][nf][r]=0.f;

#pragma unroll
        for (int ks=0; ks<4; ks++){
            int col = ks*16 + 2*j4;
            uint32_t ah[2][4], al[2][4];
#pragma unroll
            for (int mf=0; mf<2; mf++){
                int r0 = m0 + mf*16 + g;
                ah[mf][0] = *(const uint32_t*)&A_h[(r0  )*PITCH + col];
                ah[mf][1] = *(const uint32_t*)&A_h[(r0+8)*PITCH + col];
                ah[mf][2] = *(const uint32_t*)&A_h[(r0  )*PITCH + col+8];
                ah[mf][3] = *(const uint32_t*)&A_h[(r0+8)*PITCH + col+8];
                al[mf][0] = *(const uint32_t*)&A_l[(r0  )*PITCH + col];
                al[mf][1] = *(const uint32_t*)&A_l[(r0+8)*PITCH + col];
                al[mf][2] = *(const uint32_t*)&A_l[(r0  )*PITCH + col+8];
                al[mf][3] = *(const uint32_t*)&A_l[(r0+8)*PITCH + col+8];
            }
#pragma unroll
            for (int nf=0; nf<8; nf++){
                int ocr = nh*64 + nf*8 + g;
                uint32_t wh0 = *(const uint32_t*)&W_h[ocr*PITCH + col];
                uint32_t wh1 = *(const uint32_t*)&W_h[ocr*PITCH + col+8];
                uint32_t wl0 = *(const uint32_t*)&W_l[ocr*PITCH + col];
                uint32_t wl1 = *(const uint32_t*)&W_l[ocr*PITCH + col+8];
#pragma unroll
                for (int mf=0; mf<2; mf++){
                    mma16816(acc[mf][nf], ah[mf], wh0, wh1);
                    mma16816(acc[mf][nf], al[mf], wh0, wh1);
                    mma16816(acc[mf][nf], ah[mf], wl0, wl1);
                }
            }
        }
#pragma unroll
        for (int mf=0; mf<2; mf++)
#pragma unroll
        for (int nf=0; nf<8; nf++)
#pragma unroll
        for (int r=0; r<4; r++){
            int ocl = nh*64 + nf*8 + 2*j4 + (r&1);
            int hw = m0 + mf*16 + g + ((r>>1)*8);
            so[ocl*132 + hw] = fmaf(acc[mf][nf][r], bninv[co*128+ocl], bnsh[co*128+ocl]);
        }
        __syncthreads();
        for (int f=t; f<4096; f+=256){
            int ocl = f>>5, hg = (f&31)*4;
            *(float4*)&out[(size_t)(b*CIN + co*128 + ocl)*HW_ + q0 + hg] =
                make_float4(so[ocl*132+hg], so[ocl*132+hg+1],
                            so[ocl*132+hg+2], so[ocl*132+hg+3]);
        }
        __syncthreads();
    }
}

// ================= launch ==================================================
extern "C" void kernel_launch(void* const* d_in, const int* in_sizes, int n_in,
                              void* d_out, int out_size)
{
    const float* x   = (const float*)d_in[0];
    const float* wp1 = (const float*)d_in[1];
    const float* gp1 = (const float*)d_in[2];
    const float* bp1 = (const float*)d_in[3];
    const float* mp1 = (const float*)d_in[4];
    const float* vp1 = (const float*)d_in[5];
    const float* wc1 = (const float*)d_in[6];
    const float* gc1 = (const float*)d_in[7];
    const float* bc1 = (const float*)d_in[8];
    const float* mc1 = (const float*)d_in[9];
    const float* vc1 = (const float*)d_in[10];
    const float* wb  = (const float*)d_in[11];
    const float* bb  = (const float*)d_in[12];
    const float* wc2 = (const float*)d_in[13];
    const float* bc2 = (const float*)d_in[14];
    const float* wd  = (const float*)d_in[15];
    const float* bd  = (const float*)d_in[16];
    const float* alpha = (const float*)d_in[17];
    const float* beta  = (const float*)d_in[18];
    const float* wo  = (const float*)d_in[19];
    const float* go  = (const float*)d_in[20];
    const float* bo  = (const float*)d_in[21];
    const float* mo  = (const float*)d_in[22];
    const float* vo  = (const float*)d_in[23];
    float* out = (float*)d_out;

    const int K1_SMEM  = 3*XB_BYTES + 1024;            // 212992
    const int K1B_SMEM = QB_TOTAL;                     // 74752
    const int K2_SMEM  = 73728 + 512;
    const int K4_SMEM  = K4_TOTAL;                     // 65024
    const int K6_SMEM  = K6_TOTAL;                     // 145408
    cudaFuncSetAttribute(k1_tc,   cudaFuncAttributeMaxDynamicSharedMemorySize, K1_SMEM);
    cudaFuncSetAttribute(k1b_tc,  cudaFuncAttributeMaxDynamicSharedMemorySize, K1B_SMEM);
    cudaFuncSetAttribute(k2_tc,   cudaFuncAttributeMaxDynamicSharedMemorySize, K2_SMEM);
    cudaFuncSetAttribute(k4_mma,  cudaFuncAttributeMaxDynamicSharedMemorySize, K4_SMEM);
    cudaFuncSetAttribute(k6_tc,   cudaFuncAttributeMaxDynamicSharedMemorySize, K6_SMEM);

    k0w_planes<<<6, 256>>>(wp1, wc1, wo, wb, wc2, wd);
    k1_tc     <<<dim3(32, B_), 256, K1_SMEM>>>(x, gp1,bp1,mp1,vp1, gc1,bc1,mc1,vc1);
    k1b_tc    <<<dim3(64, B_), 128, K1B_SMEM>>>(bb, bc2, bd);
    k2_tc     <<<dim3(GCH, B_), 256, K2_SMEM>>>();
    k3_csoft  <<<dim3(CI, B_), 64>>>();
    k4_mma    <<<dim3(64, B_), 128, K4_SMEM>>>(alpha, beta);
    k6_tc     <<<dim3(32, B_), 256, K6_SMEM>>>(go, bo, mo, vo, out);
}